// round 5
// baseline (speedup 1.0000x reference)
#include <cuda_runtime.h>
#include <cuda_bf16.h>
#include <cuda_fp16.h>
#include <cstdint>

#define B   16384
#define D   784
#define H   768
#define C   10
#define K2  2368          // 3*784 + 16 pad
#define NCH 37            // K2/64 chunks (bf16, 128B)
#define NCH2 6            // 768/128 chunks (s8, 128B)
#define TM  128
#define TN  128

// ---------------- device scratch ----------------
__device__ __align__(128) __nv_bfloat16 g_A[(size_t)B * K2];   // split activations
__device__ __align__(128) __nv_bfloat16 g_Wb[(size_t)H * K2];  // sign(W1) bf16 x3
__device__ __align__(128) int8_t g_a2[(size_t)B * H];          // fc2 input (+-1)
__device__ __align__(128) int8_t g_a3[(size_t)B * H];          // fc3 input (+-1)
__device__ __align__(128) __half  g_h3[(size_t)B * H];         // fc4 input
__device__ __align__(128) int8_t g_w2s[H * H];
__device__ __align__(128) int8_t g_w3s[H * H];
__device__ float g_sc1[H], g_of1[H], g_sc2[H], g_of2[H], g_sc3[H], g_of3[H];

#define SWZ(o) ((o) ^ (((o) >> 3) & 0x70))

__device__ __forceinline__ uint32_t smem_u32(const void* p) {
    uint32_t a;
    asm("{ .reg .u64 t; cvta.to.shared.u64 t, %1; cvt.u32.u64 %0, t; }" : "=r"(a) : "l"(p));
    return a;
}

// ---------------- prep: folded BN scales ----------------
__global__ void prep_scales(const float* b1, const float* g1, const float* m1, const float* be1, const float* v1,
                            const float* b2, const float* g2, const float* m2, const float* be2, const float* v2,
                            const float* b3, const float* g3, const float* m3, const float* be3, const float* v3) {
    int j = threadIdx.x;
    if (j >= H) return;
    float s1 = g1[j] * (float)(1.0 / sqrt((double)(v1[j] + 1e-5f)));
    float s2 = g2[j] * (float)(1.0 / sqrt((double)(v2[j] + 1e-5f)));
    float s3 = g3[j] * (float)(1.0 / sqrt((double)(v3[j] + 1e-5f)));
    g_sc1[j] = s1; g_of1[j] = (b1[j] - m1[j]) * s1 + be1[j];
    g_sc2[j] = s2; g_of2[j] = (b2[j] - m2[j]) * s2 + be2[j];
    g_sc3[j] = s3; g_of3[j] = (b3[j] - m3[j]) * s3 + be3[j];
}

// ---------------- prep: sign(W2), sign(W3) as s8 ----------------
__global__ void pack_w_s8(const float* __restrict__ W2, const float* __restrict__ W3) {
    int t = blockIdx.x * blockDim.x + threadIdx.x;  // over 2 * H*H/4
    int half_n = (H * H) / 4;
    const float* W = (t < half_n) ? W2 : W3;
    int8_t* o = (t < half_n) ? g_w2s : g_w3s;
    int q = (t < half_n) ? t : t - half_n;
    float4 v = *(const float4*)&W[q * 4];
    char4 c;
    c.x = v.x >= 0.f ? 1 : -1; c.y = v.y >= 0.f ? 1 : -1;
    c.z = v.z >= 0.f ? 1 : -1; c.w = v.w >= 0.f ? 1 : -1;
    *(char4*)&o[q * 4] = c;
}

// ---------------- prep: 3-term bf16 split of x (one read -> 3 writes) --------
__global__ void prep_A(const float* __restrict__ X) {
    int idx = blockIdx.x * blockDim.x + threadIdx.x;   // over B*200
    if (idx >= B * 200) return;
    int b = idx / 200, q = idx - b * 200;
    __nv_bfloat16* row = &g_A[(size_t)b * K2];
    if (q >= 196) {   // zero pad [2352,2368)
        uint2 z = {0, 0};
        *(uint2*)&row[2352 + (q - 196) * 4] = z;
        return;
    }
    int kg = q * 4;
    float4 xv = *(const float4*)&X[b * D + kg];
    float xs[4] = {xv.x, xv.y, xv.z, xv.w};
    __align__(8) __nv_bfloat16 hi[4], mid[4], lo[4];
#pragma unroll
    for (int i = 0; i < 4; i++) {
        float x = xs[i];
        __nv_bfloat16 h = __float2bfloat16_rn(x);
        float r1 = x - __bfloat162float(h);
        __nv_bfloat16 m = __float2bfloat16_rn(r1);
        hi[i] = h; mid[i] = m;
        lo[i] = __float2bfloat16_rn(r1 - __bfloat162float(m));
    }
    *(uint2*)&row[kg]        = *(uint2*)hi;
    *(uint2*)&row[784 + kg]  = *(uint2*)mid;
    *(uint2*)&row[1568 + kg] = *(uint2*)lo;
}

// ---------------- prep: sign(W1) bf16, replicated 3x ----------------
__global__ void prep_Wb(const float* __restrict__ W1) {
    int idx = blockIdx.x * blockDim.x + threadIdx.x;   // over H*200
    if (idx >= H * 200) return;
    int j = idx / 200, q = idx - j * 200;
    __nv_bfloat16* row = &g_Wb[(size_t)j * K2];
    if (q >= 196) {
        uint2 z = {0, 0};
        *(uint2*)&row[2352 + (q - 196) * 4] = z;
        return;
    }
    int kg = q * 4;
    float4 wv = *(const float4*)&W1[j * D + kg];
    __align__(8) __nv_bfloat16 o[4];
    o[0] = __float2bfloat16(wv.x >= 0.f ? 1.f : -1.f);
    o[1] = __float2bfloat16(wv.y >= 0.f ? 1.f : -1.f);
    o[2] = __float2bfloat16(wv.z >= 0.f ? 1.f : -1.f);
    o[3] = __float2bfloat16(wv.w >= 0.f ? 1.f : -1.f);
    *(uint2*)&row[kg]        = *(uint2*)o;
    *(uint2*)&row[784 + kg]  = *(uint2*)o;
    *(uint2*)&row[1568 + kg] = *(uint2*)o;
}

// ---------------- fc1: bf16 mma.sync GEMM, 3-stage cp.async, fused epilogue --
// dyn smem: [0,512) sc, [512,1024) of, then 3 stages of (A 16KB | B 16KB)
#define FC1_SMEM (1024 + 3 * 32768)
#define A1_OFF(s) (1024u + (s) * 32768u)
#define B1_OFF(s) (1024u + (s) * 32768u + 16384u)

__global__ __launch_bounds__(256, 2)
void fc1_gemm() {
    extern __shared__ char smem[];
    const uint32_t sb = smem_u32(smem);
    const int tid = threadIdx.x;
    const int wid = tid >> 5, lane = tid & 31;
    const int warp_m = wid >> 2, warp_n = wid & 3;   // warp tile 64x32
    const int bn = blockIdx.x * TN, bm = blockIdx.y * TM;

    float* ssc = (float*)(smem);
    float* sof = (float*)(smem + 512);
    if (tid < 128) { ssc[tid] = g_sc1[bn + tid]; sof[tid] = g_of1[bn + tid]; }

    const char* Abase = (const char*)g_A  + (size_t)bm * (K2 * 2);
    const char* Bbase = (const char*)g_Wb + (size_t)bn * (K2 * 2);

    float acc[4][4][4];
#pragma unroll
    for (int i = 0; i < 4; i++)
#pragma unroll
        for (int j = 0; j < 4; j++)
#pragma unroll
            for (int c = 0; c < 4; c++) acc[i][j][c] = 0.f;

    auto load_stage = [&](int s, int buf) {
        size_t kb = (size_t)s * 128;
        uint32_t adst = sb + A1_OFF(buf), bdst = sb + B1_OFF(buf);
#pragma unroll
        for (int i = 0; i < 4; i++) {
            int idx = i * 256 + tid;
            int row = idx >> 3, c = idx & 7;
            uint32_t off = SWZ((uint32_t)(row * 128 + c * 16));
            const char* srcA = Abase + (size_t)row * (K2 * 2) + kb + c * 16;
            const char* srcB = Bbase + (size_t)row * (K2 * 2) + kb + c * 16;
            asm volatile("cp.async.cg.shared.global [%0], [%1], 16;" :: "r"(adst + off), "l"(srcA));
            asm volatile("cp.async.cg.shared.global [%0], [%1], 16;" :: "r"(bdst + off), "l"(srcB));
        }
        asm volatile("cp.async.commit_group;");
    };

    auto compute = [&](int buf) {
        uint32_t ab = sb + A1_OFF(buf), bb = sb + B1_OFF(buf);
#pragma unroll
        for (int ks = 0; ks < 4; ks++) {
            uint32_t a[4][4], bf[2][4];
            const int kk = ks * 16 + (lane >> 4) * 8;
            const int mrow = warp_m * 64 + (lane & 15);
#pragma unroll
            for (int mf = 0; mf < 4; mf++) {
                uint32_t addr = ab + SWZ((uint32_t)((mrow + mf * 16) * 128 + kk * 2));
                asm volatile("ldmatrix.sync.aligned.m8n8.x4.shared.b16 {%0,%1,%2,%3}, [%4];"
                    : "=r"(a[mf][0]), "=r"(a[mf][1]), "=r"(a[mf][2]), "=r"(a[mf][3]) : "r"(addr));
            }
            const int nrow = warp_n * 32 + (lane & 15);
#pragma unroll
            for (int p = 0; p < 2; p++) {
                uint32_t addr = bb + SWZ((uint32_t)((nrow + p * 16) * 128 + kk * 2));
                asm volatile("ldmatrix.sync.aligned.m8n8.x4.shared.b16 {%0,%1,%2,%3}, [%4];"
                    : "=r"(bf[p][0]), "=r"(bf[p][1]), "=r"(bf[p][2]), "=r"(bf[p][3]) : "r"(addr));
            }
#pragma unroll
            for (int mf = 0; mf < 4; mf++)
#pragma unroll
                for (int nf = 0; nf < 4; nf++) {
                    uint32_t b0 = bf[nf >> 1][nf & 1], b1 = bf[nf >> 1][(nf & 1) + 2];
                    asm volatile(
                        "mma.sync.aligned.m16n8k16.row.col.f32.bf16.bf16.f32 "
                        "{%0,%1,%2,%3}, {%4,%5,%6,%7}, {%8,%9}, {%0,%1,%2,%3};"
                        : "+f"(acc[mf][nf][0]), "+f"(acc[mf][nf][1]),
                          "+f"(acc[mf][nf][2]), "+f"(acc[mf][nf][3])
                        : "r"(a[mf][0]), "r"(a[mf][1]), "r"(a[mf][2]), "r"(a[mf][3]),
                          "r"(b0), "r"(b1));
                }
        }
    };

    // 3-stage pipeline, one barrier per chunk
    load_stage(0, 0);
    load_stage(1, 1);
    for (int s = 0; s < NCH; s++) {
        if (s + 1 < NCH) asm volatile("cp.async.wait_group 1;");
        else             asm volatile("cp.async.wait_group 0;");
        __syncthreads();                       // all warps done with compute(s-1)
        if (s + 2 < NCH) load_stage(s + 2, (s + 2) % 3);
        else             asm volatile("cp.async.commit_group;");
        compute(s % 3);
    }

    // epilogue: BN + sign -> s8 (+-1)
    const int tg = lane & 3, gid = lane >> 2;
    float scv[4][2], ofv[4][2];
#pragma unroll
    for (int nf = 0; nf < 4; nf++) {
        int cl = warp_n * 32 + nf * 8 + tg * 2;
        scv[nf][0] = ssc[cl];     ofv[nf][0] = sof[cl];
        scv[nf][1] = ssc[cl + 1]; ofv[nf][1] = sof[cl + 1];
    }
#pragma unroll
    for (int mf = 0; mf < 4; mf++) {
        int row = bm + warp_m * 64 + mf * 16 + gid;
#pragma unroll
        for (int nf = 0; nf < 4; nf++) {
            int col = bn + warp_n * 32 + nf * 8 + tg * 2;
            float f00 = fmaf(acc[mf][nf][0], scv[nf][0], ofv[nf][0]);
            float f01 = fmaf(acc[mf][nf][1], scv[nf][1], ofv[nf][1]);
            float f10 = fmaf(acc[mf][nf][2], scv[nf][0], ofv[nf][0]);
            float f11 = fmaf(acc[mf][nf][3], scv[nf][1], ofv[nf][1]);
            char2 cA, cB;
            cA.x = f00 >= 0.f ? 1 : -1; cA.y = f01 >= 0.f ? 1 : -1;
            cB.x = f10 >= 0.f ? 1 : -1; cB.y = f11 >= 0.f ? 1 : -1;
            *(char2*)&g_a2[(size_t)row * H + col]       = cA;
            *(char2*)&g_a2[(size_t)(row + 8) * H + col] = cB;
        }
    }
}

// ---------------- fc2/fc3: s8 mma GEMM (exact), fused BN epilogue ------------
// LAYER = 2: reads g_a2/g_w2s, sign -> g_a3 (s8)
// LAYER = 3: reads g_a3/g_w3s, hardtanh -> g_h3 (fp16)
// All device scratch referenced INSIDE device code (round-4 bug fix).
#define FC2_SMEM (1024 + 3 * 32768)

template<int LAYER>
__global__ __launch_bounds__(256, 2)
void fcbin_gemm() {
    extern __shared__ char smem[];
    const uint32_t sb = smem_u32(smem);
    const int tid = threadIdx.x;
    const int wid = tid >> 5, lane = tid & 31;
    const int warp_m = wid >> 2, warp_n = wid & 3;
    const int bn = blockIdx.x * TN, bm = blockIdx.y * TM;

    const int8_t* Ain = (LAYER == 2) ? g_a2 : g_a3;
    const int8_t* Wts = (LAYER == 2) ? g_w2s : g_w3s;
    const float* gsc  = (LAYER == 2) ? g_sc2 : g_sc3;
    const float* gof  = (LAYER == 2) ? g_of2 : g_of3;

    float* ssc = (float*)(smem);
    float* sof = (float*)(smem + 512);
    if (tid < 128) { ssc[tid] = gsc[bn + tid]; sof[tid] = gof[bn + tid]; }

    const char* Abase = (const char*)Ain + (size_t)bm * H;
    const char* Bbase = (const char*)Wts + (size_t)bn * H;

    int acc[4][4][4];
#pragma unroll
    for (int i = 0; i < 4; i++)
#pragma unroll
        for (int j = 0; j < 4; j++)
#pragma unroll
            for (int c = 0; c < 4; c++) acc[i][j][c] = 0;

    auto load_stage = [&](int s, int buf) {
        size_t kb = (size_t)s * 128;
        uint32_t adst = sb + A1_OFF(buf), bdst = sb + B1_OFF(buf);
#pragma unroll
        for (int i = 0; i < 4; i++) {
            int idx = i * 256 + tid;
            int row = idx >> 3, c = idx & 7;
            uint32_t off = SWZ((uint32_t)(row * 128 + c * 16));
            const char* srcA = Abase + (size_t)row * H + kb + c * 16;
            const char* srcB = Bbase + (size_t)row * H + kb + c * 16;
            asm volatile("cp.async.cg.shared.global [%0], [%1], 16;" :: "r"(adst + off), "l"(srcA));
            asm volatile("cp.async.cg.shared.global [%0], [%1], 16;" :: "r"(bdst + off), "l"(srcB));
        }
        asm volatile("cp.async.commit_group;");
    };

    auto compute = [&](int buf) {
        uint32_t ab = sb + A1_OFF(buf), bb = sb + B1_OFF(buf);
#pragma unroll
        for (int ks = 0; ks < 4; ks++) {           // 4 x k32 (32 bytes each)
            uint32_t a[4][4], bf[2][4];
            const int kbyte = ks * 32 + (lane >> 4) * 16;
            const int mrow = warp_m * 64 + (lane & 15);
#pragma unroll
            for (int mf = 0; mf < 4; mf++) {
                uint32_t addr = ab + SWZ((uint32_t)((mrow + mf * 16) * 128 + kbyte));
                asm volatile("ldmatrix.sync.aligned.m8n8.x4.shared.b16 {%0,%1,%2,%3}, [%4];"
                    : "=r"(a[mf][0]), "=r"(a[mf][1]), "=r"(a[mf][2]), "=r"(a[mf][3]) : "r"(addr));
            }
            const int nrow = warp_n * 32 + (lane & 15);
#pragma unroll
            for (int p = 0; p < 2; p++) {
                uint32_t addr = bb + SWZ((uint32_t)((nrow + p * 16) * 128 + kbyte));
                asm volatile("ldmatrix.sync.aligned.m8n8.x4.shared.b16 {%0,%1,%2,%3}, [%4];"
                    : "=r"(bf[p][0]), "=r"(bf[p][1]), "=r"(bf[p][2]), "=r"(bf[p][3]) : "r"(addr));
            }
#pragma unroll
            for (int mf = 0; mf < 4; mf++)
#pragma unroll
                for (int nf = 0; nf < 4; nf++) {
                    uint32_t b0 = bf[nf >> 1][nf & 1], b1 = bf[nf >> 1][(nf & 1) + 2];
                    asm volatile(
                        "mma.sync.aligned.m16n8k32.row.col.s32.s8.s8.s32 "
                        "{%0,%1,%2,%3}, {%4,%5,%6,%7}, {%8,%9}, {%0,%1,%2,%3};"
                        : "+r"(acc[mf][nf][0]), "+r"(acc[mf][nf][1]),
                          "+r"(acc[mf][nf][2]), "+r"(acc[mf][nf][3])
                        : "r"(a[mf][0]), "r"(a[mf][1]), "r"(a[mf][2]), "r"(a[mf][3]),
                          "r"(b0), "r"(b1));
                }
        }
    };

    load_stage(0, 0);
    load_stage(1, 1);
    for (int s = 0; s < NCH2; s++) {
        if (s + 1 < NCH2) asm volatile("cp.async.wait_group 1;");
        else              asm volatile("cp.async.wait_group 0;");
        __syncthreads();
        if (s + 2 < NCH2) load_stage(s + 2, (s + 2) % 3);
        else              asm volatile("cp.async.commit_group;");
        compute(s % 3);
    }

    const int tg = lane & 3, gid = lane >> 2;
    float scv[4][2], ofv[4][2];
#pragma unroll
    for (int nf = 0; nf < 4; nf++) {
        int cl = warp_n * 32 + nf * 8 + tg * 2;
        scv[nf][0] = ssc[cl];     ofv[nf][0] = sof[cl];
        scv[nf][1] = ssc[cl + 1]; ofv[nf][1] = sof[cl + 1];
    }
#pragma unroll
    for (int mf = 0; mf < 4; mf++) {
        int row = bm + warp_m * 64 + mf * 16 + gid;
#pragma unroll
        for (int nf = 0; nf < 4; nf++) {
            int col = bn + warp_n * 32 + nf * 8 + tg * 2;
            float f00 = fmaf((float)acc[mf][nf][0], scv[nf][0], ofv[nf][0]);
            float f01 = fmaf((float)acc[mf][nf][1], scv[nf][1], ofv[nf][1]);
            float f10 = fmaf((float)acc[mf][nf][2], scv[nf][0], ofv[nf][0]);
            float f11 = fmaf((float)acc[mf][nf][3], scv[nf][1], ofv[nf][1]);
            if (LAYER == 2) {
                char2 cA, cB;
                cA.x = f00 >= 0.f ? 1 : -1; cA.y = f01 >= 0.f ? 1 : -1;
                cB.x = f10 >= 0.f ? 1 : -1; cB.y = f11 >= 0.f ? 1 : -1;
                *(char2*)&g_a3[(size_t)row * H + col]       = cA;
                *(char2*)&g_a3[(size_t)(row + 8) * H + col] = cB;
            } else {
                __half2 hA, hB;
                hA.x = __float2half(fminf(fmaxf(f00, -1.f), 1.f));
                hA.y = __float2half(fminf(fmaxf(f01, -1.f), 1.f));
                hB.x = __float2half(fminf(fmaxf(f10, -1.f), 1.f));
                hB.y = __float2half(fminf(fmaxf(f11, -1.f), 1.f));
                *(__half2*)&g_h3[(size_t)row * H + col]       = hA;
                *(__half2*)&g_h3[(size_t)(row + 8) * H + col] = hB;
            }
        }
    }
}

// ---------------- fc4: GEMV + log_softmax, W4 in smem ----------------
__global__ __launch_bounds__(256)
void fc4_kernel(const float* __restrict__ W4, const float* __restrict__ b4,
                float* __restrict__ out) {
    __shared__ float sW[C * H];
    const int tid = threadIdx.x, lane = tid & 31, wid = tid >> 5;
    for (int i = tid; i < C * H; i += 256) sW[i] = W4[i];
    __syncthreads();
    const int row0 = blockIdx.x * 32 + wid * 4;
#pragma unroll 1
    for (int rr = 0; rr < 4; rr++) {
        const int w = row0 + rr;
        const __half2* hp = (const __half2*)&g_h3[(size_t)w * H];
        float acc[C];
#pragma unroll
        for (int c = 0; c < C; c++) acc[c] = 0.f;
#pragma unroll
        for (int t = 0; t < 12; t++) {
            int k2 = t * 32 + lane;
            float2 hv = __half22float2(hp[k2]);
#pragma unroll
            for (int c = 0; c < C; c++)
                acc[c] += hv.x * sW[c * H + 2 * k2] + hv.y * sW[c * H + 2 * k2 + 1];
        }
#pragma unroll
        for (int c = 0; c < C; c++)
#pragma unroll
            for (int off = 16; off > 0; off >>= 1)
                acc[c] += __shfl_xor_sync(0xffffffffu, acc[c], off);
        float lg[C], mx = -3.402823466e+38f;
#pragma unroll
        for (int c = 0; c < C; c++) { lg[c] = acc[c] + b4[c]; mx = fmaxf(mx, lg[c]); }
        float s = 0.f;
#pragma unroll
        for (int c = 0; c < C; c++) s += expf(lg[c] - mx);
        float lse = logf(s);
        if (lane < C) out[w * C + lane] = (lg[lane] - mx) - lse;
    }
}

// ---------------- launch ----------------
extern "C" void kernel_launch(void* const* d_in, const int* in_sizes, int n_in,
                              void* d_out, int out_size) {
    const float* x   = (const float*)d_in[0];
    const float* W1  = (const float*)d_in[1];
    const float* b1  = (const float*)d_in[2];
    const float* W2  = (const float*)d_in[3];
    const float* b2  = (const float*)d_in[4];
    const float* W3  = (const float*)d_in[5];
    const float* b3  = (const float*)d_in[6];
    const float* W4  = (const float*)d_in[7];
    const float* b4  = (const float*)d_in[8];
    const float* g1  = (const float*)d_in[9];
    const float* be1 = (const float*)d_in[10];
    const float* m1  = (const float*)d_in[11];
    const float* v1  = (const float*)d_in[12];
    const float* g2  = (const float*)d_in[13];
    const float* be2 = (const float*)d_in[14];
    const float* m2  = (const float*)d_in[15];
    const float* v2  = (const float*)d_in[16];
    const float* g3  = (const float*)d_in[17];
    const float* be3 = (const float*)d_in[18];
    const float* m3  = (const float*)d_in[19];
    const float* v3  = (const float*)d_in[20];
    float* out = (float*)d_out;

    cudaFuncSetAttribute(fc1_gemm,      cudaFuncAttributeMaxDynamicSharedMemorySize, FC1_SMEM);
    cudaFuncSetAttribute(fcbin_gemm<2>, cudaFuncAttributeMaxDynamicSharedMemorySize, FC2_SMEM);
    cudaFuncSetAttribute(fcbin_gemm<3>, cudaFuncAttributeMaxDynamicSharedMemorySize, FC2_SMEM);

    prep_scales<<<1, H>>>(b1, g1, m1, be1, v1, b2, g2, m2, be2, v2, b3, g3, m3, be3, v3);
    pack_w_s8<<<(2 * H * H / 4 + 255) / 256, 256>>>(W2, W3);
    prep_A<<<(B * 200 + 255) / 256, 256>>>(x);
    prep_Wb<<<(H * 200 + 255) / 256, 256>>>(W1);

    fc1_gemm<<<dim3(H / TN, B / TM), 256, FC1_SMEM>>>();

    fcbin_gemm<2><<<dim3(H / TN, B / TM), 256, FC2_SMEM>>>();
    fcbin_gemm<3><<<dim3(H / TN, B / TM), 256, FC2_SMEM>>>();

    fc4_kernel<<<B / 32, 256>>>(W4, b4, out);
}

// round 6
// speedup vs baseline: 1.0122x; 1.0122x over previous
#include <cuda_runtime.h>
#include <cuda_bf16.h>
#include <cuda_fp16.h>
#include <cstdint>

#define B   16384
#define D   784
#define H   768
#define C   10
#define K2  2368          // 3*784 + 16 pad
#define NCH 37            // K2/64 chunks (bf16, 128B)
#define NCH2 6            // 768/128 chunks (s8, 128B)
#define TM  128
#define TN  128

// ---------------- device scratch ----------------
__device__ __align__(128) __nv_bfloat16 g_A[(size_t)B * K2];   // split activations
__device__ __align__(128) __nv_bfloat16 g_Wb[(size_t)H * K2];  // sign(W1) bf16 x3
__device__ __align__(128) int8_t g_a2[(size_t)B * H];          // fc2 input (+-1)
__device__ __align__(128) int8_t g_a3[(size_t)B * H];          // fc3 input (+-1)
__device__ __align__(128) __half  g_h3[(size_t)B * H];         // fc4 input
__device__ __align__(128) int8_t g_w2s[H * H];
__device__ __align__(128) int8_t g_w3s[H * H];
__device__ float g_sc1[H], g_of1[H], g_sc2[H], g_of2[H], g_sc3[H], g_of3[H];

#define SWZ(o) ((o) ^ (((o) >> 3) & 0x70))

__device__ __forceinline__ uint32_t smem_u32(const void* p) {
    uint32_t a;
    asm("{ .reg .u64 t; cvta.to.shared.u64 t, %1; cvt.u32.u64 %0, t; }" : "=r"(a) : "l"(p));
    return a;
}

// ---------------- prep: folded BN scales ----------------
__global__ void prep_scales(const float* b1, const float* g1, const float* m1, const float* be1, const float* v1,
                            const float* b2, const float* g2, const float* m2, const float* be2, const float* v2,
                            const float* b3, const float* g3, const float* m3, const float* be3, const float* v3) {
    int j = threadIdx.x;
    if (j >= H) return;
    float s1 = g1[j] * (float)(1.0 / sqrt((double)(v1[j] + 1e-5f)));
    float s2 = g2[j] * (float)(1.0 / sqrt((double)(v2[j] + 1e-5f)));
    float s3 = g3[j] * (float)(1.0 / sqrt((double)(v3[j] + 1e-5f)));
    g_sc1[j] = s1; g_of1[j] = (b1[j] - m1[j]) * s1 + be1[j];
    g_sc2[j] = s2; g_of2[j] = (b2[j] - m2[j]) * s2 + be2[j];
    g_sc3[j] = s3; g_of3[j] = (b3[j] - m3[j]) * s3 + be3[j];
}

// ---------------- prep: sign(W2), sign(W3) as s8 ----------------
__global__ void pack_w_s8(const float* __restrict__ W2, const float* __restrict__ W3) {
    int t = blockIdx.x * blockDim.x + threadIdx.x;  // over 2 * H*H/4
    int half_n = (H * H) / 4;
    const float* W = (t < half_n) ? W2 : W3;
    int8_t* o = (t < half_n) ? g_w2s : g_w3s;
    int q = (t < half_n) ? t : t - half_n;
    float4 v = *(const float4*)&W[q * 4];
    char4 c;
    c.x = v.x >= 0.f ? 1 : -1; c.y = v.y >= 0.f ? 1 : -1;
    c.z = v.z >= 0.f ? 1 : -1; c.w = v.w >= 0.f ? 1 : -1;
    *(char4*)&o[q * 4] = c;
}

// ---------------- prep: 3-term bf16 split of x (one read -> 3 writes) --------
__global__ void prep_A(const float* __restrict__ X) {
    int idx = blockIdx.x * blockDim.x + threadIdx.x;   // over B*200
    if (idx >= B * 200) return;
    int b = idx / 200, q = idx - b * 200;
    __nv_bfloat16* row = &g_A[(size_t)b * K2];
    if (q >= 196) {   // zero pad [2352,2368)
        uint2 z = {0, 0};
        *(uint2*)&row[2352 + (q - 196) * 4] = z;
        return;
    }
    int kg = q * 4;
    float4 xv = *(const float4*)&X[b * D + kg];
    float xs[4] = {xv.x, xv.y, xv.z, xv.w};
    __align__(8) __nv_bfloat16 hi[4], mid[4], lo[4];
#pragma unroll
    for (int i = 0; i < 4; i++) {
        float x = xs[i];
        __nv_bfloat16 h = __float2bfloat16_rn(x);
        float r1 = x - __bfloat162float(h);
        __nv_bfloat16 m = __float2bfloat16_rn(r1);
        hi[i] = h; mid[i] = m;
        lo[i] = __float2bfloat16_rn(r1 - __bfloat162float(m));
    }
    *(uint2*)&row[kg]        = *(uint2*)hi;
    *(uint2*)&row[784 + kg]  = *(uint2*)mid;
    *(uint2*)&row[1568 + kg] = *(uint2*)lo;
}

// ---------------- prep: sign(W1) bf16, replicated 3x ----------------
__global__ void prep_Wb(const float* __restrict__ W1) {
    int idx = blockIdx.x * blockDim.x + threadIdx.x;   // over H*200
    if (idx >= H * 200) return;
    int j = idx / 200, q = idx - j * 200;
    __nv_bfloat16* row = &g_Wb[(size_t)j * K2];
    if (q >= 196) {
        uint2 z = {0, 0};
        *(uint2*)&row[2352 + (q - 196) * 4] = z;
        return;
    }
    int kg = q * 4;
    float4 wv = *(const float4*)&W1[j * D + kg];
    __align__(8) __nv_bfloat16 o[4];
    o[0] = __float2bfloat16(wv.x >= 0.f ? 1.f : -1.f);
    o[1] = __float2bfloat16(wv.y >= 0.f ? 1.f : -1.f);
    o[2] = __float2bfloat16(wv.z >= 0.f ? 1.f : -1.f);
    o[3] = __float2bfloat16(wv.w >= 0.f ? 1.f : -1.f);
    *(uint2*)&row[kg]        = *(uint2*)o;
    *(uint2*)&row[784 + kg]  = *(uint2*)o;
    *(uint2*)&row[1568 + kg] = *(uint2*)o;
}

// ---------------- fc1: bf16 mma.sync GEMM, 2-stage cp.async (R3 structure) ---
// dyn smem: [0,512) sc, [512,1024) of, A0 @1024, A1 @17408, B0 @33792, B1 @50176
#define FC1_SMEM 66560
#define A_OFF(b) (1024u + (b) * 16384u)
#define B_OFF(b) (33792u + (b) * 16384u)

__global__ __launch_bounds__(256, 2)
void fc1_gemm() {
    extern __shared__ char smem[];
    const uint32_t sb = smem_u32(smem);
    const int tid = threadIdx.x;
    const int wid = tid >> 5, lane = tid & 31;
    const int warp_m = wid >> 2, warp_n = wid & 3;   // warp tile 64x32
    const int bn = blockIdx.x * TN, bm = blockIdx.y * TM;

    float* ssc = (float*)(smem);
    float* sof = (float*)(smem + 512);
    if (tid < 128) { ssc[tid] = g_sc1[bn + tid]; sof[tid] = g_of1[bn + tid]; }

    const char* Abase = (const char*)g_A  + (size_t)bm * (K2 * 2);
    const char* Bbase = (const char*)g_Wb + (size_t)bn * (K2 * 2);

    float acc[4][4][4];
#pragma unroll
    for (int i = 0; i < 4; i++)
#pragma unroll
        for (int j = 0; j < 4; j++)
#pragma unroll
            for (int c = 0; c < 4; c++) acc[i][j][c] = 0.f;

    auto load_stage = [&](int s, int buf) {
        size_t kb = (size_t)s * 128;
        uint32_t adst = sb + A_OFF(buf), bdst = sb + B_OFF(buf);
#pragma unroll
        for (int i = 0; i < 4; i++) {
            int idx = i * 256 + tid;
            int row = idx >> 3, c = idx & 7;
            uint32_t off = SWZ((uint32_t)(row * 128 + c * 16));
            const char* srcA = Abase + (size_t)row * (K2 * 2) + kb + c * 16;
            const char* srcB = Bbase + (size_t)row * (K2 * 2) + kb + c * 16;
            asm volatile("cp.async.cg.shared.global [%0], [%1], 16;" :: "r"(adst + off), "l"(srcA));
            asm volatile("cp.async.cg.shared.global [%0], [%1], 16;" :: "r"(bdst + off), "l"(srcB));
        }
        asm volatile("cp.async.commit_group;");
    };

    auto compute = [&](int buf) {
        uint32_t ab = sb + A_OFF(buf), bb = sb + B_OFF(buf);
#pragma unroll
        for (int ks = 0; ks < 4; ks++) {
            uint32_t a[4][4], bf[2][4];
            const int kk = ks * 16 + (lane >> 4) * 8;
            const int mrow = warp_m * 64 + (lane & 15);
#pragma unroll
            for (int mf = 0; mf < 4; mf++) {
                uint32_t addr = ab + SWZ((uint32_t)((mrow + mf * 16) * 128 + kk * 2));
                asm volatile("ldmatrix.sync.aligned.m8n8.x4.shared.b16 {%0,%1,%2,%3}, [%4];"
                    : "=r"(a[mf][0]), "=r"(a[mf][1]), "=r"(a[mf][2]), "=r"(a[mf][3]) : "r"(addr));
            }
            const int nrow = warp_n * 32 + (lane & 15);
#pragma unroll
            for (int p = 0; p < 2; p++) {
                uint32_t addr = bb + SWZ((uint32_t)((nrow + p * 16) * 128 + kk * 2));
                asm volatile("ldmatrix.sync.aligned.m8n8.x4.shared.b16 {%0,%1,%2,%3}, [%4];"
                    : "=r"(bf[p][0]), "=r"(bf[p][1]), "=r"(bf[p][2]), "=r"(bf[p][3]) : "r"(addr));
            }
#pragma unroll
            for (int mf = 0; mf < 4; mf++)
#pragma unroll
                for (int nf = 0; nf < 4; nf++) {
                    uint32_t b0 = bf[nf >> 1][nf & 1], b1 = bf[nf >> 1][(nf & 1) + 2];
                    asm volatile(
                        "mma.sync.aligned.m16n8k16.row.col.f32.bf16.bf16.f32 "
                        "{%0,%1,%2,%3}, {%4,%5,%6,%7}, {%8,%9}, {%0,%1,%2,%3};"
                        : "+f"(acc[mf][nf][0]), "+f"(acc[mf][nf][1]),
                          "+f"(acc[mf][nf][2]), "+f"(acc[mf][nf][3])
                        : "r"(a[mf][0]), "r"(a[mf][1]), "r"(a[mf][2]), "r"(a[mf][3]),
                          "r"(b0), "r"(b1));
                }
        }
    };

    // R3 structure: loads issued BEFORE wait, 2 syncs per chunk
    load_stage(0, 0);
    for (int s = 0; s < NCH; s++) {
        if (s + 1 < NCH) load_stage(s + 1, (s + 1) & 1);
        if (s + 1 < NCH) asm volatile("cp.async.wait_group 1;");
        else             asm volatile("cp.async.wait_group 0;");
        __syncthreads();
        compute(s & 1);
        __syncthreads();
    }

    // epilogue: BN + sign -> s8 (+-1)
    const int tg = lane & 3, gid = lane >> 2;
    float scv[4][2], ofv[4][2];
#pragma unroll
    for (int nf = 0; nf < 4; nf++) {
        int cl = warp_n * 32 + nf * 8 + tg * 2;
        scv[nf][0] = ssc[cl];     ofv[nf][0] = sof[cl];
        scv[nf][1] = ssc[cl + 1]; ofv[nf][1] = sof[cl + 1];
    }
#pragma unroll
    for (int mf = 0; mf < 4; mf++) {
        int row = bm + warp_m * 64 + mf * 16 + gid;
#pragma unroll
        for (int nf = 0; nf < 4; nf++) {
            int col = bn + warp_n * 32 + nf * 8 + tg * 2;
            float f00 = fmaf(acc[mf][nf][0], scv[nf][0], ofv[nf][0]);
            float f01 = fmaf(acc[mf][nf][1], scv[nf][1], ofv[nf][1]);
            float f10 = fmaf(acc[mf][nf][2], scv[nf][0], ofv[nf][0]);
            float f11 = fmaf(acc[mf][nf][3], scv[nf][1], ofv[nf][1]);
            char2 cA, cB;
            cA.x = f00 >= 0.f ? 1 : -1; cA.y = f01 >= 0.f ? 1 : -1;
            cB.x = f10 >= 0.f ? 1 : -1; cB.y = f11 >= 0.f ? 1 : -1;
            *(char2*)&g_a2[(size_t)row * H + col]       = cA;
            *(char2*)&g_a2[(size_t)(row + 8) * H + col] = cB;
        }
    }
}

// ---------------- fc2/fc3: s8 mma GEMM (exact), 2-stage, fused BN epilogue ---
#define FC2_SMEM 66560

template<int LAYER>
__global__ __launch_bounds__(256, 2)
void fcbin_gemm() {
    extern __shared__ char smem[];
    const uint32_t sb = smem_u32(smem);
    const int tid = threadIdx.x;
    const int wid = tid >> 5, lane = tid & 31;
    const int warp_m = wid >> 2, warp_n = wid & 3;
    const int bn = blockIdx.x * TN, bm = blockIdx.y * TM;

    const int8_t* Ain = (LAYER == 2) ? g_a2 : g_a3;
    const int8_t* Wts = (LAYER == 2) ? g_w2s : g_w3s;
    const float* gsc  = (LAYER == 2) ? g_sc2 : g_sc3;
    const float* gof  = (LAYER == 2) ? g_of2 : g_of3;

    float* ssc = (float*)(smem);
    float* sof = (float*)(smem + 512);
    if (tid < 128) { ssc[tid] = gsc[bn + tid]; sof[tid] = gof[bn + tid]; }

    const char* Abase = (const char*)Ain + (size_t)bm * H;
    const char* Bbase = (const char*)Wts + (size_t)bn * H;

    int acc[4][4][4];
#pragma unroll
    for (int i = 0; i < 4; i++)
#pragma unroll
        for (int j = 0; j < 4; j++)
#pragma unroll
            for (int c = 0; c < 4; c++) acc[i][j][c] = 0;

    auto load_stage = [&](int s, int buf) {
        size_t kb = (size_t)s * 128;
        uint32_t adst = sb + A_OFF(buf), bdst = sb + B_OFF(buf);
#pragma unroll
        for (int i = 0; i < 4; i++) {
            int idx = i * 256 + tid;
            int row = idx >> 3, c = idx & 7;
            uint32_t off = SWZ((uint32_t)(row * 128 + c * 16));
            const char* srcA = Abase + (size_t)row * H + kb + c * 16;
            const char* srcB = Bbase + (size_t)row * H + kb + c * 16;
            asm volatile("cp.async.cg.shared.global [%0], [%1], 16;" :: "r"(adst + off), "l"(srcA));
            asm volatile("cp.async.cg.shared.global [%0], [%1], 16;" :: "r"(bdst + off), "l"(srcB));
        }
        asm volatile("cp.async.commit_group;");
    };

    auto compute = [&](int buf) {
        uint32_t ab = sb + A_OFF(buf), bb = sb + B_OFF(buf);
#pragma unroll
        for (int ks = 0; ks < 4; ks++) {           // 4 x k32 (32 bytes each)
            uint32_t a[4][4], bf[2][4];
            const int kbyte = ks * 32 + (lane >> 4) * 16;
            const int mrow = warp_m * 64 + (lane & 15);
#pragma unroll
            for (int mf = 0; mf < 4; mf++) {
                uint32_t addr = ab + SWZ((uint32_t)((mrow + mf * 16) * 128 + kbyte));
                asm volatile("ldmatrix.sync.aligned.m8n8.x4.shared.b16 {%0,%1,%2,%3}, [%4];"
                    : "=r"(a[mf][0]), "=r"(a[mf][1]), "=r"(a[mf][2]), "=r"(a[mf][3]) : "r"(addr));
            }
            const int nrow = warp_n * 32 + (lane & 15);
#pragma unroll
            for (int p = 0; p < 2; p++) {
                uint32_t addr = bb + SWZ((uint32_t)((nrow + p * 16) * 128 + kbyte));
                asm volatile("ldmatrix.sync.aligned.m8n8.x4.shared.b16 {%0,%1,%2,%3}, [%4];"
                    : "=r"(bf[p][0]), "=r"(bf[p][1]), "=r"(bf[p][2]), "=r"(bf[p][3]) : "r"(addr));
            }
#pragma unroll
            for (int mf = 0; mf < 4; mf++)
#pragma unroll
                for (int nf = 0; nf < 4; nf++) {
                    uint32_t b0 = bf[nf >> 1][nf & 1], b1 = bf[nf >> 1][(nf & 1) + 2];
                    asm volatile(
                        "mma.sync.aligned.m16n8k32.row.col.s32.s8.s8.s32 "
                        "{%0,%1,%2,%3}, {%4,%5,%6,%7}, {%8,%9}, {%0,%1,%2,%3};"
                        : "+r"(acc[mf][nf][0]), "+r"(acc[mf][nf][1]),
                          "+r"(acc[mf][nf][2]), "+r"(acc[mf][nf][3])
                        : "r"(a[mf][0]), "r"(a[mf][1]), "r"(a[mf][2]), "r"(a[mf][3]),
                          "r"(b0), "r"(b1));
                }
        }
    };

    load_stage(0, 0);
    for (int s = 0; s < NCH2; s++) {
        if (s + 1 < NCH2) load_stage(s + 1, (s + 1) & 1);
        if (s + 1 < NCH2) asm volatile("cp.async.wait_group 1;");
        else              asm volatile("cp.async.wait_group 0;");
        __syncthreads();
        compute(s & 1);
        __syncthreads();
    }

    const int tg = lane & 3, gid = lane >> 2;
    float scv[4][2], ofv[4][2];
#pragma unroll
    for (int nf = 0; nf < 4; nf++) {
        int cl = warp_n * 32 + nf * 8 + tg * 2;
        scv[nf][0] = ssc[cl];     ofv[nf][0] = sof[cl];
        scv[nf][1] = ssc[cl + 1]; ofv[nf][1] = sof[cl + 1];
    }
#pragma unroll
    for (int mf = 0; mf < 4; mf++) {
        int row = bm + warp_m * 64 + mf * 16 + gid;
#pragma unroll
        for (int nf = 0; nf < 4; nf++) {
            int col = bn + warp_n * 32 + nf * 8 + tg * 2;
            float f00 = fmaf((float)acc[mf][nf][0], scv[nf][0], ofv[nf][0]);
            float f01 = fmaf((float)acc[mf][nf][1], scv[nf][1], ofv[nf][1]);
            float f10 = fmaf((float)acc[mf][nf][2], scv[nf][0], ofv[nf][0]);
            float f11 = fmaf((float)acc[mf][nf][3], scv[nf][1], ofv[nf][1]);
            if (LAYER == 2) {
                char2 cA, cB;
                cA.x = f00 >= 0.f ? 1 : -1; cA.y = f01 >= 0.f ? 1 : -1;
                cB.x = f10 >= 0.f ? 1 : -1; cB.y = f11 >= 0.f ? 1 : -1;
                *(char2*)&g_a3[(size_t)row * H + col]       = cA;
                *(char2*)&g_a3[(size_t)(row + 8) * H + col] = cB;
            } else {
                __half2 hA, hB;
                hA.x = __float2half(fminf(fmaxf(f00, -1.f), 1.f));
                hA.y = __float2half(fminf(fmaxf(f01, -1.f), 1.f));
                hB.x = __float2half(fminf(fmaxf(f10, -1.f), 1.f));
                hB.y = __float2half(fminf(fmaxf(f11, -1.f), 1.f));
                *(__half2*)&g_h3[(size_t)row * H + col]       = hA;
                *(__half2*)&g_h3[(size_t)(row + 8) * H + col] = hB;
            }
        }
    }
}

// ---------------- fc4: GEMV + log_softmax, W4 in smem ----------------
__global__ __launch_bounds__(256)
void fc4_kernel(const float* __restrict__ W4, const float* __restrict__ b4,
                float* __restrict__ out) {
    __shared__ float sW[C * H];
    const int tid = threadIdx.x, lane = tid & 31, wid = tid >> 5;
    for (int i = tid; i < C * H; i += 256) sW[i] = W4[i];
    __syncthreads();
    const int row0 = blockIdx.x * 32 + wid * 4;
#pragma unroll 1
    for (int rr = 0; rr < 4; rr++) {
        const int w = row0 + rr;
        const __half2* hp = (const __half2*)&g_h3[(size_t)w * H];
        float acc[C];
#pragma unroll
        for (int c = 0; c < C; c++) acc[c] = 0.f;
#pragma unroll
        for (int t = 0; t < 12; t++) {
            int k2 = t * 32 + lane;
            float2 hv = __half22float2(hp[k2]);
#pragma unroll
            for (int c = 0; c < C; c++)
                acc[c] += hv.x * sW[c * H + 2 * k2] + hv.y * sW[c * H + 2 * k2 + 1];
        }
#pragma unroll
        for (int c = 0; c < C; c++)
#pragma unroll
            for (int off = 16; off > 0; off >>= 1)
                acc[c] += __shfl_xor_sync(0xffffffffu, acc[c], off);
        float lg[C], mx = -3.402823466e+38f;
#pragma unroll
        for (int c = 0; c < C; c++) { lg[c] = acc[c] + b4[c]; mx = fmaxf(mx, lg[c]); }
        float s = 0.f;
#pragma unroll
        for (int c = 0; c < C; c++) s += expf(lg[c] - mx);
        float lse = logf(s);
        if (lane < C) out[w * C + lane] = (lg[lane] - mx) - lse;
    }
}

// ---------------- launch ----------------
extern "C" void kernel_launch(void* const* d_in, const int* in_sizes, int n_in,
                              void* d_out, int out_size) {
    const float* x   = (const float*)d_in[0];
    const float* W1  = (const float*)d_in[1];
    const float* b1  = (const float*)d_in[2];
    const float* W2  = (const float*)d_in[3];
    const float* b2  = (const float*)d_in[4];
    const float* W3  = (const float*)d_in[5];
    const float* b3  = (const float*)d_in[6];
    const float* W4  = (const float*)d_in[7];
    const float* b4  = (const float*)d_in[8];
    const float* g1  = (const float*)d_in[9];
    const float* be1 = (const float*)d_in[10];
    const float* m1  = (const float*)d_in[11];
    const float* v1  = (const float*)d_in[12];
    const float* g2  = (const float*)d_in[13];
    const float* be2 = (const float*)d_in[14];
    const float* m2  = (const float*)d_in[15];
    const float* v2  = (const float*)d_in[16];
    const float* g3  = (const float*)d_in[17];
    const float* be3 = (const float*)d_in[18];
    const float* m3  = (const float*)d_in[19];
    const float* v3  = (const float*)d_in[20];
    float* out = (float*)d_out;

    cudaFuncSetAttribute(fc1_gemm,      cudaFuncAttributeMaxDynamicSharedMemorySize, FC1_SMEM);
    cudaFuncSetAttribute(fcbin_gemm<2>, cudaFuncAttributeMaxDynamicSharedMemorySize, FC2_SMEM);
    cudaFuncSetAttribute(fcbin_gemm<3>, cudaFuncAttributeMaxDynamicSharedMemorySize, FC2_SMEM);

    prep_scales<<<1, H>>>(b1, g1, m1, be1, v1, b2, g2, m2, be2, v2, b3, g3, m3, be3, v3);
    pack_w_s8<<<(2 * H * H / 4 + 255) / 256, 256>>>(W2, W3);
    prep_A<<<(B * 200 + 255) / 256, 256>>>(x);
    prep_Wb<<<(H * 200 + 255) / 256, 256>>>(W1);

    fc1_gemm<<<dim3(H / TN, B / TM), 256, FC1_SMEM>>>();

    fcbin_gemm<2><<<dim3(H / TN, B / TM), 256, FC2_SMEM>>>();
    fcbin_gemm<3><<<dim3(H / TN, B / TM), 256, FC2_SMEM>>>();

    fc4_kernel<<<B / 32, 256>>>(W4, b4, out);
}

// round 7
// speedup vs baseline: 1.3461x; 1.3298x over previous
#include <cuda_runtime.h>
#include <cuda_bf16.h>
#include <cuda_fp16.h>
#include <cstdint>

#define B   16384
#define D   784
#define H   768
#define C   10
#define HW  24            // H/32
#define K2  2368          // 3*784 + 16 pad
#define NCH 37            // K2/64 chunks (bf16, 128B)
#define TM  128
#define TN  128

// ---------------- device scratch ----------------
__device__ __align__(128) __nv_bfloat16 g_A[(size_t)B * K2];   // split activations
__device__ __align__(128) __nv_bfloat16 g_Wb[(size_t)H * K2];  // sign(W1) bf16 x3
__device__ unsigned g_bits1[B * HW];
__device__ unsigned g_bits2[B * HW];
__device__ __align__(128) __half g_h3[(size_t)B * H];          // fc4 input
__device__ unsigned g_w2bits[HW * H];
__device__ unsigned g_w3bits[HW * H];
__device__ float g_sc1[H], g_of1[H], g_sc2[H], g_of2[H], g_sc3[H], g_of3[H];

#define SWZ(o) ((o) ^ (((o) >> 3) & 0x70))

__device__ __forceinline__ uint32_t smem_u32(const void* p) {
    uint32_t a;
    asm("{ .reg .u64 t; cvta.to.shared.u64 t, %1; cvt.u32.u64 %0, t; }" : "=r"(a) : "l"(p));
    return a;
}

// ---------------- prep: folded BN scales ----------------
__global__ void prep_scales(const float* b1, const float* g1, const float* m1, const float* be1, const float* v1,
                            const float* b2, const float* g2, const float* m2, const float* be2, const float* v2,
                            const float* b3, const float* g3, const float* m3, const float* be3, const float* v3) {
    int j = threadIdx.x;
    if (j >= H) return;
    float s1 = g1[j] * (float)(1.0 / sqrt((double)(v1[j] + 1e-5f)));
    float s2 = g2[j] * (float)(1.0 / sqrt((double)(v2[j] + 1e-5f)));
    float s3 = g3[j] * (float)(1.0 / sqrt((double)(v3[j] + 1e-5f)));
    g_sc1[j] = s1; g_of1[j] = (b1[j] - m1[j]) * s1 + be1[j];
    g_sc2[j] = s2; g_of2[j] = (b2[j] - m2[j]) * s2 + be2[j];
    g_sc3[j] = s3; g_of3[j] = (b3[j] - m3[j]) * s3 + be3[j];
}

// ---------------- prep: bit-pack W2 / W3 transposed [kword][j] ----------------
__global__ void pack_wbits(const float* __restrict__ W2, const float* __restrict__ W3) {
    int t = blockIdx.x * blockDim.x + threadIdx.x;  // over 2*HW*H
    int which = t >= HW * H;
    int q = which ? t - HW * H : t;
    if (q >= HW * H) return;
    const float* W = which ? W3 : W2;
    int kw = q / H, j = q % H;
    const float* p = &W[j * H + kw * 32];
    unsigned word = 0;
#pragma unroll
    for (int i = 0; i < 32; i++) word |= (p[i] >= 0.f ? 1u : 0u) << i;
    if (which) g_w3bits[kw * H + j] = word;
    else       g_w2bits[kw * H + j] = word;
}

// ---------------- prep: 3-term bf16 split of x (one read -> 3 writes) --------
__global__ void prep_A(const float* __restrict__ X) {
    int idx = blockIdx.x * blockDim.x + threadIdx.x;   // over B*200
    if (idx >= B * 200) return;
    int b = idx / 200, q = idx - b * 200;
    __nv_bfloat16* row = &g_A[(size_t)b * K2];
    if (q >= 196) {   // zero pad [2352,2368)
        uint2 z = {0, 0};
        *(uint2*)&row[2352 + (q - 196) * 4] = z;
        return;
    }
    int kg = q * 4;
    float4 xv = *(const float4*)&X[b * D + kg];
    float xs[4] = {xv.x, xv.y, xv.z, xv.w};
    __align__(8) __nv_bfloat16 hi[4], mid[4], lo[4];
#pragma unroll
    for (int i = 0; i < 4; i++) {
        float x = xs[i];
        __nv_bfloat16 h = __float2bfloat16_rn(x);
        float r1 = x - __bfloat162float(h);
        __nv_bfloat16 m = __float2bfloat16_rn(r1);
        hi[i] = h; mid[i] = m;
        lo[i] = __float2bfloat16_rn(r1 - __bfloat162float(m));
    }
    *(uint2*)&row[kg]        = *(uint2*)hi;
    *(uint2*)&row[784 + kg]  = *(uint2*)mid;
    *(uint2*)&row[1568 + kg] = *(uint2*)lo;
}

// ---------------- prep: sign(W1) bf16, replicated 3x ----------------
__global__ void prep_Wb(const float* __restrict__ W1) {
    int idx = blockIdx.x * blockDim.x + threadIdx.x;   // over H*200
    if (idx >= H * 200) return;
    int j = idx / 200, q = idx - j * 200;
    __nv_bfloat16* row = &g_Wb[(size_t)j * K2];
    if (q >= 196) {
        uint2 z = {0, 0};
        *(uint2*)&row[2352 + (q - 196) * 4] = z;
        return;
    }
    int kg = q * 4;
    float4 wv = *(const float4*)&W1[j * D + kg];
    __align__(8) __nv_bfloat16 o[4];
    o[0] = __float2bfloat16(wv.x >= 0.f ? 1.f : -1.f);
    o[1] = __float2bfloat16(wv.y >= 0.f ? 1.f : -1.f);
    o[2] = __float2bfloat16(wv.z >= 0.f ? 1.f : -1.f);
    o[3] = __float2bfloat16(wv.w >= 0.f ? 1.f : -1.f);
    *(uint2*)&row[kg]        = *(uint2*)o;
    *(uint2*)&row[784 + kg]  = *(uint2*)o;
    *(uint2*)&row[1568 + kg] = *(uint2*)o;
}

// ---------------- fc1: bf16 mma.sync GEMM (R3 pipeline) + bit-pack epilogue --
// dyn smem: [0,512) sc, [512,1024) of, A0 @1024, A1 @17408, B0 @33792, B1 @50176
#define FC1_SMEM 66560
#define A_OFF(b) (1024u + (b) * 16384u)
#define B_OFF(b) (33792u + (b) * 16384u)

__global__ __launch_bounds__(256, 2)
void fc1_gemm() {
    extern __shared__ char smem[];
    const uint32_t sb = smem_u32(smem);
    const int tid = threadIdx.x;
    const int wid = tid >> 5, lane = tid & 31;
    const int warp_m = wid >> 2, warp_n = wid & 3;   // warp tile 64x32
    const int bn = blockIdx.x * TN, bm = blockIdx.y * TM;

    float* ssc = (float*)(smem);
    float* sof = (float*)(smem + 512);
    if (tid < 128) { ssc[tid] = g_sc1[bn + tid]; sof[tid] = g_of1[bn + tid]; }

    const char* Abase = (const char*)g_A  + (size_t)bm * (K2 * 2);
    const char* Bbase = (const char*)g_Wb + (size_t)bn * (K2 * 2);

    float acc[4][4][4];
#pragma unroll
    for (int i = 0; i < 4; i++)
#pragma unroll
        for (int j = 0; j < 4; j++)
#pragma unroll
            for (int c = 0; c < 4; c++) acc[i][j][c] = 0.f;

    auto load_stage = [&](int s, int buf) {
        size_t kb = (size_t)s * 128;
        uint32_t adst = sb + A_OFF(buf), bdst = sb + B_OFF(buf);
#pragma unroll
        for (int i = 0; i < 4; i++) {
            int idx = i * 256 + tid;
            int row = idx >> 3, c = idx & 7;
            uint32_t off = SWZ((uint32_t)(row * 128 + c * 16));
            const char* srcA = Abase + (size_t)row * (K2 * 2) + kb + c * 16;
            const char* srcB = Bbase + (size_t)row * (K2 * 2) + kb + c * 16;
            asm volatile("cp.async.cg.shared.global [%0], [%1], 16;" :: "r"(adst + off), "l"(srcA));
            asm volatile("cp.async.cg.shared.global [%0], [%1], 16;" :: "r"(bdst + off), "l"(srcB));
        }
        asm volatile("cp.async.commit_group;");
    };

    auto compute = [&](int buf) {
        uint32_t ab = sb + A_OFF(buf), bb = sb + B_OFF(buf);
#pragma unroll
        for (int ks = 0; ks < 4; ks++) {
            uint32_t a[4][4], bf[2][4];
            const int kk = ks * 16 + (lane >> 4) * 8;
            const int mrow = warp_m * 64 + (lane & 15);
#pragma unroll
            for (int mf = 0; mf < 4; mf++) {
                uint32_t addr = ab + SWZ((uint32_t)((mrow + mf * 16) * 128 + kk * 2));
                asm volatile("ldmatrix.sync.aligned.m8n8.x4.shared.b16 {%0,%1,%2,%3}, [%4];"
                    : "=r"(a[mf][0]), "=r"(a[mf][1]), "=r"(a[mf][2]), "=r"(a[mf][3]) : "r"(addr));
            }
            const int nrow = warp_n * 32 + (lane & 15);
#pragma unroll
            for (int p = 0; p < 2; p++) {
                uint32_t addr = bb + SWZ((uint32_t)((nrow + p * 16) * 128 + kk * 2));
                asm volatile("ldmatrix.sync.aligned.m8n8.x4.shared.b16 {%0,%1,%2,%3}, [%4];"
                    : "=r"(bf[p][0]), "=r"(bf[p][1]), "=r"(bf[p][2]), "=r"(bf[p][3]) : "r"(addr));
            }
#pragma unroll
            for (int mf = 0; mf < 4; mf++)
#pragma unroll
                for (int nf = 0; nf < 4; nf++) {
                    uint32_t b0 = bf[nf >> 1][nf & 1], b1 = bf[nf >> 1][(nf & 1) + 2];
                    asm volatile(
                        "mma.sync.aligned.m16n8k16.row.col.f32.bf16.bf16.f32 "
                        "{%0,%1,%2,%3}, {%4,%5,%6,%7}, {%8,%9}, {%0,%1,%2,%3};"
                        : "+f"(acc[mf][nf][0]), "+f"(acc[mf][nf][1]),
                          "+f"(acc[mf][nf][2]), "+f"(acc[mf][nf][3])
                        : "r"(a[mf][0]), "r"(a[mf][1]), "r"(a[mf][2]), "r"(a[mf][3]),
                          "r"(b0), "r"(b1));
                }
        }
    };

    // R3 pipeline: loads issued BEFORE wait, 2 syncs per chunk
    load_stage(0, 0);
    for (int s = 0; s < NCH; s++) {
        if (s + 1 < NCH) load_stage(s + 1, (s + 1) & 1);
        if (s + 1 < NCH) asm volatile("cp.async.wait_group 1;");
        else             asm volatile("cp.async.wait_group 0;");
        __syncthreads();
        compute(s & 1);
        __syncthreads();
    }

    // epilogue: BN + sign + bit-pack (R3, validated)
    const int tg = lane & 3, gid = lane >> 2;
    float scv[4][2], ofv[4][2];
#pragma unroll
    for (int nf = 0; nf < 4; nf++) {
        int cl = warp_n * 32 + nf * 8 + tg * 2;
        scv[nf][0] = ssc[cl];     ofv[nf][0] = sof[cl];
        scv[nf][1] = ssc[cl + 1]; ofv[nf][1] = sof[cl + 1];
    }
    const int widx = (bn >> 5) + warp_n;
#pragma unroll
    for (int mf = 0; mf < 4; mf++) {
        unsigned mA = 0, mB = 0;
#pragma unroll
        for (int nf = 0; nf < 4; nf++) {
            int p = nf * 8 + tg * 2;
            float f00 = fmaf(acc[mf][nf][0], scv[nf][0], ofv[nf][0]);
            float f01 = fmaf(acc[mf][nf][1], scv[nf][1], ofv[nf][1]);
            float f10 = fmaf(acc[mf][nf][2], scv[nf][0], ofv[nf][0]);
            float f11 = fmaf(acc[mf][nf][3], scv[nf][1], ofv[nf][1]);
            mA |= ((f00 >= 0.f ? 1u : 0u) << p) | ((f01 >= 0.f ? 1u : 0u) << (p + 1));
            mB |= ((f10 >= 0.f ? 1u : 0u) << p) | ((f11 >= 0.f ? 1u : 0u) << (p + 1));
        }
        mA |= __shfl_xor_sync(0xffffffffu, mA, 1); mA |= __shfl_xor_sync(0xffffffffu, mA, 2);
        mB |= __shfl_xor_sync(0xffffffffu, mB, 1); mB |= __shfl_xor_sync(0xffffffffu, mB, 2);
        if (tg == 0) {
            int row = bm + warp_m * 64 + mf * 16 + gid;
            g_bits1[row * HW + widx]       = mA;
            g_bits1[(row + 8) * HW + widx] = mB;
        }
    }
}

// ---------------- fc2 / fc3: XNOR-popcount, weights in smem (R3) -------------
#define FC_SMEM (HW * H * 4 + 2 * H * 4)   // 79872

__global__ __launch_bounds__(256)
void fc2_kernel() {
    extern __shared__ char smem[];
    unsigned* ws = (unsigned*)smem;
    float* ssc = (float*)(smem + HW * H * 4);
    float* sof = ssc + H;
    const int tid = threadIdx.x, lane = tid & 31, wid = tid >> 5;
    for (int i = tid; i < HW * H; i += 256) ws[i] = g_w2bits[i];
    for (int i = tid; i < H; i += 256) { ssc[i] = g_sc2[i]; sof[i] = g_of2[i]; }
    __syncthreads();
    const int row0 = blockIdx.x * 64 + wid * 8;
#pragma unroll 1
    for (int rr = 0; rr < 8; rr++) {
        const int b = row0 + rr;
        const uint4* ap = (const uint4*)&g_bits1[b * HW];
        uint4 a0 = ap[0], a1 = ap[1], a2 = ap[2], a3 = ap[3], a4 = ap[4], a5 = ap[5];
        unsigned a[24] = {a0.x,a0.y,a0.z,a0.w, a1.x,a1.y,a1.z,a1.w, a2.x,a2.y,a2.z,a2.w,
                          a3.x,a3.y,a3.z,a3.w, a4.x,a4.y,a4.z,a4.w, a5.x,a5.y,a5.z,a5.w};
#pragma unroll 1
        for (int jw = 0; jw < HW; jw++) {
            const int j = jw * 32 + lane;
            int c0 = 0, c1 = 0;
#pragma unroll
            for (int k = 0; k < HW; k += 2) {
                c0 += __popc(a[k]     ^ ws[k * H + j]);
                c1 += __popc(a[k + 1] ^ ws[(k + 1) * H + j]);
            }
            float pop = (float)(H - 2 * (c0 + c1));
            float f = fmaf(pop, ssc[j], sof[j]);
            unsigned bal = __ballot_sync(0xffffffffu, f >= 0.f);
            if (lane == 0) g_bits2[b * HW + jw] = bal;
        }
    }
}

__global__ __launch_bounds__(256)
void fc3_kernel() {
    extern __shared__ char smem[];
    unsigned* ws = (unsigned*)smem;
    float* ssc = (float*)(smem + HW * H * 4);
    float* sof = ssc + H;
    const int tid = threadIdx.x, lane = tid & 31, wid = tid >> 5;
    for (int i = tid; i < HW * H; i += 256) ws[i] = g_w3bits[i];
    for (int i = tid; i < H; i += 256) { ssc[i] = g_sc3[i]; sof[i] = g_of3[i]; }
    __syncthreads();
    const int row0 = blockIdx.x * 64 + wid * 8;
#pragma unroll 1
    for (int rr = 0; rr < 8; rr++) {
        const int b = row0 + rr;
        const uint4* ap = (const uint4*)&g_bits2[b * HW];
        uint4 a0 = ap[0], a1 = ap[1], a2 = ap[2], a3 = ap[3], a4 = ap[4], a5 = ap[5];
        unsigned a[24] = {a0.x,a0.y,a0.z,a0.w, a1.x,a1.y,a1.z,a1.w, a2.x,a2.y,a2.z,a2.w,
                          a3.x,a3.y,a3.z,a3.w, a4.x,a4.y,a4.z,a4.w, a5.x,a5.y,a5.z,a5.w};
#pragma unroll 1
        for (int jw = 0; jw < HW; jw++) {
            const int j = jw * 32 + lane;
            int c0 = 0, c1 = 0;
#pragma unroll
            for (int k = 0; k < HW; k += 2) {
                c0 += __popc(a[k]     ^ ws[k * H + j]);
                c1 += __popc(a[k + 1] ^ ws[(k + 1) * H + j]);
            }
            float pop = (float)(H - 2 * (c0 + c1));
            float f = fmaf(pop, ssc[j], sof[j]);
            g_h3[(size_t)b * H + j] = __float2half(fminf(fmaxf(f, -1.f), 1.f));
        }
    }
}

// ---------------- fc4: GEMV + log_softmax, W4 in smem ----------------
__global__ __launch_bounds__(256)
void fc4_kernel(const float* __restrict__ W4, const float* __restrict__ b4,
                float* __restrict__ out) {
    __shared__ float sW[C * H];
    const int tid = threadIdx.x, lane = tid & 31, wid = tid >> 5;
    for (int i = tid; i < C * H; i += 256) sW[i] = W4[i];
    __syncthreads();
    const int row0 = blockIdx.x * 32 + wid * 4;
#pragma unroll 1
    for (int rr = 0; rr < 4; rr++) {
        const int w = row0 + rr;
        const __half2* hp = (const __half2*)&g_h3[(size_t)w * H];
        float acc[C];
#pragma unroll
        for (int c = 0; c < C; c++) acc[c] = 0.f;
#pragma unroll
        for (int t = 0; t < 12; t++) {
            int k2 = t * 32 + lane;
            float2 hv = __half22float2(hp[k2]);
#pragma unroll
            for (int c = 0; c < C; c++)
                acc[c] += hv.x * sW[c * H + 2 * k2] + hv.y * sW[c * H + 2 * k2 + 1];
        }
#pragma unroll
        for (int c = 0; c < C; c++)
#pragma unroll
            for (int off = 16; off > 0; off >>= 1)
                acc[c] += __shfl_xor_sync(0xffffffffu, acc[c], off);
        float lg[C], mx = -3.402823466e+38f;
#pragma unroll
        for (int c = 0; c < C; c++) { lg[c] = acc[c] + b4[c]; mx = fmaxf(mx, lg[c]); }
        float s = 0.f;
#pragma unroll
        for (int c = 0; c < C; c++) s += expf(lg[c] - mx);
        float lse = logf(s);
        if (lane < C) out[w * C + lane] = (lg[lane] - mx) - lse;
    }
}

// ---------------- launch ----------------
extern "C" void kernel_launch(void* const* d_in, const int* in_sizes, int n_in,
                              void* d_out, int out_size) {
    const float* x   = (const float*)d_in[0];
    const float* W1  = (const float*)d_in[1];
    const float* b1  = (const float*)d_in[2];
    const float* W2  = (const float*)d_in[3];
    const float* b2  = (const float*)d_in[4];
    const float* W3  = (const float*)d_in[5];
    const float* b3  = (const float*)d_in[6];
    const float* W4  = (const float*)d_in[7];
    const float* b4  = (const float*)d_in[8];
    const float* g1  = (const float*)d_in[9];
    const float* be1 = (const float*)d_in[10];
    const float* m1  = (const float*)d_in[11];
    const float* v1  = (const float*)d_in[12];
    const float* g2  = (const float*)d_in[13];
    const float* be2 = (const float*)d_in[14];
    const float* m2  = (const float*)d_in[15];
    const float* v2  = (const float*)d_in[16];
    const float* g3  = (const float*)d_in[17];
    const float* be3 = (const float*)d_in[18];
    const float* m3  = (const float*)d_in[19];
    const float* v3  = (const float*)d_in[20];
    float* out = (float*)d_out;

    cudaFuncSetAttribute(fc1_gemm,   cudaFuncAttributeMaxDynamicSharedMemorySize, FC1_SMEM);
    cudaFuncSetAttribute(fc2_kernel, cudaFuncAttributeMaxDynamicSharedMemorySize, FC_SMEM);
    cudaFuncSetAttribute(fc3_kernel, cudaFuncAttributeMaxDynamicSharedMemorySize, FC_SMEM);

    prep_scales<<<1, H>>>(b1, g1, m1, be1, v1, b2, g2, m2, be2, v2, b3, g3, m3, be3, v3);
    pack_wbits<<<(2 * HW * H + 255) / 256, 256>>>(W2, W3);
    prep_A<<<(B * 200 + 255) / 256, 256>>>(x);
    prep_Wb<<<(H * 200 + 255) / 256, 256>>>(W1);

    fc1_gemm<<<dim3(H / TN, B / TM), 256, FC1_SMEM>>>();

    fc2_kernel<<<B / 64, 256, FC_SMEM>>>();
    fc3_kernel<<<B / 64, 256, FC_SMEM>>>();
    fc4_kernel<<<B / 32, 256>>>(W4, b4, out);
}

// round 9
// speedup vs baseline: 1.5593x; 1.1584x over previous
#include <cuda_runtime.h>
#include <cuda_fp16.h>
#include <cstdint>

#define B   16384
#define D   784
#define H   768
#define C   10
#define HW  24            // H/32
#define K2  1600          // 2*784 + 32 pad (fp16 2-term split)
#define NCH 25            // K2/64 chunks (fp16, 128B)
#define TM  128
#define TN  128

// ---------------- device scratch ----------------
__device__ __align__(128) __half g_A[(size_t)B * K2];    // hi|lo split activations
__device__ __align__(128) __half g_Wb[(size_t)H * K2];   // sign(W1) fp16 x2 (pad 0)
__device__ unsigned g_bits1[B * HW];
__device__ unsigned g_bits2[B * HW];
__device__ __align__(128) __half g_h3[(size_t)B * H];
__device__ unsigned g_w2bits[HW * H];
__device__ unsigned g_w3bits[HW * H];
__device__ float g_sc1[H], g_of1[H], g_sc2[H], g_of2[H], g_sc3[H], g_of3[H];

#define SWZ(o) ((o) ^ (((o) >> 3) & 0x70))

__device__ __forceinline__ uint32_t smem_u32(const void* p) {
    uint32_t a;
    asm("{ .reg .u64 t; cvta.to.shared.u64 t, %1; cvt.u32.u64 %0, t; }" : "=r"(a) : "l"(p));
    return a;
}

// ---------------- prep: folded BN scales ----------------
__global__ void prep_scales(const float* b1, const float* g1, const float* m1, const float* be1, const float* v1,
                            const float* b2, const float* g2, const float* m2, const float* be2, const float* v2,
                            const float* b3, const float* g3, const float* m3, const float* be3, const float* v3) {
    int j = threadIdx.x;
    if (j >= H) return;
    float s1 = g1[j] * (float)(1.0 / sqrt((double)(v1[j] + 1e-5f)));
    float s2 = g2[j] * (float)(1.0 / sqrt((double)(v2[j] + 1e-5f)));
    float s3 = g3[j] * (float)(1.0 / sqrt((double)(v3[j] + 1e-5f)));
    g_sc1[j] = s1; g_of1[j] = (b1[j] - m1[j]) * s1 + be1[j];
    g_sc2[j] = s2; g_of2[j] = (b2[j] - m2[j]) * s2 + be2[j];
    g_sc3[j] = s3; g_of3[j] = (b3[j] - m3[j]) * s3 + be3[j];
}

// ---------------- prep: 2-term fp16 split of x (one read -> 2 writes) --------
__global__ void prep_A(const float* __restrict__ X) {
    int idx = blockIdx.x * blockDim.x + threadIdx.x;   // over B*204
    if (idx >= B * 204) return;
    int b = idx / 204, q = idx - b * 204;
    __half* row = &g_A[(size_t)b * K2];
    if (q >= 196) {   // zero pad [1568,1600)
        uint2 z = {0, 0};
        *(uint2*)&row[1568 + (q - 196) * 4] = z;
        return;
    }
    int kg = q * 4;
    float4 xv = *(const float4*)&X[b * D + kg];
    float xs[4] = {xv.x, xv.y, xv.z, xv.w};
    __align__(8) __half hi[4], lo[4];
#pragma unroll
    for (int i = 0; i < 4; i++) {
        float x = xs[i];
        __half h = __float2half_rn(x);
        hi[i] = h;
        lo[i] = __float2half_rn(x - __half2float(h));
    }
    *(uint2*)&row[kg]       = *(uint2*)hi;
    *(uint2*)&row[784 + kg] = *(uint2*)lo;
}

// ---------------- prep: sign(W1) fp16, replicated 2x, pad 0 ----------------
__global__ void prep_Wb(const float* __restrict__ W1) {
    int idx = blockIdx.x * blockDim.x + threadIdx.x;   // over H*204
    if (idx >= H * 204) return;
    int j = idx / 204, q = idx - j * 204;
    __half* row = &g_Wb[(size_t)j * K2];
    if (q >= 196) {
        uint2 z = {0, 0};
        *(uint2*)&row[1568 + (q - 196) * 4] = z;
        return;
    }
    int kg = q * 4;
    float4 wv = *(const float4*)&W1[j * D + kg];
    __align__(8) __half o[4];
    o[0] = __float2half(wv.x >= 0.f ? 1.f : -1.f);
    o[1] = __float2half(wv.y >= 0.f ? 1.f : -1.f);
    o[2] = __float2half(wv.z >= 0.f ? 1.f : -1.f);
    o[3] = __float2half(wv.w >= 0.f ? 1.f : -1.f);
    *(uint2*)&row[kg]       = *(uint2*)o;
    *(uint2*)&row[784 + kg] = *(uint2*)o;
}

// ---------------- prep: bit-pack W2 / W3 transposed [kword][j] ----------------
__global__ void pack_wbits(const float* __restrict__ W2, const float* __restrict__ W3) {
    int t = blockIdx.x * blockDim.x + threadIdx.x;  // over 2*HW*H
    int which = t >= HW * H;
    int q = which ? t - HW * H : t;
    if (q >= HW * H) return;
    const float* W = which ? W3 : W2;
    int kw = q / H, j = q % H;
    const float* p = &W[j * H + kw * 32];
    unsigned word = 0;
#pragma unroll
    for (int i = 0; i < 32; i++) word |= (p[i] >= 0.f ? 1u : 0u) << i;
    if (which) g_w3bits[kw * H + j] = word;
    else       g_w2bits[kw * H + j] = word;
}

// ---------------- fc1: fp16 mma.sync GEMM (R3/R7 pipeline) + bit-pack --------
// dyn smem: [0,512) sc, [512,1024) of, A0 @1024, A1 @17408, B0 @33792, B1 @50176
#define FC1_SMEM 66560
#define A_OFF(b) (1024u + (b) * 16384u)
#define B_OFF(b) (33792u + (b) * 16384u)

__global__ __launch_bounds__(256, 2)
void fc1_gemm() {
    extern __shared__ char smem[];
    const uint32_t sb = smem_u32(smem);
    const int tid = threadIdx.x;
    const int wid = tid >> 5, lane = tid & 31;
    const int warp_m = wid >> 2, warp_n = wid & 3;   // warp tile 64x32
    const int bn = blockIdx.x * TN, bm = blockIdx.y * TM;

    float* ssc = (float*)(smem);
    float* sof = (float*)(smem + 512);
    if (tid < 128) { ssc[tid] = g_sc1[bn + tid]; sof[tid] = g_of1[bn + tid]; }

    const char* Abase = (const char*)g_A  + (size_t)bm * (K2 * 2);
    const char* Bbase = (const char*)g_Wb + (size_t)bn * (K2 * 2);

    float acc[4][4][4];
#pragma unroll
    for (int i = 0; i < 4; i++)
#pragma unroll
        for (int j = 0; j < 4; j++)
#pragma unroll
            for (int c = 0; c < 4; c++) acc[i][j][c] = 0.f;

    auto load_stage = [&](int s, int buf) {
        size_t kb = (size_t)s * 128;
        uint32_t adst = sb + A_OFF(buf), bdst = sb + B_OFF(buf);
#pragma unroll
        for (int i = 0; i < 4; i++) {
            int idx = i * 256 + tid;
            int row = idx >> 3, c = idx & 7;
            uint32_t off = SWZ((uint32_t)(row * 128 + c * 16));
            const char* srcA = Abase + (size_t)row * (K2 * 2) + kb + c * 16;
            const char* srcB = Bbase + (size_t)row * (K2 * 2) + kb + c * 16;
            asm volatile("cp.async.cg.shared.global [%0], [%1], 16;" :: "r"(adst + off), "l"(srcA));
            asm volatile("cp.async.cg.shared.global [%0], [%1], 16;" :: "r"(bdst + off), "l"(srcB));
        }
        asm volatile("cp.async.commit_group;");
    };

    auto compute = [&](int buf) {
        uint32_t ab = sb + A_OFF(buf), bb = sb + B_OFF(buf);
#pragma unroll
        for (int ks = 0; ks < 4; ks++) {
            uint32_t a[4][4], bf[2][4];
            const int kk = ks * 16 + (lane >> 4) * 8;
            const int mrow = warp_m * 64 + (lane & 15);
#pragma unroll
            for (int mf = 0; mf < 4; mf++) {
                uint32_t addr = ab + SWZ((uint32_t)((mrow + mf * 16) * 128 + kk * 2));
                asm volatile("ldmatrix.sync.aligned.m8n8.x4.shared.b16 {%0,%1,%2,%3}, [%4];"
                    : "=r"(a[mf][0]), "=r"(a[mf][1]), "=r"(a[mf][2]), "=r"(a[mf][3]) : "r"(addr));
            }
            const int nrow = warp_n * 32 + (lane & 15);
#pragma unroll
            for (int p = 0; p < 2; p++) {
                uint32_t addr = bb + SWZ((uint32_t)((nrow + p * 16) * 128 + kk * 2));
                asm volatile("ldmatrix.sync.aligned.m8n8.x4.shared.b16 {%0,%1,%2,%3}, [%4];"
                    : "=r"(bf[p][0]), "=r"(bf[p][1]), "=r"(bf[p][2]), "=r"(bf[p][3]) : "r"(addr));
            }
#pragma unroll
            for (int mf = 0; mf < 4; mf++)
#pragma unroll
                for (int nf = 0; nf < 4; nf++) {
                    uint32_t b0 = bf[nf >> 1][nf & 1], b1 = bf[nf >> 1][(nf & 1) + 2];
                    asm volatile(
                        "mma.sync.aligned.m16n8k16.row.col.f32.f16.f16.f32 "
                        "{%0,%1,%2,%3}, {%4,%5,%6,%7}, {%8,%9}, {%0,%1,%2,%3};"
                        : "+f"(acc[mf][nf][0]), "+f"(acc[mf][nf][1]),
                          "+f"(acc[mf][nf][2]), "+f"(acc[mf][nf][3])
                        : "r"(a[mf][0]), "r"(a[mf][1]), "r"(a[mf][2]), "r"(a[mf][3]),
                          "r"(b0), "r"(b1));
                }
        }
    };

    // 2-stage pipeline, loads issued BEFORE wait
    load_stage(0, 0);
    for (int s = 0; s < NCH; s++) {
        if (s + 1 < NCH) load_stage(s + 1, (s + 1) & 1);
        if (s + 1 < NCH) asm volatile("cp.async.wait_group 1;");
        else             asm volatile("cp.async.wait_group 0;");
        __syncthreads();
        compute(s & 1);
        __syncthreads();
    }

    // epilogue: BN + sign + bit-pack (validated R3/R7)
    const int tg = lane & 3, gid = lane >> 2;
    float scv[4][2], ofv[4][2];
#pragma unroll
    for (int nf = 0; nf < 4; nf++) {
        int cl = warp_n * 32 + nf * 8 + tg * 2;
        scv[nf][0] = ssc[cl];     ofv[nf][0] = sof[cl];
        scv[nf][1] = ssc[cl + 1]; ofv[nf][1] = sof[cl + 1];
    }
    const int widx = (bn >> 5) + warp_n;
#pragma unroll
    for (int mf = 0; mf < 4; mf++) {
        unsigned mA = 0, mB = 0;
#pragma unroll
        for (int nf = 0; nf < 4; nf++) {
            int p = nf * 8 + tg * 2;
            float f00 = fmaf(acc[mf][nf][0], scv[nf][0], ofv[nf][0]);
            float f01 = fmaf(acc[mf][nf][1], scv[nf][1], ofv[nf][1]);
            float f10 = fmaf(acc[mf][nf][2], scv[nf][0], ofv[nf][0]);
            float f11 = fmaf(acc[mf][nf][3], scv[nf][1], ofv[nf][1]);
            mA |= ((f00 >= 0.f ? 1u : 0u) << p) | ((f01 >= 0.f ? 1u : 0u) << (p + 1));
            mB |= ((f10 >= 0.f ? 1u : 0u) << p) | ((f11 >= 0.f ? 1u : 0u) << (p + 1));
        }
        mA |= __shfl_xor_sync(0xffffffffu, mA, 1); mA |= __shfl_xor_sync(0xffffffffu, mA, 2);
        mB |= __shfl_xor_sync(0xffffffffu, mB, 1); mB |= __shfl_xor_sync(0xffffffffu, mB, 2);
        if (tg == 0) {
            int row = bm + warp_m * 64 + mf * 16 + gid;
            g_bits1[row * HW + widx]       = mA;
            g_bits1[(row + 8) * HW + widx] = mB;
        }
    }
}

// ---------------- fc2 / fc3: XNOR-popcount, weights in smem ----------------
#define FC_SMEM (HW * H * 4 + 2 * H * 4)   // 79872

__global__ __launch_bounds__(256)
void fc2_kernel() {
    extern __shared__ char smem[];
    unsigned* ws = (unsigned*)smem;
    float* ssc = (float*)(smem + HW * H * 4);
    float* sof = ssc + H;
    const int tid = threadIdx.x, lane = tid & 31, wid = tid >> 5;
    for (int i = tid; i < HW * H; i += 256) ws[i] = g_w2bits[i];
    for (int i = tid; i < H; i += 256) { ssc[i] = g_sc2[i]; sof[i] = g_of2[i]; }
    __syncthreads();
    const int row0 = blockIdx.x * 64 + wid * 8;
#pragma unroll 1
    for (int rr = 0; rr < 8; rr++) {
        const int b = row0 + rr;
        const uint4* ap = (const uint4*)&g_bits1[b * HW];
        uint4 a0 = ap[0], a1 = ap[1], a2 = ap[2], a3 = ap[3], a4 = ap[4], a5 = ap[5];
        unsigned a[24] = {a0.x,a0.y,a0.z,a0.w, a1.x,a1.y,a1.z,a1.w, a2.x,a2.y,a2.z,a2.w,
                          a3.x,a3.y,a3.z,a3.w, a4.x,a4.y,a4.z,a4.w, a5.x,a5.y,a5.z,a5.w};
#pragma unroll 1
        for (int jw = 0; jw < HW; jw++) {
            const int j = jw * 32 + lane;
            int c0 = 0, c1 = 0;
#pragma unroll
            for (int k = 0; k < HW; k += 2) {
                c0 += __popc(a[k]     ^ ws[k * H + j]);
                c1 += __popc(a[k + 1] ^ ws[(k + 1) * H + j]);
            }
            float pop = (float)(H - 2 * (c0 + c1));
            float f = fmaf(pop, ssc[j], sof[j]);
            unsigned bal = __ballot_sync(0xffffffffu, f >= 0.f);
            if (lane == 0) g_bits2[b * HW + jw] = bal;
        }
    }
}

__global__ __launch_bounds__(256)
void fc3_kernel() {
    extern __shared__ char smem[];
    unsigned* ws = (unsigned*)smem;
    float* ssc = (float*)(smem + HW * H * 4);
    float* sof = ssc + H;
    const int tid = threadIdx.x, lane = tid & 31, wid = tid >> 5;
    for (int i = tid; i < HW * H; i += 256) ws[i] = g_w3bits[i];
    for (int i = tid; i < H; i += 256) { ssc[i] = g_sc3[i]; sof[i] = g_of3[i]; }
    __syncthreads();
    const int row0 = blockIdx.x * 64 + wid * 8;
#pragma unroll 1
    for (int rr = 0; rr < 8; rr++) {
        const int b = row0 + rr;
        const uint4* ap = (const uint4*)&g_bits2[b * HW];
        uint4 a0 = ap[0], a1 = ap[1], a2 = ap[2], a3 = ap[3], a4 = ap[4], a5 = ap[5];
        unsigned a[24] = {a0.x,a0.y,a0.z,a0.w, a1.x,a1.y,a1.z,a1.w, a2.x,a2.y,a2.z,a2.w,
                          a3.x,a3.y,a3.z,a3.w, a4.x,a4.y,a4.z,a4.w, a5.x,a5.y,a5.z,a5.w};
#pragma unroll 1
        for (int jw = 0; jw < HW; jw++) {
            const int j = jw * 32 + lane;
            int c0 = 0, c1 = 0;
#pragma unroll
            for (int k = 0; k < HW; k += 2) {
                c0 += __popc(a[k]     ^ ws[k * H + j]);
                c1 += __popc(a[k + 1] ^ ws[(k + 1) * H + j]);
            }
            float pop = (float)(H - 2 * (c0 + c1));
            float f = fmaf(pop, ssc[j], sof[j]);
            g_h3[(size_t)b * H + j] = __float2half(fminf(fmaxf(f, -1.f), 1.f));
        }
    }
}

// ---------------- fc4: GEMV + log_softmax, W4 in smem ----------------
__global__ __launch_bounds__(256)
void fc4_kernel(const float* __restrict__ W4, const float* __restrict__ b4,
                float* __restrict__ out) {
    __shared__ float sW[C * H];
    const int tid = threadIdx.x, lane = tid & 31, wid = tid >> 5;
    for (int i = tid; i < C * H; i += 256) sW[i] = W4[i];
    __syncthreads();
    const int row0 = blockIdx.x * 32 + wid * 4;
#pragma unroll 1
    for (int rr = 0; rr < 4; rr++) {
        const int w = row0 + rr;
        const __half2* hp = (const __half2*)&g_h3[(size_t)w * H];
        float acc[C];
#pragma unroll
        for (int c = 0; c < C; c++) acc[c] = 0.f;
#pragma unroll
        for (int t = 0; t < 12; t++) {
            int k2 = t * 32 + lane;
            float2 hv = __half22float2(hp[k2]);
#pragma unroll
            for (int c = 0; c < C; c++)
                acc[c] += hv.x * sW[c * H + 2 * k2] + hv.y * sW[c * H + 2 * k2 + 1];
        }
#pragma unroll
        for (int c = 0; c < C; c++)
#pragma unroll
            for (int off = 16; off > 0; off >>= 1)
                acc[c] += __shfl_xor_sync(0xffffffffu, acc[c], off);
        float lg[C], mx = -3.402823466e+38f;
#pragma unroll
        for (int c = 0; c < C; c++) { lg[c] = acc[c] + b4[c]; mx = fmaxf(mx, lg[c]); }
        float s = 0.f;
#pragma unroll
        for (int c = 0; c < C; c++) s += expf(lg[c] - mx);
        float lse = logf(s);
        if (lane < C) out[w * C + lane] = (lg[lane] - mx) - lse;
    }
}

// ---------------- launch (fc1 is launch #4 -> captured by ncu) ----------------
extern "C" void kernel_launch(void* const* d_in, const int* in_sizes, int n_in,
                              void* d_out, int out_size) {
    const float* x   = (const float*)d_in[0];
    const float* W1  = (const float*)d_in[1];
    const float* b1  = (const float*)d_in[2];
    const float* W2  = (const float*)d_in[3];
    const float* b2  = (const float*)d_in[4];
    const float* W3  = (const float*)d_in[5];
    const float* b3  = (const float*)d_in[6];
    const float* W4  = (const float*)d_in[7];
    const float* b4  = (const float*)d_in[8];
    const float* g1  = (const float*)d_in[9];
    const float* be1 = (const float*)d_in[10];
    const float* m1  = (const float*)d_in[11];
    const float* v1  = (const float*)d_in[12];
    const float* g2  = (const float*)d_in[13];
    const float* be2 = (const float*)d_in[14];
    const float* m2  = (const float*)d_in[15];
    const float* v2  = (const float*)d_in[16];
    const float* g3  = (const float*)d_in[17];
    const float* be3 = (const float*)d_in[18];
    const float* m3  = (const float*)d_in[19];
    const float* v3  = (const float*)d_in[20];
    float* out = (float*)d_out;

    cudaFuncSetAttribute(fc1_gemm,   cudaFuncAttributeMaxDynamicSharedMemorySize, FC1_SMEM);
    cudaFuncSetAttribute(fc2_kernel, cudaFuncAttributeMaxDynamicSharedMemorySize, FC_SMEM);
    cudaFuncSetAttribute(fc3_kernel, cudaFuncAttributeMaxDynamicSharedMemorySize, FC_SMEM);

    prep_scales<<<1, H>>>(b1, g1, m1, be1, v1, b2, g2, m2, be2, v2, b3, g3, m3, be3, v3);
    prep_A<<<(B * 204 + 255) / 256, 256>>>(x);
    prep_Wb<<<(H * 204 + 255) / 256, 256>>>(W1);

    fc1_gemm<<<dim3(H / TN, B / TM), 256, FC1_SMEM>>>();      // launch #4

    pack_wbits<<<(2 * HW * H + 255) / 256, 256>>>(W2, W3);
    fc2_kernel<<<B / 64, 256, FC_SMEM>>>();
    fc3_kernel<<<B / 64, 256, FC_SMEM>>>();
    fc4_kernel<<<B / 32, 256>>>(W4, b4, out);
}

// round 10
// speedup vs baseline: 1.9123x; 1.2264x over previous
#include <cuda_runtime.h>
#include <cuda_fp16.h>
#include <cstdint>

#define B   16384
#define D   784
#define H   768
#define C   10
#define HW  24            // H/32
#define K2  1600          // 2*784 + 32 pad (fp16 2-term split)
#define NCH 25            // K2/64 chunks (fp16, 128B)
#define TM  128
#define TN  128

// ---------------- device scratch ----------------
__device__ __align__(128) __half g_A[(size_t)B * K2];    // hi|lo split activations
__device__ __align__(128) __half g_Wb[(size_t)H * K2];   // sign(W1) fp16 x2 (pad 0)
__device__ unsigned g_bits1[B * HW];
__device__ unsigned g_bits2[B * HW];
__device__ unsigned g_w2bits[HW * H];
__device__ unsigned g_w3bits[HW * H];
__device__ float g_sc1[H], g_of1[H], g_sc2[H], g_of2[H], g_sc3[H], g_of3[H];

#define SWZ(o) ((o) ^ (((o) >> 3) & 0x70))

__device__ __forceinline__ uint32_t smem_u32(const void* p) {
    uint32_t a;
    asm("{ .reg .u64 t; cvta.to.shared.u64 t, %1; cvt.u32.u64 %0, t; }" : "=r"(a) : "l"(p));
    return a;
}

// ---------------- prep #1: folded BN scales + bit-pack W2/W3 ----------------
__global__ void prep_misc(const float* __restrict__ W2, const float* __restrict__ W3,
                          const float* b1, const float* g1, const float* m1, const float* be1, const float* v1,
                          const float* b2, const float* g2, const float* m2, const float* be2, const float* v2,
                          const float* b3, const float* g3, const float* m3, const float* be3, const float* v3) {
    int t = blockIdx.x * blockDim.x + threadIdx.x;
    if (t < H) {
        int j = t;
        float s1 = g1[j] * (float)(1.0 / sqrt((double)(v1[j] + 1e-5f)));
        float s2 = g2[j] * (float)(1.0 / sqrt((double)(v2[j] + 1e-5f)));
        float s3 = g3[j] * (float)(1.0 / sqrt((double)(v3[j] + 1e-5f)));
        g_sc1[j] = s1; g_of1[j] = (b1[j] - m1[j]) * s1 + be1[j];
        g_sc2[j] = s2; g_of2[j] = (b2[j] - m2[j]) * s2 + be2[j];
        g_sc3[j] = s3; g_of3[j] = (b3[j] - m3[j]) * s3 + be3[j];
        return;
    }
    int q = t - H;
    if (q >= 2 * HW * H) return;
    int which = q >= HW * H;
    if (which) q -= HW * H;
    const float* W = which ? W3 : W2;
    int kw = q / H, j = q % H;
    const float* p = &W[j * H + kw * 32];
    unsigned word = 0;
#pragma unroll
    for (int i = 0; i < 32; i++) word |= (p[i] >= 0.f ? 1u : 0u) << i;
    if (which) g_w3bits[kw * H + j] = word;
    else       g_w2bits[kw * H + j] = word;
}

// ---------------- prep #2: fp16 split of x AND sign(W1) in one kernel -------
__global__ void prep_split(const float* __restrict__ X, const float* __restrict__ W1) {
    int idx = blockIdx.x * blockDim.x + threadIdx.x;
    if (idx < B * 204) {
        int b = idx / 204, q = idx - b * 204;
        __half* row = &g_A[(size_t)b * K2];
        if (q >= 196) {
            uint2 z = {0, 0};
            *(uint2*)&row[1568 + (q - 196) * 4] = z;
            return;
        }
        int kg = q * 4;
        float4 xv = *(const float4*)&X[b * D + kg];
        float xs[4] = {xv.x, xv.y, xv.z, xv.w};
        __align__(8) __half hi[4], lo[4];
#pragma unroll
        for (int i = 0; i < 4; i++) {
            float x = xs[i];
            __half h = __float2half_rn(x);
            hi[i] = h;
            lo[i] = __float2half_rn(x - __half2float(h));
        }
        *(uint2*)&row[kg]       = *(uint2*)hi;
        *(uint2*)&row[784 + kg] = *(uint2*)lo;
        return;
    }
    int idx2 = idx - B * 204;
    if (idx2 >= H * 204) return;
    int j = idx2 / 204, q = idx2 - j * 204;
    __half* row = &g_Wb[(size_t)j * K2];
    if (q >= 196) {
        uint2 z = {0, 0};
        *(uint2*)&row[1568 + (q - 196) * 4] = z;
        return;
    }
    int kg = q * 4;
    float4 wv = *(const float4*)&W1[j * D + kg];
    __align__(8) __half o[4];
    o[0] = __float2half(wv.x >= 0.f ? 1.f : -1.f);
    o[1] = __float2half(wv.y >= 0.f ? 1.f : -1.f);
    o[2] = __float2half(wv.z >= 0.f ? 1.f : -1.f);
    o[3] = __float2half(wv.w >= 0.f ? 1.f : -1.f);
    *(uint2*)&row[kg]       = *(uint2*)o;
    *(uint2*)&row[784 + kg] = *(uint2*)o;
}

// ---------------- fc1: fp16 mma.sync GEMM + bit-pack (unchanged, R9) --------
#define FC1_SMEM 66560
#define A_OFF(b) (1024u + (b) * 16384u)
#define B_OFF(b) (33792u + (b) * 16384u)

__global__ __launch_bounds__(256, 2)
void fc1_gemm() {
    extern __shared__ char smem[];
    const uint32_t sb = smem_u32(smem);
    const int tid = threadIdx.x;
    const int wid = tid >> 5, lane = tid & 31;
    const int warp_m = wid >> 2, warp_n = wid & 3;
    const int bn = blockIdx.x * TN, bm = blockIdx.y * TM;

    float* ssc = (float*)(smem);
    float* sof = (float*)(smem + 512);
    if (tid < 128) { ssc[tid] = g_sc1[bn + tid]; sof[tid] = g_of1[bn + tid]; }

    const char* Abase = (const char*)g_A  + (size_t)bm * (K2 * 2);
    const char* Bbase = (const char*)g_Wb + (size_t)bn * (K2 * 2);

    float acc[4][4][4];
#pragma unroll
    for (int i = 0; i < 4; i++)
#pragma unroll
        for (int j = 0; j < 4; j++)
#pragma unroll
            for (int c = 0; c < 4; c++) acc[i][j][c] = 0.f;

    auto load_stage = [&](int s, int buf) {
        size_t kb = (size_t)s * 128;
        uint32_t adst = sb + A_OFF(buf), bdst = sb + B_OFF(buf);
#pragma unroll
        for (int i = 0; i < 4; i++) {
            int idx = i * 256 + tid;
            int row = idx >> 3, c = idx & 7;
            uint32_t off = SWZ((uint32_t)(row * 128 + c * 16));
            const char* srcA = Abase + (size_t)row * (K2 * 2) + kb + c * 16;
            const char* srcB = Bbase + (size_t)row * (K2 * 2) + kb + c * 16;
            asm volatile("cp.async.cg.shared.global [%0], [%1], 16;" :: "r"(adst + off), "l"(srcA));
            asm volatile("cp.async.cg.shared.global [%0], [%1], 16;" :: "r"(bdst + off), "l"(srcB));
        }
        asm volatile("cp.async.commit_group;");
    };

    auto compute = [&](int buf) {
        uint32_t ab = sb + A_OFF(buf), bb = sb + B_OFF(buf);
#pragma unroll
        for (int ks = 0; ks < 4; ks++) {
            uint32_t a[4][4], bf[2][4];
            const int kk = ks * 16 + (lane >> 4) * 8;
            const int mrow = warp_m * 64 + (lane & 15);
#pragma unroll
            for (int mf = 0; mf < 4; mf++) {
                uint32_t addr = ab + SWZ((uint32_t)((mrow + mf * 16) * 128 + kk * 2));
                asm volatile("ldmatrix.sync.aligned.m8n8.x4.shared.b16 {%0,%1,%2,%3}, [%4];"
                    : "=r"(a[mf][0]), "=r"(a[mf][1]), "=r"(a[mf][2]), "=r"(a[mf][3]) : "r"(addr));
            }
            const int nrow = warp_n * 32 + (lane & 15);
#pragma unroll
            for (int p = 0; p < 2; p++) {
                uint32_t addr = bb + SWZ((uint32_t)((nrow + p * 16) * 128 + kk * 2));
                asm volatile("ldmatrix.sync.aligned.m8n8.x4.shared.b16 {%0,%1,%2,%3}, [%4];"
                    : "=r"(bf[p][0]), "=r"(bf[p][1]), "=r"(bf[p][2]), "=r"(bf[p][3]) : "r"(addr));
            }
#pragma unroll
            for (int mf = 0; mf < 4; mf++)
#pragma unroll
                for (int nf = 0; nf < 4; nf++) {
                    uint32_t b0 = bf[nf >> 1][nf & 1], b1 = bf[nf >> 1][(nf & 1) + 2];
                    asm volatile(
                        "mma.sync.aligned.m16n8k16.row.col.f32.f16.f16.f32 "
                        "{%0,%1,%2,%3}, {%4,%5,%6,%7}, {%8,%9}, {%0,%1,%2,%3};"
                        : "+f"(acc[mf][nf][0]), "+f"(acc[mf][nf][1]),
                          "+f"(acc[mf][nf][2]), "+f"(acc[mf][nf][3])
                        : "r"(a[mf][0]), "r"(a[mf][1]), "r"(a[mf][2]), "r"(a[mf][3]),
                          "r"(b0), "r"(b1));
                }
        }
    };

    load_stage(0, 0);
    for (int s = 0; s < NCH; s++) {
        if (s + 1 < NCH) load_stage(s + 1, (s + 1) & 1);
        if (s + 1 < NCH) asm volatile("cp.async.wait_group 1;");
        else             asm volatile("cp.async.wait_group 0;");
        __syncthreads();
        compute(s & 1);
        __syncthreads();
    }

    const int tg = lane & 3, gid = lane >> 2;
    float scv[4][2], ofv[4][2];
#pragma unroll
    for (int nf = 0; nf < 4; nf++) {
        int cl = warp_n * 32 + nf * 8 + tg * 2;
        scv[nf][0] = ssc[cl];     ofv[nf][0] = sof[cl];
        scv[nf][1] = ssc[cl + 1]; ofv[nf][1] = sof[cl + 1];
    }
    const int widx = (bn >> 5) + warp_n;
#pragma unroll
    for (int mf = 0; mf < 4; mf++) {
        unsigned mA = 0, mB = 0;
#pragma unroll
        for (int nf = 0; nf < 4; nf++) {
            int p = nf * 8 + tg * 2;
            float f00 = fmaf(acc[mf][nf][0], scv[nf][0], ofv[nf][0]);
            float f01 = fmaf(acc[mf][nf][1], scv[nf][1], ofv[nf][1]);
            float f10 = fmaf(acc[mf][nf][2], scv[nf][0], ofv[nf][0]);
            float f11 = fmaf(acc[mf][nf][3], scv[nf][1], ofv[nf][1]);
            mA |= ((f00 >= 0.f ? 1u : 0u) << p) | ((f01 >= 0.f ? 1u : 0u) << (p + 1));
            mB |= ((f10 >= 0.f ? 1u : 0u) << p) | ((f11 >= 0.f ? 1u : 0u) << (p + 1));
        }
        mA |= __shfl_xor_sync(0xffffffffu, mA, 1); mA |= __shfl_xor_sync(0xffffffffu, mA, 2);
        mB |= __shfl_xor_sync(0xffffffffu, mB, 1); mB |= __shfl_xor_sync(0xffffffffu, mB, 2);
        if (tg == 0) {
            int row = bm + warp_m * 64 + mf * 16 + gid;
            g_bits1[row * HW + widx]       = mA;
            g_bits1[(row + 8) * HW + widx] = mB;
        }
    }
}

// ---------------- fc2: XNOR-popcount, 4-row register tile -------------------
#define FC2_SMEM (HW * H * 4 + 2 * H * 4)   // 79872

__global__ __launch_bounds__(256, 2)
void fc2_kernel() {
    extern __shared__ char smem[];
    unsigned* ws = (unsigned*)smem;
    float* ssc = (float*)(smem + HW * H * 4);
    float* sof = ssc + H;
    const int tid = threadIdx.x, lane = tid & 31, wid = tid >> 5;
    for (int i = tid; i < HW * H; i += 256) ws[i] = g_w2bits[i];
    for (int i = tid; i < H; i += 256) { ssc[i] = g_sc2[i]; sof[i] = g_of2[i]; }
    __syncthreads();
    const int row0 = blockIdx.x * 64 + wid * 8;
#pragma unroll 1
    for (int g = 0; g < 2; g++) {
        const int rb = row0 + g * 4;
        unsigned a[4][24];
#pragma unroll
        for (int r = 0; r < 4; r++) {
            const uint4* ap = (const uint4*)&g_bits1[(rb + r) * HW];
#pragma unroll
            for (int t = 0; t < 6; t++) {
                uint4 v = ap[t];
                a[r][t * 4 + 0] = v.x; a[r][t * 4 + 1] = v.y;
                a[r][t * 4 + 2] = v.z; a[r][t * 4 + 3] = v.w;
            }
        }
#pragma unroll 1
        for (int jw = 0; jw < HW; jw++) {
            const int j = jw * 32 + lane;
            int cnt[4] = {0, 0, 0, 0};
#pragma unroll
            for (int k = 0; k < HW; k++) {
                unsigned wk = ws[k * H + j];
                cnt[0] += __popc(a[0][k] ^ wk);
                cnt[1] += __popc(a[1][k] ^ wk);
                cnt[2] += __popc(a[2][k] ^ wk);
                cnt[3] += __popc(a[3][k] ^ wk);
            }
            const float sc = ssc[j], of = sof[j];
#pragma unroll
            for (int r = 0; r < 4; r++) {
                float f = fmaf((float)(H - 2 * cnt[r]), sc, of);
                unsigned bal = __ballot_sync(0xffffffffu, f >= 0.f);
                if (lane == 0) g_bits2[(rb + r) * HW + jw] = bal;
            }
        }
    }
}

// ---------------- fc3+fc4 fused: popcount + BN/hardtanh + GEMV + logsoftmax --
// smem: ws 73728 | ssc 3072 | sof 3072 | sW4 30720 | b4 64
#define FC3_SMEM (HW * H * 4 + 2 * H * 4 + C * H * 4 + 64)   // 110656

__global__ __launch_bounds__(256, 2)
void fc3_fused(const float* __restrict__ W4, const float* __restrict__ b4,
               float* __restrict__ out) {
    extern __shared__ char smem[];
    unsigned* ws = (unsigned*)smem;
    float* ssc = (float*)(smem + HW * H * 4);
    float* sof = ssc + H;
    float* sW4 = sof + H;
    float* sb4 = sW4 + C * H;
    const int tid = threadIdx.x, lane = tid & 31, wid = tid >> 5;
    for (int i = tid; i < HW * H; i += 256) ws[i] = g_w3bits[i];
    for (int i = tid; i < H; i += 256) { ssc[i] = g_sc3[i]; sof[i] = g_of3[i]; }
    for (int i = tid; i < C * H; i += 256) sW4[i] = W4[i];
    if (tid < C) sb4[tid] = b4[tid];
    __syncthreads();
    const int row0 = blockIdx.x * 64 + wid * 8;
#pragma unroll 1
    for (int g = 0; g < 4; g++) {
        const int rb = row0 + g * 2;
        unsigned a[2][24];
#pragma unroll
        for (int r = 0; r < 2; r++) {
            const uint4* ap = (const uint4*)&g_bits2[(rb + r) * HW];
#pragma unroll
            for (int t = 0; t < 6; t++) {
                uint4 v = ap[t];
                a[r][t * 4 + 0] = v.x; a[r][t * 4 + 1] = v.y;
                a[r][t * 4 + 2] = v.z; a[r][t * 4 + 3] = v.w;
            }
        }
        float acc0[C], acc1[C];
#pragma unroll
        for (int c = 0; c < C; c++) { acc0[c] = 0.f; acc1[c] = 0.f; }
#pragma unroll 1
        for (int jw = 0; jw < HW; jw++) {
            const int j = jw * 32 + lane;
            int c0 = 0, c1 = 0;
#pragma unroll
            for (int k = 0; k < HW; k++) {
                unsigned wk = ws[k * H + j];
                c0 += __popc(a[0][k] ^ wk);
                c1 += __popc(a[1][k] ^ wk);
            }
            const float sc = ssc[j], of = sof[j];
            float h0 = fminf(fmaxf(fmaf((float)(H - 2 * c0), sc, of), -1.f), 1.f);
            float h1 = fminf(fmaxf(fmaf((float)(H - 2 * c1), sc, of), -1.f), 1.f);
#pragma unroll
            for (int c = 0; c < C; c++) {
                float w4 = sW4[c * H + j];
                acc0[c] = fmaf(h0, w4, acc0[c]);
                acc1[c] = fmaf(h1, w4, acc1[c]);
            }
        }
        // per-row logsoftmax
#pragma unroll
        for (int r = 0; r < 2; r++) {
            float lg[C], mx = -3.402823466e+38f;
#pragma unroll
            for (int c = 0; c < C; c++) {
                float v = (r == 0) ? acc0[c] : acc1[c];
#pragma unroll
                for (int off = 16; off > 0; off >>= 1)
                    v += __shfl_xor_sync(0xffffffffu, v, off);
                lg[c] = v + sb4[c];
                mx = fmaxf(mx, lg[c]);
            }
            float s = 0.f;
#pragma unroll
            for (int c = 0; c < C; c++) s += expf(lg[c] - mx);
            float lse = logf(s);
            float myv = 0.f;
#pragma unroll
            for (int c = 0; c < C; c++) if (lane == c) myv = lg[c];
            if (lane < C) out[(rb + r) * C + lane] = myv - mx - lse;
        }
    }
}

// ---------------- launch (fc2 is launch #4 -> captured by ncu) ----------------
extern "C" void kernel_launch(void* const* d_in, const int* in_sizes, int n_in,
                              void* d_out, int out_size) {
    const float* x   = (const float*)d_in[0];
    const float* W1  = (const float*)d_in[1];
    const float* b1  = (const float*)d_in[2];
    const float* W2  = (const float*)d_in[3];
    const float* b2  = (const float*)d_in[4];
    const float* W3  = (const float*)d_in[5];
    const float* b3  = (const float*)d_in[6];
    const float* W4  = (const float*)d_in[7];
    const float* b4  = (const float*)d_in[8];
    const float* g1  = (const float*)d_in[9];
    const float* be1 = (const float*)d_in[10];
    const float* m1  = (const float*)d_in[11];
    const float* v1  = (const float*)d_in[12];
    const float* g2  = (const float*)d_in[13];
    const float* be2 = (const float*)d_in[14];
    const float* m2  = (const float*)d_in[15];
    const float* v2  = (const float*)d_in[16];
    const float* g3  = (const float*)d_in[17];
    const float* be3 = (const float*)d_in[18];
    const float* m3  = (const float*)d_in[19];
    const float* v3  = (const float*)d_in[20];
    float* out = (float*)d_out;

    cudaFuncSetAttribute(fc1_gemm,   cudaFuncAttributeMaxDynamicSharedMemorySize, FC1_SMEM);
    cudaFuncSetAttribute(fc2_kernel, cudaFuncAttributeMaxDynamicSharedMemorySize, FC2_SMEM);
    cudaFuncSetAttribute(fc3_fused,  cudaFuncAttributeMaxDynamicSharedMemorySize, FC3_SMEM);

    int miscThreads = H + 2 * HW * H;
    prep_misc<<<(miscThreads + 255) / 256, 256>>>(W2, W3,
        b1, g1, m1, be1, v1, b2, g2, m2, be2, v2, b3, g3, m3, be3, v3);

    int splitThreads = B * 204 + H * 204;
    prep_split<<<(splitThreads + 255) / 256, 256>>>(x, W1);

    fc1_gemm<<<dim3(H / TN, B / TM), 256, FC1_SMEM>>>();

    fc2_kernel<<<B / 64, 256, FC2_SMEM>>>();                  // launch #4 (profiled)

    fc3_fused<<<B / 64, 256, FC3_SMEM>>>(W4, b4, out);
}

// round 11
// speedup vs baseline: 2.0115x; 1.0519x over previous
#include <cuda_runtime.h>
#include <cuda_fp16.h>
#include <cstdint>

#define B   16384
#define D   784
#define H   768
#define C   10
#define HW  24            // H/32
#define K2  1600          // 2*784 + 32 pad (fp16 2-term split)
#define NCH 25            // fc1 K chunks (128B)
#define NC2 12            // fc2 K chunks: 768*2B / 128B
#define TM  128
#define TN  128

// ---------------- device scratch ----------------
__device__ __align__(128) __half g_A[(size_t)B * K2];    // hi|lo split activations
__device__ __align__(128) __half g_Wb[(size_t)H * K2];   // sign(W1) fp16 x2 (pad 0)
__device__ __align__(128) __half g_a2h[(size_t)B * H];   // fc2 input, fp16 +-1
__device__ __align__(128) __half g_w2h[H * H];           // sign(W2) fp16
__device__ unsigned g_bits2[B * HW];
__device__ unsigned g_w3bits[HW * H];
__device__ float g_sc1[H], g_of1[H], g_sc2[H], g_of2[H], g_sc3[H], g_of3[H];

#define SWZ(o) ((o) ^ (((o) >> 3) & 0x70))

__device__ __forceinline__ uint32_t smem_u32(const void* p) {
    uint32_t a;
    asm("{ .reg .u64 t; cvta.to.shared.u64 t, %1; cvt.u32.u64 %0, t; }" : "=r"(a) : "l"(p));
    return a;
}

// ---------------- prep #1: folded BN scales + bit-pack W3 ----------------
__global__ void prep_misc(const float* __restrict__ W3,
                          const float* b1, const float* g1, const float* m1, const float* be1, const float* v1,
                          const float* b2, const float* g2, const float* m2, const float* be2, const float* v2,
                          const float* b3, const float* g3, const float* m3, const float* be3, const float* v3) {
    int t = blockIdx.x * blockDim.x + threadIdx.x;
    if (t < H) {
        int j = t;
        float s1 = g1[j] * (float)(1.0 / sqrt((double)(v1[j] + 1e-5f)));
        float s2 = g2[j] * (float)(1.0 / sqrt((double)(v2[j] + 1e-5f)));
        float s3 = g3[j] * (float)(1.0 / sqrt((double)(v3[j] + 1e-5f)));
        g_sc1[j] = s1; g_of1[j] = (b1[j] - m1[j]) * s1 + be1[j];
        g_sc2[j] = s2; g_of2[j] = (b2[j] - m2[j]) * s2 + be2[j];
        g_sc3[j] = s3; g_of3[j] = (b3[j] - m3[j]) * s3 + be3[j];
        return;
    }
    int q = t - H;
    if (q >= HW * H) return;
    int kw = q / H, j = q % H;
    const float* p = &W3[j * H + kw * 32];
    unsigned word = 0;
#pragma unroll
    for (int i = 0; i < 32; i++) word |= (p[i] >= 0.f ? 1u : 0u) << i;
    g_w3bits[kw * H + j] = word;
}

// ---------------- prep #2: fp16 split of x, sign(W1), sign(W2) --------------
__global__ void prep_split(const float* __restrict__ X, const float* __restrict__ W1,
                           const float* __restrict__ W2) {
    int idx = blockIdx.x * blockDim.x + threadIdx.x;
    if (idx < B * 204) {
        int b = idx / 204, q = idx - b * 204;
        __half* row = &g_A[(size_t)b * K2];
        if (q >= 196) {
            uint2 z = {0, 0};
            *(uint2*)&row[1568 + (q - 196) * 4] = z;
            return;
        }
        int kg = q * 4;
        float4 xv = *(const float4*)&X[b * D + kg];
        float xs[4] = {xv.x, xv.y, xv.z, xv.w};
        __align__(8) __half hi[4], lo[4];
#pragma unroll
        for (int i = 0; i < 4; i++) {
            float x = xs[i];
            __half h = __float2half_rn(x);
            hi[i] = h;
            lo[i] = __float2half_rn(x - __half2float(h));
        }
        *(uint2*)&row[kg]       = *(uint2*)hi;
        *(uint2*)&row[784 + kg] = *(uint2*)lo;
        return;
    }
    int idx2 = idx - B * 204;
    if (idx2 < H * 204) {
        int j = idx2 / 204, q = idx2 - j * 204;
        __half* row = &g_Wb[(size_t)j * K2];
        if (q >= 196) {
            uint2 z = {0, 0};
            *(uint2*)&row[1568 + (q - 196) * 4] = z;
            return;
        }
        int kg = q * 4;
        float4 wv = *(const float4*)&W1[j * D + kg];
        __align__(8) __half o[4];
        o[0] = __float2half(wv.x >= 0.f ? 1.f : -1.f);
        o[1] = __float2half(wv.y >= 0.f ? 1.f : -1.f);
        o[2] = __float2half(wv.z >= 0.f ? 1.f : -1.f);
        o[3] = __float2half(wv.w >= 0.f ? 1.f : -1.f);
        *(uint2*)&row[kg]       = *(uint2*)o;
        *(uint2*)&row[784 + kg] = *(uint2*)o;
        return;
    }
    int idx3 = idx2 - H * 204;
    if (idx3 >= H * 192) return;   // sign(W2): 768*768/4 quads
    int kg = idx3 * 4;
    float4 wv = *(const float4*)&W2[kg];
    __align__(8) __half o[4];
    o[0] = __float2half(wv.x >= 0.f ? 1.f : -1.f);
    o[1] = __float2half(wv.y >= 0.f ? 1.f : -1.f);
    o[2] = __float2half(wv.z >= 0.f ? 1.f : -1.f);
    o[3] = __float2half(wv.w >= 0.f ? 1.f : -1.f);
    *(uint2*)&g_w2h[kg] = *(uint2*)o;
}

// ================= shared GEMM machinery (fc1 / fc2) =========================
#define GEMM_SMEM 66560
#define A_OFF(b) (1024u + (b) * 16384u)
#define B_OFF(b) (33792u + (b) * 16384u)

// ---------------- fc1: fp16 mma GEMM, epilogue -> fp16 +-1 (g_a2h) ----------
__global__ __launch_bounds__(256, 2)
void fc1_gemm() {
    extern __shared__ char smem[];
    const uint32_t sb = smem_u32(smem);
    const int tid = threadIdx.x;
    const int wid = tid >> 5, lane = tid & 31;
    const int warp_m = wid >> 2, warp_n = wid & 3;
    const int bn = blockIdx.x * TN, bm = blockIdx.y * TM;

    float* ssc = (float*)(smem);
    float* sof = (float*)(smem + 512);
    if (tid < 128) { ssc[tid] = g_sc1[bn + tid]; sof[tid] = g_of1[bn + tid]; }

    const char* Abase = (const char*)g_A  + (size_t)bm * (K2 * 2);
    const char* Bbase = (const char*)g_Wb + (size_t)bn * (K2 * 2);

    float acc[4][4][4];
#pragma unroll
    for (int i = 0; i < 4; i++)
#pragma unroll
        for (int j = 0; j < 4; j++)
#pragma unroll
            for (int c = 0; c < 4; c++) acc[i][j][c] = 0.f;

    auto load_stage = [&](int s, int buf) {
        size_t kb = (size_t)s * 128;
        uint32_t adst = sb + A_OFF(buf), bdst = sb + B_OFF(buf);
#pragma unroll
        for (int i = 0; i < 4; i++) {
            int idx = i * 256 + tid;
            int row = idx >> 3, c = idx & 7;
            uint32_t off = SWZ((uint32_t)(row * 128 + c * 16));
            const char* srcA = Abase + (size_t)row * (K2 * 2) + kb + c * 16;
            const char* srcB = Bbase + (size_t)row * (K2 * 2) + kb + c * 16;
            asm volatile("cp.async.cg.shared.global [%0], [%1], 16;" :: "r"(adst + off), "l"(srcA));
            asm volatile("cp.async.cg.shared.global [%0], [%1], 16;" :: "r"(bdst + off), "l"(srcB));
        }
        asm volatile("cp.async.commit_group;");
    };

    auto compute = [&](int buf) {
        uint32_t ab = sb + A_OFF(buf), bb = sb + B_OFF(buf);
#pragma unroll
        for (int ks = 0; ks < 4; ks++) {
            uint32_t a[4][4], bf[2][4];
            const int kk = ks * 16 + (lane >> 4) * 8;
            const int mrow = warp_m * 64 + (lane & 15);
#pragma unroll
            for (int mf = 0; mf < 4; mf++) {
                uint32_t addr = ab + SWZ((uint32_t)((mrow + mf * 16) * 128 + kk * 2));
                asm volatile("ldmatrix.sync.aligned.m8n8.x4.shared.b16 {%0,%1,%2,%3}, [%4];"
                    : "=r"(a[mf][0]), "=r"(a[mf][1]), "=r"(a[mf][2]), "=r"(a[mf][3]) : "r"(addr));
            }
            const int nrow = warp_n * 32 + (lane & 15);
#pragma unroll
            for (int p = 0; p < 2; p++) {
                uint32_t addr = bb + SWZ((uint32_t)((nrow + p * 16) * 128 + kk * 2));
                asm volatile("ldmatrix.sync.aligned.m8n8.x4.shared.b16 {%0,%1,%2,%3}, [%4];"
                    : "=r"(bf[p][0]), "=r"(bf[p][1]), "=r"(bf[p][2]), "=r"(bf[p][3]) : "r"(addr));
            }
#pragma unroll
            for (int mf = 0; mf < 4; mf++)
#pragma unroll
                for (int nf = 0; nf < 4; nf++) {
                    uint32_t b0 = bf[nf >> 1][nf & 1], b1 = bf[nf >> 1][(nf & 1) + 2];
                    asm volatile(
                        "mma.sync.aligned.m16n8k16.row.col.f32.f16.f16.f32 "
                        "{%0,%1,%2,%3}, {%4,%5,%6,%7}, {%8,%9}, {%0,%1,%2,%3};"
                        : "+f"(acc[mf][nf][0]), "+f"(acc[mf][nf][1]),
                          "+f"(acc[mf][nf][2]), "+f"(acc[mf][nf][3])
                        : "r"(a[mf][0]), "r"(a[mf][1]), "r"(a[mf][2]), "r"(a[mf][3]),
                          "r"(b0), "r"(b1));
                }
        }
    };

    load_stage(0, 0);
    for (int s = 0; s < NCH; s++) {
        if (s + 1 < NCH) load_stage(s + 1, (s + 1) & 1);
        if (s + 1 < NCH) asm volatile("cp.async.wait_group 1;");
        else             asm volatile("cp.async.wait_group 0;");
        __syncthreads();
        compute(s & 1);
        __syncthreads();
    }

    // epilogue: BN + sign -> fp16 +-1 into g_a2h (half2 stores)
    const int tg = lane & 3, gid = lane >> 2;
    float scv[4][2], ofv[4][2];
#pragma unroll
    for (int nf = 0; nf < 4; nf++) {
        int cl = warp_n * 32 + nf * 8 + tg * 2;
        scv[nf][0] = ssc[cl];     ofv[nf][0] = sof[cl];
        scv[nf][1] = ssc[cl + 1]; ofv[nf][1] = sof[cl + 1];
    }
    const __half hp1 = __float2half(1.f), hm1 = __float2half(-1.f);
#pragma unroll
    for (int mf = 0; mf < 4; mf++) {
        int row = bm + warp_m * 64 + mf * 16 + gid;
#pragma unroll
        for (int nf = 0; nf < 4; nf++) {
            int col = bn + warp_n * 32 + nf * 8 + tg * 2;
            float f00 = fmaf(acc[mf][nf][0], scv[nf][0], ofv[nf][0]);
            float f01 = fmaf(acc[mf][nf][1], scv[nf][1], ofv[nf][1]);
            float f10 = fmaf(acc[mf][nf][2], scv[nf][0], ofv[nf][0]);
            float f11 = fmaf(acc[mf][nf][3], scv[nf][1], ofv[nf][1]);
            __half2 hA = __halves2half2(f00 >= 0.f ? hp1 : hm1, f01 >= 0.f ? hp1 : hm1);
            __half2 hB = __halves2half2(f10 >= 0.f ? hp1 : hm1, f11 >= 0.f ? hp1 : hm1);
            *(__half2*)&g_a2h[(size_t)row * H + col]       = hA;
            *(__half2*)&g_a2h[(size_t)(row + 8) * H + col] = hB;
        }
    }
}

// ---------------- fc2: fp16 mma GEMM (exact +-1), epilogue -> bits2 ---------
__global__ __launch_bounds__(256, 2)
void fc2_gemm() {
    extern __shared__ char smem[];
    const uint32_t sb = smem_u32(smem);
    const int tid = threadIdx.x;
    const int wid = tid >> 5, lane = tid & 31;
    const int warp_m = wid >> 2, warp_n = wid & 3;
    const int bn = blockIdx.x * TN, bm = blockIdx.y * TM;

    float* ssc = (float*)(smem);
    float* sof = (float*)(smem + 512);
    if (tid < 128) { ssc[tid] = g_sc2[bn + tid]; sof[tid] = g_of2[bn + tid]; }

    const char* Abase = (const char*)g_a2h + (size_t)bm * (H * 2);
    const char* Bbase = (const char*)g_w2h + (size_t)bn * (H * 2);

    float acc[4][4][4];
#pragma unroll
    for (int i = 0; i < 4; i++)
#pragma unroll
        for (int j = 0; j < 4; j++)
#pragma unroll
            for (int c = 0; c < 4; c++) acc[i][j][c] = 0.f;

    auto load_stage = [&](int s, int buf) {
        size_t kb = (size_t)s * 128;
        uint32_t adst = sb + A_OFF(buf), bdst = sb + B_OFF(buf);
#pragma unroll
        for (int i = 0; i < 4; i++) {
            int idx = i * 256 + tid;
            int row = idx >> 3, c = idx & 7;
            uint32_t off = SWZ((uint32_t)(row * 128 + c * 16));
            const char* srcA = Abase + (size_t)row * (H * 2) + kb + c * 16;
            const char* srcB = Bbase + (size_t)row * (H * 2) + kb + c * 16;
            asm volatile("cp.async.cg.shared.global [%0], [%1], 16;" :: "r"(adst + off), "l"(srcA));
            asm volatile("cp.async.cg.shared.global [%0], [%1], 16;" :: "r"(bdst + off), "l"(srcB));
        }
        asm volatile("cp.async.commit_group;");
    };

    auto compute = [&](int buf) {
        uint32_t ab = sb + A_OFF(buf), bb = sb + B_OFF(buf);
#pragma unroll
        for (int ks = 0; ks < 4; ks++) {
            uint32_t a[4][4], bf[2][4];
            const int kk = ks * 16 + (lane >> 4) * 8;
            const int mrow = warp_m * 64 + (lane & 15);
#pragma unroll
            for (int mf = 0; mf < 4; mf++) {
                uint32_t addr = ab + SWZ((uint32_t)((mrow + mf * 16) * 128 + kk * 2));
                asm volatile("ldmatrix.sync.aligned.m8n8.x4.shared.b16 {%0,%1,%2,%3}, [%4];"
                    : "=r"(a[mf][0]), "=r"(a[mf][1]), "=r"(a[mf][2]), "=r"(a[mf][3]) : "r"(addr));
            }
            const int nrow = warp_n * 32 + (lane & 15);
#pragma unroll
            for (int p = 0; p < 2; p++) {
                uint32_t addr = bb + SWZ((uint32_t)((nrow + p * 16) * 128 + kk * 2));
                asm volatile("ldmatrix.sync.aligned.m8n8.x4.shared.b16 {%0,%1,%2,%3}, [%4];"
                    : "=r"(bf[p][0]), "=r"(bf[p][1]), "=r"(bf[p][2]), "=r"(bf[p][3]) : "r"(addr));
            }
#pragma unroll
            for (int mf = 0; mf < 4; mf++)
#pragma unroll
                for (int nf = 0; nf < 4; nf++) {
                    uint32_t b0 = bf[nf >> 1][nf & 1], b1 = bf[nf >> 1][(nf & 1) + 2];
                    asm volatile(
                        "mma.sync.aligned.m16n8k16.row.col.f32.f16.f16.f32 "
                        "{%0,%1,%2,%3}, {%4,%5,%6,%7}, {%8,%9}, {%0,%1,%2,%3};"
                        : "+f"(acc[mf][nf][0]), "+f"(acc[mf][nf][1]),
                          "+f"(acc[mf][nf][2]), "+f"(acc[mf][nf][3])
                        : "r"(a[mf][0]), "r"(a[mf][1]), "r"(a[mf][2]), "r"(a[mf][3]),
                          "r"(b0), "r"(b1));
                }
        }
    };

    load_stage(0, 0);
    for (int s = 0; s < NC2; s++) {
        if (s + 1 < NC2) load_stage(s + 1, (s + 1) & 1);
        if (s + 1 < NC2) asm volatile("cp.async.wait_group 1;");
        else             asm volatile("cp.async.wait_group 0;");
        __syncthreads();
        compute(s & 1);
        __syncthreads();
    }

    // epilogue: BN + sign + bit-pack -> g_bits2 (validated pattern)
    const int tg = lane & 3, gid = lane >> 2;
    float scv[4][2], ofv[4][2];
#pragma unroll
    for (int nf = 0; nf < 4; nf++) {
        int cl = warp_n * 32 + nf * 8 + tg * 2;
        scv[nf][0] = ssc[cl];     ofv[nf][0] = sof[cl];
        scv[nf][1] = ssc[cl + 1]; ofv[nf][1] = sof[cl + 1];
    }
    const int widx = (bn >> 5) + warp_n;
#pragma unroll
    for (int mf = 0; mf < 4; mf++) {
        unsigned mA = 0, mB = 0;
#pragma unroll
        for (int nf = 0; nf < 4; nf++) {
            int p = nf * 8 + tg * 2;
            float f00 = fmaf(acc[mf][nf][0], scv[nf][0], ofv[nf][0]);
            float f01 = fmaf(acc[mf][nf][1], scv[nf][1], ofv[nf][1]);
            float f10 = fmaf(acc[mf][nf][2], scv[nf][0], ofv[nf][0]);
            float f11 = fmaf(acc[mf][nf][3], scv[nf][1], ofv[nf][1]);
            mA |= ((f00 >= 0.f ? 1u : 0u) << p) | ((f01 >= 0.f ? 1u : 0u) << (p + 1));
            mB |= ((f10 >= 0.f ? 1u : 0u) << p) | ((f11 >= 0.f ? 1u : 0u) << (p + 1));
        }
        mA |= __shfl_xor_sync(0xffffffffu, mA, 1); mA |= __shfl_xor_sync(0xffffffffu, mA, 2);
        mB |= __shfl_xor_sync(0xffffffffu, mB, 1); mB |= __shfl_xor_sync(0xffffffffu, mB, 2);
        if (tg == 0) {
            int row = bm + warp_m * 64 + mf * 16 + gid;
            g_bits2[row * HW + widx]       = mA;
            g_bits2[(row + 8) * HW + widx] = mB;
        }
    }
}

// ---------------- fc3+fc4 fused (unchanged R10) ----------------
#define FC3_SMEM (HW * H * 4 + 2 * H * 4 + C * H * 4 + 64)   // 110656

__global__ __launch_bounds__(256, 2)
void fc3_fused(const float* __restrict__ W4, const float* __restrict__ b4,
               float* __restrict__ out) {
    extern __shared__ char smem[];
    unsigned* ws = (unsigned*)smem;
    float* ssc = (float*)(smem + HW * H * 4);
    float* sof = ssc + H;
    float* sW4 = sof + H;
    float* sb4 = sW4 + C * H;
    const int tid = threadIdx.x, lane = tid & 31, wid = tid >> 5;
    for (int i = tid; i < HW * H; i += 256) ws[i] = g_w3bits[i];
    for (int i = tid; i < H; i += 256) { ssc[i] = g_sc3[i]; sof[i] = g_of3[i]; }
    for (int i = tid; i < C * H; i += 256) sW4[i] = W4[i];
    if (tid < C) sb4[tid] = b4[tid];
    __syncthreads();
    const int row0 = blockIdx.x * 64 + wid * 8;
#pragma unroll 1
    for (int g = 0; g < 4; g++) {
        const int rb = row0 + g * 2;
        unsigned a[2][24];
#pragma unroll
        for (int r = 0; r < 2; r++) {
            const uint4* ap = (const uint4*)&g_bits2[(rb + r) * HW];
#pragma unroll
            for (int t = 0; t < 6; t++) {
                uint4 v = ap[t];
                a[r][t * 4 + 0] = v.x; a[r][t * 4 + 1] = v.y;
                a[r][t * 4 + 2] = v.z; a[r][t * 4 + 3] = v.w;
            }
        }
        float acc0[C], acc1[C];
#pragma unroll
        for (int c = 0; c < C; c++) { acc0[c] = 0.f; acc1[c] = 0.f; }
#pragma unroll 1
        for (int jw = 0; jw < HW; jw++) {
            const int j = jw * 32 + lane;
            int c0 = 0, c1 = 0;
#pragma unroll
            for (int k = 0; k < HW; k++) {
                unsigned wk = ws[k * H + j];
                c0 += __popc(a[0][k] ^ wk);
                c1 += __popc(a[1][k] ^ wk);
            }
            const float sc = ssc[j], of = sof[j];
            float h0 = fminf(fmaxf(fmaf((float)(H - 2 * c0), sc, of), -1.f), 1.f);
            float h1 = fminf(fmaxf(fmaf((float)(H - 2 * c1), sc, of), -1.f), 1.f);
#pragma unroll
            for (int c = 0; c < C; c++) {
                float w4 = sW4[c * H + j];
                acc0[c] = fmaf(h0, w4, acc0[c]);
                acc1[c] = fmaf(h1, w4, acc1[c]);
            }
        }
#pragma unroll
        for (int r = 0; r < 2; r++) {
            float lg[C], mx = -3.402823466e+38f;
#pragma unroll
            for (int c = 0; c < C; c++) {
                float v = (r == 0) ? acc0[c] : acc1[c];
#pragma unroll
                for (int off = 16; off > 0; off >>= 1)
                    v += __shfl_xor_sync(0xffffffffu, v, off);
                lg[c] = v + sb4[c];
                mx = fmaxf(mx, lg[c]);
            }
            float s = 0.f;
#pragma unroll
            for (int c = 0; c < C; c++) s += expf(lg[c] - mx);
            float lse = logf(s);
            float myv = 0.f;
#pragma unroll
            for (int c = 0; c < C; c++) if (lane == c) myv = lg[c];
            if (lane < C) out[(rb + r) * C + lane] = myv - mx - lse;
        }
    }
}

// ---------------- launch (fc2_gemm is launch #4 -> profiled) ----------------
extern "C" void kernel_launch(void* const* d_in, const int* in_sizes, int n_in,
                              void* d_out, int out_size) {
    const float* x   = (const float*)d_in[0];
    const float* W1  = (const float*)d_in[1];
    const float* b1  = (const float*)d_in[2];
    const float* W2  = (const float*)d_in[3];
    const float* b2  = (const float*)d_in[4];
    const float* W3  = (const float*)d_in[5];
    const float* b3  = (const float*)d_in[6];
    const float* W4  = (const float*)d_in[7];
    const float* b4  = (const float*)d_in[8];
    const float* g1  = (const float*)d_in[9];
    const float* be1 = (const float*)d_in[10];
    const float* m1  = (const float*)d_in[11];
    const float* v1  = (const float*)d_in[12];
    const float* g2  = (const float*)d_in[13];
    const float* be2 = (const float*)d_in[14];
    const float* m2  = (const float*)d_in[15];
    const float* v2  = (const float*)d_in[16];
    const float* g3  = (const float*)d_in[17];
    const float* be3 = (const float*)d_in[18];
    const float* m3  = (const float*)d_in[19];
    const float* v3  = (const float*)d_in[20];
    float* out = (float*)d_out;

    cudaFuncSetAttribute(fc1_gemm,  cudaFuncAttributeMaxDynamicSharedMemorySize, GEMM_SMEM);
    cudaFuncSetAttribute(fc2_gemm,  cudaFuncAttributeMaxDynamicSharedMemorySize, GEMM_SMEM);
    cudaFuncSetAttribute(fc3_fused, cudaFuncAttributeMaxDynamicSharedMemorySize, FC3_SMEM);

    int miscThreads = H + HW * H;
    prep_misc<<<(miscThreads + 255) / 256, 256>>>(W3,
        b1, g1, m1, be1, v1, b2, g2, m2, be2, v2, b3, g3, m3, be3, v3);

    int splitThreads = B * 204 + H * 204 + H * 192;
    prep_split<<<(splitThreads + 255) / 256, 256>>>(x, W1, W2);

    fc1_gemm<<<dim3(H / TN, B / TM), 256, GEMM_SMEM>>>();

    fc2_gemm<<<dim3(H / TN, B / TM), 256, GEMM_SMEM>>>();     // launch #4 (profiled)

    fc3_fused<<<B / 64, 256, FC3_SMEM>>>(W4, b4, out);
}

// round 12
// speedup vs baseline: 2.0517x; 1.0200x over previous
#include <cuda_runtime.h>
#include <cuda_fp16.h>
#include <cstdint>

#define B   16384
#define D   784
#define H   768
#define C   10
#define HW  24            // H/32
#define K2  1600          // 2*784 + 32 pad (fp16 2-term split)
#define NCH 25            // fc1 K chunks (128B)
#define NC2 12            // fc2 K chunks: 768*2B / 128B
#define TM  128
#define TN  128

// ---------------- device scratch ----------------
__device__ __align__(128) __half g_A[(size_t)B * K2];    // hi|lo split activations
__device__ __align__(128) __half g_Wb[(size_t)H * K2];   // sign(W1) fp16 x2 (pad 0)
__device__ __align__(128) __half g_a2h[(size_t)B * H];   // fc2 input, fp16 +-1
__device__ __align__(128) __half g_w2h[H * H];           // sign(W2) fp16
__device__ unsigned g_bits2[B * HW];
__device__ unsigned g_w3bits[HW * H];
__device__ float g_sc1[H], g_of1[H], g_sc2[H], g_of2[H], g_sc3[H], g_of3[H];

#define SWZ(o) ((o) ^ (((o) >> 3) & 0x70))

__device__ __forceinline__ uint32_t smem_u32(const void* p) {
    uint32_t a;
    asm("{ .reg .u64 t; cvta.to.shared.u64 t, %1; cvt.u32.u64 %0, t; }" : "=r"(a) : "l"(p));
    return a;
}

// ---------------- prep #1: folded BN scales + bit-pack W3 ----------------
__global__ void prep_misc(const float* __restrict__ W3,
                          const float* b1, const float* g1, const float* m1, const float* be1, const float* v1,
                          const float* b2, const float* g2, const float* m2, const float* be2, const float* v2,
                          const float* b3, const float* g3, const float* m3, const float* be3, const float* v3) {
    int t = blockIdx.x * blockDim.x + threadIdx.x;
    if (t < H) {
        int j = t;
        float s1 = g1[j] * (float)(1.0 / sqrt((double)(v1[j] + 1e-5f)));
        float s2 = g2[j] * (float)(1.0 / sqrt((double)(v2[j] + 1e-5f)));
        float s3 = g3[j] * (float)(1.0 / sqrt((double)(v3[j] + 1e-5f)));
        g_sc1[j] = s1; g_of1[j] = (b1[j] - m1[j]) * s1 + be1[j];
        g_sc2[j] = s2; g_of2[j] = (b2[j] - m2[j]) * s2 + be2[j];
        g_sc3[j] = s3; g_of3[j] = (b3[j] - m3[j]) * s3 + be3[j];
        return;
    }
    int q = t - H;
    if (q >= HW * H) return;
    int kw = q / H, j = q % H;
    const float* p = &W3[j * H + kw * 32];
    unsigned word = 0;
#pragma unroll
    for (int i = 0; i < 32; i++) word |= (p[i] >= 0.f ? 1u : 0u) << i;
    g_w3bits[kw * H + j] = word;
}

// ---------------- prep #2: fp16 split of x, sign(W1), sign(W2) --------------
__global__ void prep_split(const float* __restrict__ X, const float* __restrict__ W1,
                           const float* __restrict__ W2) {
    int idx = blockIdx.x * blockDim.x + threadIdx.x;
    if (idx < B * 204) {
        int b = idx / 204, q = idx - b * 204;
        __half* row = &g_A[(size_t)b * K2];
        if (q >= 196) {
            uint2 z = {0, 0};
            *(uint2*)&row[1568 + (q - 196) * 4] = z;
            return;
        }
        int kg = q * 4;
        float4 xv = *(const float4*)&X[b * D + kg];
        float xs[4] = {xv.x, xv.y, xv.z, xv.w};
        __align__(8) __half hi[4], lo[4];
#pragma unroll
        for (int i = 0; i < 4; i++) {
            float x = xs[i];
            __half h = __float2half_rn(x);
            hi[i] = h;
            lo[i] = __float2half_rn(x - __half2float(h));
        }
        *(uint2*)&row[kg]       = *(uint2*)hi;
        *(uint2*)&row[784 + kg] = *(uint2*)lo;
        return;
    }
    int idx2 = idx - B * 204;
    if (idx2 < H * 204) {
        int j = idx2 / 204, q = idx2 - j * 204;
        __half* row = &g_Wb[(size_t)j * K2];
        if (q >= 196) {
            uint2 z = {0, 0};
            *(uint2*)&row[1568 + (q - 196) * 4] = z;
            return;
        }
        int kg = q * 4;
        float4 wv = *(const float4*)&W1[j * D + kg];
        __align__(8) __half o[4];
        o[0] = __float2half(wv.x >= 0.f ? 1.f : -1.f);
        o[1] = __float2half(wv.y >= 0.f ? 1.f : -1.f);
        o[2] = __float2half(wv.z >= 0.f ? 1.f : -1.f);
        o[3] = __float2half(wv.w >= 0.f ? 1.f : -1.f);
        *(uint2*)&row[kg]       = *(uint2*)o;
        *(uint2*)&row[784 + kg] = *(uint2*)o;
        return;
    }
    int idx3 = idx2 - H * 204;
    if (idx3 >= H * 192) return;   // sign(W2): 768*768/4 quads
    int kg = idx3 * 4;
    float4 wv = *(const float4*)&W2[kg];
    __align__(8) __half o[4];
    o[0] = __float2half(wv.x >= 0.f ? 1.f : -1.f);
    o[1] = __float2half(wv.y >= 0.f ? 1.f : -1.f);
    o[2] = __float2half(wv.z >= 0.f ? 1.f : -1.f);
    o[3] = __float2half(wv.w >= 0.f ? 1.f : -1.f);
    *(uint2*)&g_w2h[kg] = *(uint2*)o;
}

// ================= shared GEMM machinery (fc1 / fc2) =========================
// 4 warps, warp tile 64x64, CTA tile 128x128, 2-stage cp.async
#define GEMM_SMEM 66560
#define A_OFF(b) (1024u + (b) * 16384u)
#define B_OFF(b) (33792u + (b) * 16384u)

#define GEMM_PROLOG(GSC, GOF, ABASE, BBASE, LDBYTES)                                    \
    extern __shared__ char smem[];                                                     \
    const uint32_t sb = smem_u32(smem);                                                \
    const int tid = threadIdx.x;                                                       \
    const int wid = tid >> 5, lane = tid & 31;                                         \
    const int warp_m = wid >> 1, warp_n = wid & 1;                                     \
    const int bn = blockIdx.x * TN, bm = blockIdx.y * TM;                              \
    float* ssc = (float*)(smem);                                                       \
    float* sof = (float*)(smem + 512);                                                 \
    if (tid < 128) { ssc[tid] = GSC[bn + tid]; sof[tid] = GOF[bn + tid]; }             \
    const char* Abase = (const char*)(ABASE) + (size_t)bm * (LDBYTES);                 \
    const char* Bbase = (const char*)(BBASE) + (size_t)bn * (LDBYTES);                 \
    float acc[4][8][4];                                                                \
    _Pragma("unroll") for (int i = 0; i < 4; i++)                                      \
    _Pragma("unroll") for (int j = 0; j < 8; j++)                                      \
    _Pragma("unroll") for (int c = 0; c < 4; c++) acc[i][j][c] = 0.f;                  \
    auto load_stage = [&](int s, int buf) {                                            \
        size_t kb = (size_t)s * 128;                                                   \
        uint32_t adst = sb + A_OFF(buf), bdst = sb + B_OFF(buf);                       \
        _Pragma("unroll") for (int i = 0; i < 8; i++) {                                \
            int idx = i * 128 + tid;                                                   \
            int row = idx >> 3, c = idx & 7;                                           \
            uint32_t off = SWZ((uint32_t)(row * 128 + c * 16));                        \
            const char* srcA = Abase + (size_t)row * (LDBYTES) + kb + c * 16;          \
            const char* srcB = Bbase + (size_t)row * (LDBYTES) + kb + c * 16;          \
            asm volatile("cp.async.cg.shared.global [%0], [%1], 16;" :: "r"(adst + off), "l"(srcA)); \
            asm volatile("cp.async.cg.shared.global [%0], [%1], 16;" :: "r"(bdst + off), "l"(srcB)); \
        }                                                                              \
        asm volatile("cp.async.commit_group;");                                       \
    };                                                                                 \
    auto compute = [&](int buf) {                                                      \
        uint32_t ab = sb + A_OFF(buf), bb = sb + B_OFF(buf);                           \
        _Pragma("unroll") for (int ks = 0; ks < 4; ks++) {                             \
            uint32_t a[4][4], bf[4][4];                                                \
            const int kk = ks * 16 + (lane >> 4) * 8;                                  \
            const int mrow = warp_m * 64 + (lane & 15);                                \
            _Pragma("unroll") for (int mf = 0; mf < 4; mf++) {                         \
                uint32_t addr = ab + SWZ((uint32_t)((mrow + mf * 16) * 128 + kk * 2)); \
                asm volatile("ldmatrix.sync.aligned.m8n8.x4.shared.b16 {%0,%1,%2,%3}, [%4];" \
                    : "=r"(a[mf][0]), "=r"(a[mf][1]), "=r"(a[mf][2]), "=r"(a[mf][3]) : "r"(addr)); \
            }                                                                          \
            const int nrow = warp_n * 64 + (lane & 15);                                \
            _Pragma("unroll") for (int p = 0; p < 4; p++) {                            \
                uint32_t addr = bb + SWZ((uint32_t)((nrow + p * 16) * 128 + kk * 2));  \
                asm volatile("ldmatrix.sync.aligned.m8n8.x4.shared.b16 {%0,%1,%2,%3}, [%4];" \
                    : "=r"(bf[p][0]), "=r"(bf[p][1]), "=r"(bf[p][2]), "=r"(bf[p][3]) : "r"(addr)); \
            }                                                                          \
            _Pragma("unroll") for (int mf = 0; mf < 4; mf++)                           \
            _Pragma("unroll") for (int nf = 0; nf < 8; nf++) {                         \
                uint32_t b0 = bf[nf >> 1][nf & 1], b1 = bf[nf >> 1][(nf & 1) + 2];     \
                asm volatile(                                                          \
                    "mma.sync.aligned.m16n8k16.row.col.f32.f16.f16.f32 "               \
                    "{%0,%1,%2,%3}, {%4,%5,%6,%7}, {%8,%9}, {%0,%1,%2,%3};"            \
                    : "+f"(acc[mf][nf][0]), "+f"(acc[mf][nf][1]),                      \
                      "+f"(acc[mf][nf][2]), "+f"(acc[mf][nf][3])                       \
                    : "r"(a[mf][0]), "r"(a[mf][1]), "r"(a[mf][2]), "r"(a[mf][3]),      \
                      "r"(b0), "r"(b1));                                               \
            }                                                                          \
        }                                                                              \
    };

#define GEMM_MAINLOOP(NCHUNK)                                                          \
    load_stage(0, 0);                                                                  \
    for (int s = 0; s < (NCHUNK); s++) {                                               \
        if (s + 1 < (NCHUNK)) load_stage(s + 1, (s + 1) & 1);                          \
        if (s + 1 < (NCHUNK)) asm volatile("cp.async.wait_group 1;");                  \
        else                  asm volatile("cp.async.wait_group 0;");                  \
        __syncthreads();                                                               \
        compute(s & 1);                                                                \
        __syncthreads();                                                               \
    }

// ---------------- fc1: epilogue -> fp16 +-1 (g_a2h) ----------
__global__ __launch_bounds__(128, 2)
void fc1_gemm() {
    GEMM_PROLOG(g_sc1, g_of1, g_A, g_Wb, (K2 * 2))
    GEMM_MAINLOOP(NCH)

    const int tg = lane & 3, gid = lane >> 2;
    const __half hp1 = __float2half(1.f), hm1 = __float2half(-1.f);
#pragma unroll
    for (int mf = 0; mf < 4; mf++) {
        int row = bm + warp_m * 64 + mf * 16 + gid;
#pragma unroll
        for (int nf = 0; nf < 8; nf++) {
            int cl = warp_n * 64 + nf * 8 + tg * 2;
            int col = bn + cl;
            float f00 = fmaf(acc[mf][nf][0], ssc[cl],     sof[cl]);
            float f01 = fmaf(acc[mf][nf][1], ssc[cl + 1], sof[cl + 1]);
            float f10 = fmaf(acc[mf][nf][2], ssc[cl],     sof[cl]);
            float f11 = fmaf(acc[mf][nf][3], ssc[cl + 1], sof[cl + 1]);
            __half2 hA = __halves2half2(f00 >= 0.f ? hp1 : hm1, f01 >= 0.f ? hp1 : hm1);
            __half2 hB = __halves2half2(f10 >= 0.f ? hp1 : hm1, f11 >= 0.f ? hp1 : hm1);
            *(__half2*)&g_a2h[(size_t)row * H + col]       = hA;
            *(__half2*)&g_a2h[(size_t)(row + 8) * H + col] = hB;
        }
    }
}

// ---------------- fc2: epilogue -> bit-pack (g_bits2) ----------
__global__ __launch_bounds__(128, 2)
void fc2_gemm() {
    GEMM_PROLOG(g_sc2, g_of2, g_a2h, g_w2h, (H * 2))
    GEMM_MAINLOOP(NC2)

    const int tg = lane & 3, gid = lane >> 2;
    const int widx0 = (bn >> 5) + warp_n * 2;
#pragma unroll
    for (int mf = 0; mf < 4; mf++) {
        unsigned mA[2] = {0, 0}, mB[2] = {0, 0};
#pragma unroll
        for (int nf = 0; nf < 8; nf++) {
            int cl = warp_n * 64 + nf * 8 + tg * 2;
            int w = nf >> 2;
            int p = (nf & 3) * 8 + tg * 2;
            float f00 = fmaf(acc[mf][nf][0], ssc[cl],     sof[cl]);
            float f01 = fmaf(acc[mf][nf][1], ssc[cl + 1], sof[cl + 1]);
            float f10 = fmaf(acc[mf][nf][2], ssc[cl],     sof[cl]);
            float f11 = fmaf(acc[mf][nf][3], ssc[cl + 1], sof[cl + 1]);
            mA[w] |= ((f00 >= 0.f ? 1u : 0u) << p) | ((f01 >= 0.f ? 1u : 0u) << (p + 1));
            mB[w] |= ((f10 >= 0.f ? 1u : 0u) << p) | ((f11 >= 0.f ? 1u : 0u) << (p + 1));
        }
#pragma unroll
        for (int w = 0; w < 2; w++) {
            mA[w] |= __shfl_xor_sync(0xffffffffu, mA[w], 1); mA[w] |= __shfl_xor_sync(0xffffffffu, mA[w], 2);
            mB[w] |= __shfl_xor_sync(0xffffffffu, mB[w], 1); mB[w] |= __shfl_xor_sync(0xffffffffu, mB[w], 2);
        }
        if (tg == 0) {
            int row = bm + warp_m * 64 + mf * 16 + gid;
#pragma unroll
            for (int w = 0; w < 2; w++) {
                g_bits2[row * HW + widx0 + w]       = mA[w];
                g_bits2[(row + 8) * HW + widx0 + w] = mB[w];
            }
        }
    }
}

// ---------------- fc3+fc4 fused (unchanged R10/R11) ----------------
#define FC3_SMEM (HW * H * 4 + 2 * H * 4 + C * H * 4 + 64)   // 110656

__global__ __launch_bounds__(256, 2)
void fc3_fused(const float* __restrict__ W4, const float* __restrict__ b4,
               float* __restrict__ out) {
    extern __shared__ char smem[];
    unsigned* ws = (unsigned*)smem;
    float* ssc = (float*)(smem + HW * H * 4);
    float* sof = ssc + H;
    float* sW4 = sof + H;
    float* sb4 = sW4 + C * H;
    const int tid = threadIdx.x, lane = tid & 31, wid = tid >> 5;
    for (int i = tid; i < HW * H; i += 256) ws[i] = g_w3bits[i];
    for (int i = tid; i < H; i += 256) { ssc[i] = g_sc3[i]; sof[i] = g_of3[i]; }
    for (int i = tid; i < C * H; i += 256) sW4[i] = W4[i];
    if (tid < C) sb4[tid] = b4[tid];
    __syncthreads();
    const int row0 = blockIdx.x * 64 + wid * 8;
#pragma unroll 1
    for (int g = 0; g < 4; g++) {
        const int rb = row0 + g * 2;
        unsigned a[2][24];
#pragma unroll
        for (int r = 0; r < 2; r++) {
            const uint4* ap = (const uint4*)&g_bits2[(rb + r) * HW];
#pragma unroll
            for (int t = 0; t < 6; t++) {
                uint4 v = ap[t];
                a[r][t * 4 + 0] = v.x; a[r][t * 4 + 1] = v.y;
                a[r][t * 4 + 2] = v.z; a[r][t * 4 + 3] = v.w;
            }
        }
        float acc0[C], acc1[C];
#pragma unroll
        for (int c = 0; c < C; c++) { acc0[c] = 0.f; acc1[c] = 0.f; }
#pragma unroll 1
        for (int jw = 0; jw < HW; jw++) {
            const int j = jw * 32 + lane;
            int c0 = 0, c1 = 0;
#pragma unroll
            for (int k = 0; k < HW; k++) {
                unsigned wk = ws[k * H + j];
                c0 += __popc(a[0][k] ^ wk);
                c1 += __popc(a[1][k] ^ wk);
            }
            const float sc = ssc[j], of = sof[j];
            float h0 = fminf(fmaxf(fmaf((float)(H - 2 * c0), sc, of), -1.f), 1.f);
            float h1 = fminf(fmaxf(fmaf((float)(H - 2 * c1), sc, of), -1.f), 1.f);
#pragma unroll
            for (int c = 0; c < C; c++) {
                float w4 = sW4[c * H + j];
                acc0[c] = fmaf(h0, w4, acc0[c]);
                acc1[c] = fmaf(h1, w4, acc1[c]);
            }
        }
#pragma unroll
        for (int r = 0; r < 2; r++) {
            float lg[C], mx = -3.402823466e+38f;
#pragma unroll
            for (int c = 0; c < C; c++) {
                float v = (r == 0) ? acc0[c] : acc1[c];
#pragma unroll
                for (int off = 16; off > 0; off >>= 1)
                    v += __shfl_xor_sync(0xffffffffu, v, off);
                lg[c] = v + sb4[c];
                mx = fmaxf(mx, lg[c]);
            }
            float s = 0.f;
#pragma unroll
            for (int c = 0; c < C; c++) s += expf(lg[c] - mx);
            float lse = logf(s);
            float myv = 0.f;
#pragma unroll
            for (int c = 0; c < C; c++) if (lane == c) myv = lg[c];
            if (lane < C) out[(rb + r) * C + lane] = myv - mx - lse;
        }
    }
}

// ---------------- launch (fc2_gemm is launch #4 -> profiled) ----------------
extern "C" void kernel_launch(void* const* d_in, const int* in_sizes, int n_in,
                              void* d_out, int out_size) {
    const float* x   = (const float*)d_in[0];
    const float* W1  = (const float*)d_in[1];
    const float* b1  = (const float*)d_in[2];
    const float* W2  = (const float*)d_in[3];
    const float* b2  = (const float*)d_in[4];
    const float* W3  = (const float*)d_in[5];
    const float* b3  = (const float*)d_in[6];
    const float* W4  = (const float*)d_in[7];
    const float* b4  = (const float*)d_in[8];
    const float* g1  = (const float*)d_in[9];
    const float* be1 = (const float*)d_in[10];
    const float* m1  = (const float*)d_in[11];
    const float* v1  = (const float*)d_in[12];
    const float* g2  = (const float*)d_in[13];
    const float* be2 = (const float*)d_in[14];
    const float* m2  = (const float*)d_in[15];
    const float* v2  = (const float*)d_in[16];
    const float* g3  = (const float*)d_in[17];
    const float* be3 = (const float*)d_in[18];
    const float* m3  = (const float*)d_in[19];
    const float* v3  = (const float*)d_in[20];
    float* out = (float*)d_out;

    cudaFuncSetAttribute(fc1_gemm,  cudaFuncAttributeMaxDynamicSharedMemorySize, GEMM_SMEM);
    cudaFuncSetAttribute(fc2_gemm,  cudaFuncAttributeMaxDynamicSharedMemorySize, GEMM_SMEM);
    cudaFuncSetAttribute(fc3_fused, cudaFuncAttributeMaxDynamicSharedMemorySize, FC3_SMEM);

    int miscThreads = H + HW * H;
    prep_misc<<<(miscThreads + 255) / 256, 256>>>(W3,
        b1, g1, m1, be1, v1, b2, g2, m2, be2, v2, b3, g3, m3, be3, v3);

    int splitThreads = B * 204 + H * 204 + H * 192;
    prep_split<<<(splitThreads + 255) / 256, 256>>>(x, W1, W2);

    fc1_gemm<<<dim3(H / TN, B / TM), 128, GEMM_SMEM>>>();

    fc2_gemm<<<dim3(H / TN, B / TM), 128, GEMM_SMEM>>>();     // launch #4 (profiled)

    fc3_fused<<<B / 64, 256, FC3_SMEM>>>(W4, b4, out);
}

// round 14
// speedup vs baseline: 2.0782x; 1.0129x over previous
#include <cuda_runtime.h>
#include <cuda_fp16.h>
#include <cstdint>

#define B   16384
#define D   784
#define H   768
#define C   10
#define HW  24            // H/32
#define K2  1600          // 2*784 + 32 pad (fp16 2-term split)
#define NCH 25            // fc1 K chunks (128B)
#define NC2 12            // fc2 K chunks: 768*2B / 128B
#define TM  128
#define TN  128

// ---------------- device scratch ----------------
__device__ __align__(128) __half g_A[(size_t)B * K2];    // hi|lo split activations
__device__ __align__(128) __half g_Wb[(size_t)H * K2];   // sign(W1) fp16 x2 (pad 0)
__device__ __align__(128) __half g_a2h[(size_t)B * H];   // fc2 input, fp16 +-1
__device__ __align__(128) __half g_w2h[H * H];           // sign(W2) fp16
__device__ unsigned g_bits2[B * HW];
__device__ unsigned g_w3bits[HW * H];
__device__ float g_sc1[H], g_of1[H], g_sc2[H], g_of2[H], g_sc3[H], g_of3[H];

#define SWZ(o) ((o) ^ (((o) >> 3) & 0x70))

__device__ __forceinline__ uint32_t smem_u32(const void* p) {
    uint32_t a;
    asm("{ .reg .u64 t; cvta.to.shared.u64 t, %1; cvt.u32.u64 %0, t; }" : "=r"(a) : "l"(p));
    return a;
}

// ---------------- prep #1: folded BN scales + bit-pack W3 ----------------
__global__ void prep_misc(const float* __restrict__ W3,
                          const float* b1, const float* g1, const float* m1, const float* be1, const float* v1,
                          const float* b2, const float* g2, const float* m2, const float* be2, const float* v2,
                          const float* b3, const float* g3, const float* m3, const float* be3, const float* v3) {
    int t = blockIdx.x * blockDim.x + threadIdx.x;
    if (t < H) {
        int j = t;
        float s1 = g1[j] * (float)(1.0 / sqrt((double)(v1[j] + 1e-5f)));
        float s2 = g2[j] * (float)(1.0 / sqrt((double)(v2[j] + 1e-5f)));
        float s3 = g3[j] * (float)(1.0 / sqrt((double)(v3[j] + 1e-5f)));
        g_sc1[j] = s1; g_of1[j] = (b1[j] - m1[j]) * s1 + be1[j];
        g_sc2[j] = s2; g_of2[j] = (b2[j] - m2[j]) * s2 + be2[j];
        g_sc3[j] = s3; g_of3[j] = (b3[j] - m3[j]) * s3 + be3[j];
        return;
    }
    int q = t - H;
    if (q >= HW * H) return;
    int kw = q / H, j = q % H;
    const float* p = &W3[j * H + kw * 32];
    unsigned word = 0;
#pragma unroll
    for (int i = 0; i < 32; i++) word |= (p[i] >= 0.f ? 1u : 0u) << i;
    g_w3bits[kw * H + j] = word;
}

// ---------------- prep #2: fp16 split of x, sign(W1), sign(W2) --------------
__global__ void prep_split(const float* __restrict__ X, const float* __restrict__ W1,
                           const float* __restrict__ W2) {
    int idx = blockIdx.x * blockDim.x + threadIdx.x;
    if (idx < B * 204) {
        int b = idx / 204, q = idx - b * 204;
        __half* row = &g_A[(size_t)b * K2];
        if (q >= 196) {
            uint2 z = {0, 0};
            *(uint2*)&row[1568 + (q - 196) * 4] = z;
            return;
        }
        int kg = q * 4;
        float4 xv = *(const float4*)&X[b * D + kg];
        float xs[4] = {xv.x, xv.y, xv.z, xv.w};
        __align__(8) __half hi[4], lo[4];
#pragma unroll
        for (int i = 0; i < 4; i++) {
            float x = xs[i];
            __half h = __float2half_rn(x);
            hi[i] = h;
            lo[i] = __float2half_rn(x - __half2float(h));
        }
        *(uint2*)&row[kg]       = *(uint2*)hi;
        *(uint2*)&row[784 + kg] = *(uint2*)lo;
        return;
    }
    int idx2 = idx - B * 204;
    if (idx2 < H * 204) {
        int j = idx2 / 204, q = idx2 - j * 204;
        __half* row = &g_Wb[(size_t)j * K2];
        if (q >= 196) {
            uint2 z = {0, 0};
            *(uint2*)&row[1568 + (q - 196) * 4] = z;
            return;
        }
        int kg = q * 4;
        float4 wv = *(const float4*)&W1[j * D + kg];
        __align__(8) __half o[4];
        o[0] = __float2half(wv.x >= 0.f ? 1.f : -1.f);
        o[1] = __float2half(wv.y >= 0.f ? 1.f : -1.f);
        o[2] = __float2half(wv.z >= 0.f ? 1.f : -1.f);
        o[3] = __float2half(wv.w >= 0.f ? 1.f : -1.f);
        *(uint2*)&row[kg]       = *(uint2*)o;
        *(uint2*)&row[784 + kg] = *(uint2*)o;
        return;
    }
    int idx3 = idx2 - H * 204;
    if (idx3 >= H * 192) return;   // sign(W2): 768*768/4 quads
    int kg = idx3 * 4;
    float4 wv = *(const float4*)&W2[kg];
    __align__(8) __half o[4];
    o[0] = __float2half(wv.x >= 0.f ? 1.f : -1.f);
    o[1] = __float2half(wv.y >= 0.f ? 1.f : -1.f);
    o[2] = __float2half(wv.z >= 0.f ? 1.f : -1.f);
    o[3] = __float2half(wv.w >= 0.f ? 1.f : -1.f);
    *(uint2*)&g_w2h[kg] = *(uint2*)o;
}

// ================= GEMM tiles: 4 warps, warp tile 64x64, CTA 128x128 =========
#define GEMM_SMEM 66560
#define A_OFF(b) (1024u + (b) * 16384u)
#define B_OFF(b) (33792u + (b) * 16384u)

// ---------------- fc1: fp32-acc fp16 GEMM (R12, unchanged) ------------------
__global__ __launch_bounds__(128, 2)
void fc1_gemm() {
    extern __shared__ char smem[];
    const uint32_t sb = smem_u32(smem);
    const int tid = threadIdx.x;
    const int wid = tid >> 5, lane = tid & 31;
    const int warp_m = wid >> 1, warp_n = wid & 1;
    const int bn = blockIdx.x * TN, bm = blockIdx.y * TM;

    float* ssc = (float*)(smem);
    float* sof = (float*)(smem + 512);
    ssc[tid] = g_sc1[bn + tid]; sof[tid] = g_of1[bn + tid];

    const char* Abase = (const char*)g_A  + (size_t)bm * (K2 * 2);
    const char* Bbase = (const char*)g_Wb + (size_t)bn * (K2 * 2);

    float acc[4][8][4];
#pragma unroll
    for (int i = 0; i < 4; i++)
#pragma unroll
        for (int j = 0; j < 8; j++)
#pragma unroll
            for (int c = 0; c < 4; c++) acc[i][j][c] = 0.f;

    auto load_stage = [&](int s, int buf) {
        size_t kb = (size_t)s * 128;
        uint32_t adst = sb + A_OFF(buf), bdst = sb + B_OFF(buf);
#pragma unroll
        for (int i = 0; i < 8; i++) {
            int idx = i * 128 + tid;
            int row = idx >> 3, c = idx & 7;
            uint32_t off = SWZ((uint32_t)(row * 128 + c * 16));
            const char* srcA = Abase + (size_t)row * (K2 * 2) + kb + c * 16;
            const char* srcB = Bbase + (size_t)row * (K2 * 2) + kb + c * 16;
            asm volatile("cp.async.cg.shared.global [%0], [%1], 16;" :: "r"(adst + off), "l"(srcA));
            asm volatile("cp.async.cg.shared.global [%0], [%1], 16;" :: "r"(bdst + off), "l"(srcB));
        }
        asm volatile("cp.async.commit_group;");
    };

    auto compute = [&](int buf) {
        uint32_t ab = sb + A_OFF(buf), bb = sb + B_OFF(buf);
#pragma unroll
        for (int ks = 0; ks < 4; ks++) {
            uint32_t a[4][4], bf[4][4];
            const int kk = ks * 16 + (lane >> 4) * 8;
            const int mrow = warp_m * 64 + (lane & 15);
            const int nrow = warp_n * 64 + (lane & 15);
#pragma unroll
            for (int mf = 0; mf < 4; mf++) {
                uint32_t addr = ab + SWZ((uint32_t)((mrow + mf * 16) * 128 + kk * 2));
                asm volatile("ldmatrix.sync.aligned.m8n8.x4.shared.b16 {%0,%1,%2,%3}, [%4];"
                    : "=r"(a[mf][0]), "=r"(a[mf][1]), "=r"(a[mf][2]), "=r"(a[mf][3]) : "r"(addr));
            }
#pragma unroll
            for (int p = 0; p < 4; p++) {
                uint32_t addr = bb + SWZ((uint32_t)((nrow + p * 16) * 128 + kk * 2));
                asm volatile("ldmatrix.sync.aligned.m8n8.x4.shared.b16 {%0,%1,%2,%3}, [%4];"
                    : "=r"(bf[p][0]), "=r"(bf[p][1]), "=r"(bf[p][2]), "=r"(bf[p][3]) : "r"(addr));
            }
#pragma unroll
            for (int mf = 0; mf < 4; mf++)
#pragma unroll
                for (int nf = 0; nf < 8; nf++) {
                    uint32_t b0 = bf[nf >> 1][nf & 1], b1 = bf[nf >> 1][(nf & 1) + 2];
                    asm volatile(
                        "mma.sync.aligned.m16n8k16.row.col.f32.f16.f16.f32 "
                        "{%0,%1,%2,%3}, {%4,%5,%6,%7}, {%8,%9}, {%0,%1,%2,%3};"
                        : "+f"(acc[mf][nf][0]), "+f"(acc[mf][nf][1]),
                          "+f"(acc[mf][nf][2]), "+f"(acc[mf][nf][3])
                        : "r"(a[mf][0]), "r"(a[mf][1]), "r"(a[mf][2]), "r"(a[mf][3]),
                          "r"(b0), "r"(b1));
                }
        }
    };

    load_stage(0, 0);
    for (int s = 0; s < NCH; s++) {
        if (s + 1 < NCH) load_stage(s + 1, (s + 1) & 1);
        if (s + 1 < NCH) asm volatile("cp.async.wait_group 1;");
        else             asm volatile("cp.async.wait_group 0;");
        __syncthreads();
        compute(s & 1);
        __syncthreads();
    }

    // epilogue: BN + sign -> fp16 +-1 into g_a2h
    const int tg = lane & 3, gid = lane >> 2;
    const __half hp1 = __float2half(1.f), hm1 = __float2half(-1.f);
#pragma unroll
    for (int mf = 0; mf < 4; mf++) {
        int row = bm + warp_m * 64 + mf * 16 + gid;
#pragma unroll
        for (int nf = 0; nf < 8; nf++) {
            int cl = warp_n * 64 + nf * 8 + tg * 2;
            int col = bn + cl;
            float f00 = fmaf(acc[mf][nf][0], ssc[cl],     sof[cl]);
            float f01 = fmaf(acc[mf][nf][1], ssc[cl + 1], sof[cl + 1]);
            float f10 = fmaf(acc[mf][nf][2], ssc[cl],     sof[cl]);
            float f11 = fmaf(acc[mf][nf][3], ssc[cl + 1], sof[cl + 1]);
            __half2 hA = __halves2half2(f00 >= 0.f ? hp1 : hm1, f01 >= 0.f ? hp1 : hm1);
            __half2 hB = __halves2half2(f10 >= 0.f ? hp1 : hm1, f11 >= 0.f ? hp1 : hm1);
            *(__half2*)&g_a2h[(size_t)row * H + col]       = hA;
            *(__half2*)&g_a2h[(size_t)(row + 8) * H + col] = hB;
        }
    }
}

// ---------------- fc2: fp16-accumulator GEMM (exact +-1 integers) -----------
__global__ __launch_bounds__(128, 3)
void fc2_gemm() {
    extern __shared__ char smem[];
    const uint32_t sb = smem_u32(smem);
    const int tid = threadIdx.x;
    const int wid = tid >> 5, lane = tid & 31;
    const int warp_m = wid >> 1, warp_n = wid & 1;
    const int bn = blockIdx.x * TN, bm = blockIdx.y * TM;

    float* ssc = (float*)(smem);
    float* sof = (float*)(smem + 512);
    ssc[tid] = g_sc2[bn + tid]; sof[tid] = g_of2[bn + tid];

    const char* Abase = (const char*)g_a2h + (size_t)bm * (H * 2);
    const char* Bbase = (const char*)g_w2h + (size_t)bn * (H * 2);

    uint32_t acc[4][8][2];   // f16x2 accumulators (exact: integer sums <= 768)
#pragma unroll
    for (int i = 0; i < 4; i++)
#pragma unroll
        for (int j = 0; j < 8; j++) { acc[i][j][0] = 0u; acc[i][j][1] = 0u; }

    auto load_stage = [&](int s, int buf) {
        size_t kb = (size_t)s * 128;
        uint32_t adst = sb + A_OFF(buf), bdst = sb + B_OFF(buf);
#pragma unroll
        for (int i = 0; i < 8; i++) {
            int idx = i * 128 + tid;
            int row = idx >> 3, c = idx & 7;
            uint32_t off = SWZ((uint32_t)(row * 128 + c * 16));
            const char* srcA = Abase + (size_t)row * (H * 2) + kb + c * 16;
            const char* srcB = Bbase + (size_t)row * (H * 2) + kb + c * 16;
            asm volatile("cp.async.cg.shared.global [%0], [%1], 16;" :: "r"(adst + off), "l"(srcA));
            asm volatile("cp.async.cg.shared.global [%0], [%1], 16;" :: "r"(bdst + off), "l"(srcB));
        }
        asm volatile("cp.async.commit_group;");
    };

    auto compute = [&](int buf) {
        uint32_t ab = sb + A_OFF(buf), bb = sb + B_OFF(buf);
#pragma unroll
        for (int ks = 0; ks < 4; ks++) {
            uint32_t a[4][4], bf[4][4];
            const int kk = ks * 16 + (lane >> 4) * 8;
            const int mrow = warp_m * 64 + (lane & 15);
            const int nrow = warp_n * 64 + (lane & 15);
#pragma unroll
            for (int mf = 0; mf < 4; mf++) {
                uint32_t addr = ab + SWZ((uint32_t)((mrow + mf * 16) * 128 + kk * 2));
                asm volatile("ldmatrix.sync.aligned.m8n8.x4.shared.b16 {%0,%1,%2,%3}, [%4];"
                    : "=r"(a[mf][0]), "=r"(a[mf][1]), "=r"(a[mf][2]), "=r"(a[mf][3]) : "r"(addr));
            }
#pragma unroll
            for (int p = 0; p < 4; p++) {
                uint32_t addr = bb + SWZ((uint32_t)((nrow + p * 16) * 128 + kk * 2));
                asm volatile("ldmatrix.sync.aligned.m8n8.x4.shared.b16 {%0,%1,%2,%3}, [%4];"
                    : "=r"(bf[p][0]), "=r"(bf[p][1]), "=r"(bf[p][2]), "=r"(bf[p][3]) : "r"(addr));
            }
#pragma unroll
            for (int mf = 0; mf < 4; mf++)
#pragma unroll
                for (int nf = 0; nf < 8; nf++) {
                    uint32_t b0 = bf[nf >> 1][nf & 1], b1 = bf[nf >> 1][(nf & 1) + 2];
                    asm volatile(
                        "mma.sync.aligned.m16n8k16.row.col.f16.f16.f16.f16 "
                        "{%0,%1}, {%2,%3,%4,%5}, {%6,%7}, {%0,%1};"
                        : "+r"(acc[mf][nf][0]), "+r"(acc[mf][nf][1])
                        : "r"(a[mf][0]), "r"(a[mf][1]), "r"(a[mf][2]), "r"(a[mf][3]),
                          "r"(b0), "r"(b1));
                }
        }
    };

    load_stage(0, 0);
    for (int s = 0; s < NC2; s++) {
        if (s + 1 < NC2) load_stage(s + 1, (s + 1) & 1);
        if (s + 1 < NC2) asm volatile("cp.async.wait_group 1;");
        else             asm volatile("cp.async.wait_group 0;");
        __syncthreads();
        compute(s & 1);
        __syncthreads();
    }

    // epilogue: BN + sign + bit-pack -> g_bits2
    const int tg = lane & 3, gid = lane >> 2;
    const int widx0 = (bn >> 5) + warp_n * 2;
#pragma unroll
    for (int mf = 0; mf < 4; mf++) {
        unsigned mA[2] = {0, 0}, mB[2] = {0, 0};
#pragma unroll
        for (int nf = 0; nf < 8; nf++) {
            int cl = warp_n * 64 + nf * 8 + tg * 2;
            int w = nf >> 2;
            int p = (nf & 3) * 8 + tg * 2;
            float2 fa = __half22float2(*(__half2*)&acc[mf][nf][0]);   // row gid
            float2 fb = __half22float2(*(__half2*)&acc[mf][nf][1]);   // row gid+8
            float f00 = fmaf(fa.x, ssc[cl],     sof[cl]);
            float f01 = fmaf(fa.y, ssc[cl + 1], sof[cl + 1]);
            float f10 = fmaf(fb.x, ssc[cl],     sof[cl]);
            float f11 = fmaf(fb.y, ssc[cl + 1], sof[cl + 1]);
            mA[w] |= ((f00 >= 0.f ? 1u : 0u) << p) | ((f01 >= 0.f ? 1u : 0u) << (p + 1));
            mB[w] |= ((f10 >= 0.f ? 1u : 0u) << p) | ((f11 >= 0.f ? 1u : 0u) << (p + 1));
        }
#pragma unroll
        for (int w = 0; w < 2; w++) {
            mA[w] |= __shfl_xor_sync(0xffffffffu, mA[w], 1); mA[w] |= __shfl_xor_sync(0xffffffffu, mA[w], 2);
            mB[w] |= __shfl_xor_sync(0xffffffffu, mB[w], 1); mB[w] |= __shfl_xor_sync(0xffffffffu, mB[w], 2);
        }
        if (tg == 0) {
            int row = bm + warp_m * 64 + mf * 16 + gid;
#pragma unroll
            for (int w = 0; w < 2; w++) {
                g_bits2[row * HW + widx0 + w]       = mA[w];
                g_bits2[(row + 8) * HW + widx0 + w] = mB[w];
            }
        }
    }
}

// ---------------- fc3+fc4 fused (unchanged) ----------------
#define FC3_SMEM (HW * H * 4 + 2 * H * 4 + C * H * 4 + 64)   // 110656

__global__ __launch_bounds__(256, 2)
void fc3_fused(const float* __restrict__ W4, const float* __restrict__ b4,
               float* __restrict__ out) {
    extern __shared__ char smem[];
    unsigned* ws = (unsigned*)smem;
    float* ssc = (float*)(smem + HW * H * 4);
    float* sof = ssc + H;
    float* sW4 = sof + H;
    float* sb4 = sW4 + C * H;
    const int tid = threadIdx.x, lane = tid & 31, wid = tid >> 5;
    for (int i = tid; i < HW * H; i += 256) ws[i] = g_w3bits[i];
    for (int i = tid; i < H; i += 256) { ssc[i] = g_sc3[i]; sof[i] = g_of3[i]; }
    for (int i = tid; i < C * H; i += 256) sW4[i] = W4[i];
    if (tid < C) sb4[tid] = b4[tid];
    __syncthreads();
    const int row0 = blockIdx.x * 64 + wid * 8;
#pragma unroll 1
    for (int g = 0; g < 4; g++) {
        const int rb = row0 + g * 2;
        unsigned a[2][24];
#pragma unroll
        for (int r = 0; r < 2; r++) {
            const uint4* ap = (const uint4*)&g_bits2[(rb + r) * HW];
#pragma unroll
            for (int t = 0; t < 6; t++) {
                uint4 v = ap[t];
                a[r][t * 4 + 0] = v.x; a[r][t * 4 + 1] = v.y;
                a[r][t * 4 + 2] = v.z; a[r][t * 4 + 3] = v.w;
            }
        }
        float acc0[C], acc1[C];
#pragma unroll
        for (int c = 0; c < C; c++) { acc0[c] = 0.f; acc1[c] = 0.f; }
#pragma unroll 1
        for (int jw = 0; jw < HW; jw++) {
            const int j = jw * 32 + lane;
            int c0 = 0, c1 = 0;
#pragma unroll
            for (int k = 0; k < HW; k++) {
                unsigned wk = ws[k * H + j];
                c0 += __popc(a[0][k] ^ wk);
                c1 += __popc(a[1][k] ^ wk);
            }
            const float sc = ssc[j], of = sof[j];
            float h0 = fminf(fmaxf(fmaf((float)(H - 2 * c0), sc, of), -1.f), 1.f);
            float h1 = fminf(fmaxf(fmaf((float)(H - 2 * c1), sc, of), -1.f), 1.f);
#pragma unroll
            for (int c = 0; c < C; c++) {
                float w4 = sW4[c * H + j];
                acc0[c] = fmaf(h0, w4, acc0[c]);
                acc1[c] = fmaf(h1, w4, acc1[c]);
            }
        }
#pragma unroll
        for (int r = 0; r < 2; r++) {
            float lg[C], mx = -3.402823466e+38f;
#pragma unroll
            for (int c = 0; c < C; c++) {
                float v = (r == 0) ? acc0[c] : acc1[c];
#pragma unroll
                for (int off = 16; off > 0; off >>= 1)
                    v += __shfl_xor_sync(0xffffffffu, v, off);
                lg[c] = v + sb4[c];
                mx = fmaxf(mx, lg[c]);
            }
            float s = 0.f;
#pragma unroll
            for (int c = 0; c < C; c++) s += expf(lg[c] - mx);
            float lse = logf(s);
            float myv = 0.f;
#pragma unroll
            for (int c = 0; c < C; c++) if (lane == c) myv = lg[c];
            if (lane < C) out[(rb + r) * C + lane] = myv - mx - lse;
        }
    }
}

// ---------------- launch (fc2_gemm is launch #4 -> profiled) ----------------
extern "C" void kernel_launch(void* const* d_in, const int* in_sizes, int n_in,
                              void* d_out, int out_size) {
    const float* x   = (const float*)d_in[0];
    const float* W1  = (const float*)d_in[1];
    const float* b1  = (const float*)d_in[2];
    const float* W2  = (const float*)d_in[3];
    const float* b2  = (const float*)d_in[4];
    const float* W3  = (const float*)d_in[5];
    const float* b3  = (const float*)d_in[6];
    const float* W4  = (const float*)d_in[7];
    const float* b4  = (const float*)d_in[8];
    const float* g1  = (const float*)d_in[9];
    const float* be1 = (const float*)d_in[10];
    const float* m1  = (const float*)d_in[11];
    const float* v1  = (const float*)d_in[12];
    const float* g2  = (const float*)d_in[13];
    const float* be2 = (const float*)d_in[14];
    const float* m2  = (const float*)d_in[15];
    const float* v2  = (const float*)d_in[16];
    const float* g3  = (const float*)d_in[17];
    const float* be3 = (const float*)d_in[18];
    const float* m3  = (const float*)d_in[19];
    const float* v3  = (const float*)d_in[20];
    float* out = (float*)d_out;

    cudaFuncSetAttribute(fc1_gemm,  cudaFuncAttributeMaxDynamicSharedMemorySize, GEMM_SMEM);
    cudaFuncSetAttribute(fc2_gemm,  cudaFuncAttributeMaxDynamicSharedMemorySize, GEMM_SMEM);
    cudaFuncSetAttribute(fc3_fused, cudaFuncAttributeMaxDynamicSharedMemorySize, FC3_SMEM);

    int miscThreads = H + HW * H;
    prep_misc<<<(miscThreads + 255) / 256, 256>>>(W3,
        b1, g1, m1, be1, v1, b2, g2, m2, be2, v2, b3, g3, m3, be3, v3);

    int splitThreads = B * 204 + H * 204 + H * 192;
    prep_split<<<(splitThreads + 255) / 256, 256>>>(x, W1, W2);

    fc1_gemm<<<dim3(H / TN, B / TM), 128, GEMM_SMEM>>>();

    fc2_gemm<<<dim3(H / TN, B / TM), 128, GEMM_SMEM>>>();     // launch #4 (profiled)

    fc3_fused<<<B / 64, 256, FC3_SMEM>>>(W4, b4, out);
}

// round 15
// speedup vs baseline: 2.1809x; 1.0494x over previous
#include <cuda_runtime.h>
#include <cuda_fp16.h>
#include <cstdint>

#define B   16384
#define D   784
#define H   768
#define C   10
#define K2  1600          // 2*784 + 32 pad (fp16 2-term split)
#define NCH 25            // fc1 K chunks (128B)
#define NC2 12            // fc2/fc3 K chunks: 768*2B / 128B
#define TM  128
#define TN  128
#define NPART 12          // fc4 partials: 6 N-tiles x 2 warp_n

// ---------------- device scratch ----------------
__device__ __align__(128) __half g_A[(size_t)B * K2];    // hi|lo split activations
__device__ __align__(128) __half g_Wb[(size_t)H * K2];   // sign(W1) fp16 x2 (pad 0)
__device__ __align__(128) __half g_a2h[(size_t)B * H];   // fc2 input, fp16 +-1
__device__ __align__(128) __half g_a3h[(size_t)B * H];   // fc3 input, fp16 +-1
__device__ __align__(128) __half g_w2h[H * H];           // sign(W2) fp16
__device__ __align__(128) __half g_w3h[H * H];           // sign(W3) fp16
__device__ __align__(128) float  g_plog[(size_t)NPART * B * C];  // fc4 partial logits
__device__ float g_sc1[H], g_of1[H], g_sc2[H], g_of2[H], g_sc3[H], g_of3[H];

#define SWZ(o) ((o) ^ (((o) >> 3) & 0x70))

__device__ __forceinline__ uint32_t smem_u32(const void* p) {
    uint32_t a;
    asm("{ .reg .u64 t; cvta.to.shared.u64 t, %1; cvt.u32.u64 %0, t; }" : "=r"(a) : "l"(p));
    return a;
}

// ---------------- prep: everything in one kernel ----------------
// branches: X split | sign(W1) | sign(W2) | sign(W3) | BN scales
__global__ void prep_all(const float* __restrict__ X, const float* __restrict__ W1,
                         const float* __restrict__ W2, const float* __restrict__ W3,
                         const float* b1, const float* g1, const float* m1, const float* be1, const float* v1,
                         const float* b2, const float* g2, const float* m2, const float* be2, const float* v2,
                         const float* b3, const float* g3, const float* m3, const float* be3, const float* v3) {
    int idx = blockIdx.x * blockDim.x + threadIdx.x;
    if (idx < B * 204) {
        int b = idx / 204, q = idx - b * 204;
        __half* row = &g_A[(size_t)b * K2];
        if (q >= 196) {
            uint2 z = {0, 0};
            *(uint2*)&row[1568 + (q - 196) * 4] = z;
            return;
        }
        int kg = q * 4;
        float4 xv = *(const float4*)&X[b * D + kg];
        float xs[4] = {xv.x, xv.y, xv.z, xv.w};
        __align__(8) __half hi[4], lo[4];
#pragma unroll
        for (int i = 0; i < 4; i++) {
            float x = xs[i];
            __half h = __float2half_rn(x);
            hi[i] = h;
            lo[i] = __float2half_rn(x - __half2float(h));
        }
        *(uint2*)&row[kg]       = *(uint2*)hi;
        *(uint2*)&row[784 + kg] = *(uint2*)lo;
        return;
    }
    int idx2 = idx - B * 204;
    if (idx2 < H * 204) {
        int j = idx2 / 204, q = idx2 - j * 204;
        __half* row = &g_Wb[(size_t)j * K2];
        if (q >= 196) {
            uint2 z = {0, 0};
            *(uint2*)&row[1568 + (q - 196) * 4] = z;
            return;
        }
        int kg = q * 4;
        float4 wv = *(const float4*)&W1[j * D + kg];
        __align__(8) __half o[4];
        o[0] = __float2half(wv.x >= 0.f ? 1.f : -1.f);
        o[1] = __float2half(wv.y >= 0.f ? 1.f : -1.f);
        o[2] = __float2half(wv.z >= 0.f ? 1.f : -1.f);
        o[3] = __float2half(wv.w >= 0.f ? 1.f : -1.f);
        *(uint2*)&row[kg]       = *(uint2*)o;
        *(uint2*)&row[784 + kg] = *(uint2*)o;
        return;
    }
    int idx3 = idx2 - H * 204;
    if (idx3 < 2 * H * 192) {   // sign(W2) then sign(W3)
        int which = idx3 >= H * 192;
        int q = which ? idx3 - H * 192 : idx3;
        const float* W = which ? W3 : W2;
        __half* dst = which ? g_w3h : g_w2h;
        int kg = q * 4;
        float4 wv = *(const float4*)&W[kg];
        __align__(8) __half o[4];
        o[0] = __float2half(wv.x >= 0.f ? 1.f : -1.f);
        o[1] = __float2half(wv.y >= 0.f ? 1.f : -1.f);
        o[2] = __float2half(wv.z >= 0.f ? 1.f : -1.f);
        o[3] = __float2half(wv.w >= 0.f ? 1.f : -1.f);
        *(uint2*)&dst[kg] = *(uint2*)o;
        return;
    }
    int j = idx3 - 2 * H * 192;
    if (j >= H) return;
    float s1 = g1[j] * (float)(1.0 / sqrt((double)(v1[j] + 1e-5f)));
    float s2 = g2[j] * (float)(1.0 / sqrt((double)(v2[j] + 1e-5f)));
    float s3 = g3[j] * (float)(1.0 / sqrt((double)(v3[j] + 1e-5f)));
    g_sc1[j] = s1; g_of1[j] = (b1[j] - m1[j]) * s1 + be1[j];
    g_sc2[j] = s2; g_of2[j] = (b2[j] - m2[j]) * s2 + be2[j];
    g_sc3[j] = s3; g_of3[j] = (b3[j] - m3[j]) * s3 + be3[j];
}

// ================= GEMM tiles: 4 warps, warp tile 64x64, CTA 128x128 =========
#define GEMM_SMEM 66560
#define A_OFF(b) (1024u + (b) * 16384u)
#define B_OFF(b) (33792u + (b) * 16384u)

// ---------------- fc1: fp32-acc fp16 GEMM (R14, unchanged) ------------------
__global__ __launch_bounds__(128, 2)
void fc1_gemm() {
    extern __shared__ char smem[];
    const uint32_t sb = smem_u32(smem);
    const int tid = threadIdx.x;
    const int wid = tid >> 5, lane = tid & 31;
    const int warp_m = wid >> 1, warp_n = wid & 1;
    const int bn = blockIdx.x * TN, bm = blockIdx.y * TM;

    float* ssc = (float*)(smem);
    float* sof = (float*)(smem + 512);
    ssc[tid] = g_sc1[bn + tid]; sof[tid] = g_of1[bn + tid];

    const char* Abase = (const char*)g_A  + (size_t)bm * (K2 * 2);
    const char* Bbase = (const char*)g_Wb + (size_t)bn * (K2 * 2);

    float acc[4][8][4];
#pragma unroll
    for (int i = 0; i < 4; i++)
#pragma unroll
        for (int j = 0; j < 8; j++)
#pragma unroll
            for (int c = 0; c < 4; c++) acc[i][j][c] = 0.f;

    auto load_stage = [&](int s, int buf) {
        size_t kb = (size_t)s * 128;
        uint32_t adst = sb + A_OFF(buf), bdst = sb + B_OFF(buf);
#pragma unroll
        for (int i = 0; i < 8; i++) {
            int idx = i * 128 + tid;
            int row = idx >> 3, c = idx & 7;
            uint32_t off = SWZ((uint32_t)(row * 128 + c * 16));
            const char* srcA = Abase + (size_t)row * (K2 * 2) + kb + c * 16;
            const char* srcB = Bbase + (size_t)row * (K2 * 2) + kb + c * 16;
            asm volatile("cp.async.cg.shared.global [%0], [%1], 16;" :: "r"(adst + off), "l"(srcA));
            asm volatile("cp.async.cg.shared.global [%0], [%1], 16;" :: "r"(bdst + off), "l"(srcB));
        }
        asm volatile("cp.async.commit_group;");
    };

    auto compute = [&](int buf) {
        uint32_t ab = sb + A_OFF(buf), bb = sb + B_OFF(buf);
#pragma unroll
        for (int ks = 0; ks < 4; ks++) {
            uint32_t a[4][4], bf[4][4];
            const int kk = ks * 16 + (lane >> 4) * 8;
            const int mrow = warp_m * 64 + (lane & 15);
            const int nrow = warp_n * 64 + (lane & 15);
#pragma unroll
            for (int mf = 0; mf < 4; mf++) {
                uint32_t addr = ab + SWZ((uint32_t)((mrow + mf * 16) * 128 + kk * 2));
                asm volatile("ldmatrix.sync.aligned.m8n8.x4.shared.b16 {%0,%1,%2,%3}, [%4];"
                    : "=r"(a[mf][0]), "=r"(a[mf][1]), "=r"(a[mf][2]), "=r"(a[mf][3]) : "r"(addr));
            }
#pragma unroll
            for (int p = 0; p < 4; p++) {
                uint32_t addr = bb + SWZ((uint32_t)((nrow + p * 16) * 128 + kk * 2));
                asm volatile("ldmatrix.sync.aligned.m8n8.x4.shared.b16 {%0,%1,%2,%3}, [%4];"
                    : "=r"(bf[p][0]), "=r"(bf[p][1]), "=r"(bf[p][2]), "=r"(bf[p][3]) : "r"(addr));
            }
#pragma unroll
            for (int mf = 0; mf < 4; mf++)
#pragma unroll
                for (int nf = 0; nf < 8; nf++) {
                    uint32_t b0 = bf[nf >> 1][nf & 1], b1 = bf[nf >> 1][(nf & 1) + 2];
                    asm volatile(
                        "mma.sync.aligned.m16n8k16.row.col.f32.f16.f16.f32 "
                        "{%0,%1,%2,%3}, {%4,%5,%6,%7}, {%8,%9}, {%0,%1,%2,%3};"
                        : "+f"(acc[mf][nf][0]), "+f"(acc[mf][nf][1]),
                          "+f"(acc[mf][nf][2]), "+f"(acc[mf][nf][3])
                        : "r"(a[mf][0]), "r"(a[mf][1]), "r"(a[mf][2]), "r"(a[mf][3]),
                          "r"(b0), "r"(b1));
                }
        }
    };

    load_stage(0, 0);
    for (int s = 0; s < NCH; s++) {
        if (s + 1 < NCH) load_stage(s + 1, (s + 1) & 1);
        if (s + 1 < NCH) asm volatile("cp.async.wait_group 1;");
        else             asm volatile("cp.async.wait_group 0;");
        __syncthreads();
        compute(s & 1);
        __syncthreads();
    }

    const int tg = lane & 3, gid = lane >> 2;
    const __half hp1 = __float2half(1.f), hm1 = __float2half(-1.f);
#pragma unroll
    for (int mf = 0; mf < 4; mf++) {
        int row = bm + warp_m * 64 + mf * 16 + gid;
#pragma unroll
        for (int nf = 0; nf < 8; nf++) {
            int cl = warp_n * 64 + nf * 8 + tg * 2;
            int col = bn + cl;
            float f00 = fmaf(acc[mf][nf][0], ssc[cl],     sof[cl]);
            float f01 = fmaf(acc[mf][nf][1], ssc[cl + 1], sof[cl + 1]);
            float f10 = fmaf(acc[mf][nf][2], ssc[cl],     sof[cl]);
            float f11 = fmaf(acc[mf][nf][3], ssc[cl + 1], sof[cl + 1]);
            __half2 hA = __halves2half2(f00 >= 0.f ? hp1 : hm1, f01 >= 0.f ? hp1 : hm1);
            __half2 hB = __halves2half2(f10 >= 0.f ? hp1 : hm1, f11 >= 0.f ? hp1 : hm1);
            *(__half2*)&g_a2h[(size_t)row * H + col]       = hA;
            *(__half2*)&g_a2h[(size_t)(row + 8) * H + col] = hB;
        }
    }
}

// ---------------- fc2: fp16-acc GEMM, epilogue -> fp16 +-1 (g_a3h) ----------
__global__ __launch_bounds__(128, 3)
void fc2_gemm() {
    extern __shared__ char smem[];
    const uint32_t sb = smem_u32(smem);
    const int tid = threadIdx.x;
    const int wid = tid >> 5, lane = tid & 31;
    const int warp_m = wid >> 1, warp_n = wid & 1;
    const int bn = blockIdx.x * TN, bm = blockIdx.y * TM;

    float* ssc = (float*)(smem);
    float* sof = (float*)(smem + 512);
    ssc[tid] = g_sc2[bn + tid]; sof[tid] = g_of2[bn + tid];

    const char* Abase = (const char*)g_a2h + (size_t)bm * (H * 2);
    const char* Bbase = (const char*)g_w2h + (size_t)bn * (H * 2);

    uint32_t acc[4][8][2];
#pragma unroll
    for (int i = 0; i < 4; i++)
#pragma unroll
        for (int j = 0; j < 8; j++) { acc[i][j][0] = 0u; acc[i][j][1] = 0u; }

    auto load_stage = [&](int s, int buf) {
        size_t kb = (size_t)s * 128;
        uint32_t adst = sb + A_OFF(buf), bdst = sb + B_OFF(buf);
#pragma unroll
        for (int i = 0; i < 8; i++) {
            int idx = i * 128 + tid;
            int row = idx >> 3, c = idx & 7;
            uint32_t off = SWZ((uint32_t)(row * 128 + c * 16));
            const char* srcA = Abase + (size_t)row * (H * 2) + kb + c * 16;
            const char* srcB = Bbase + (size_t)row * (H * 2) + kb + c * 16;
            asm volatile("cp.async.cg.shared.global [%0], [%1], 16;" :: "r"(adst + off), "l"(srcA));
            asm volatile("cp.async.cg.shared.global [%0], [%1], 16;" :: "r"(bdst + off), "l"(srcB));
        }
        asm volatile("cp.async.commit_group;");
    };

    auto compute = [&](int buf) {
        uint32_t ab = sb + A_OFF(buf), bb = sb + B_OFF(buf);
#pragma unroll
        for (int ks = 0; ks < 4; ks++) {
            uint32_t a[4][4], bf[4][4];
            const int kk = ks * 16 + (lane >> 4) * 8;
            const int mrow = warp_m * 64 + (lane & 15);
            const int nrow = warp_n * 64 + (lane & 15);
#pragma unroll
            for (int mf = 0; mf < 4; mf++) {
                uint32_t addr = ab + SWZ((uint32_t)((mrow + mf * 16) * 128 + kk * 2));
                asm volatile("ldmatrix.sync.aligned.m8n8.x4.shared.b16 {%0,%1,%2,%3}, [%4];"
                    : "=r"(a[mf][0]), "=r"(a[mf][1]), "=r"(a[mf][2]), "=r"(a[mf][3]) : "r"(addr));
            }
#pragma unroll
            for (int p = 0; p < 4; p++) {
                uint32_t addr = bb + SWZ((uint32_t)((nrow + p * 16) * 128 + kk * 2));
                asm volatile("ldmatrix.sync.aligned.m8n8.x4.shared.b16 {%0,%1,%2,%3}, [%4];"
                    : "=r"(bf[p][0]), "=r"(bf[p][1]), "=r"(bf[p][2]), "=r"(bf[p][3]) : "r"(addr));
            }
#pragma unroll
            for (int mf = 0; mf < 4; mf++)
#pragma unroll
                for (int nf = 0; nf < 8; nf++) {
                    uint32_t b0 = bf[nf >> 1][nf & 1], b1 = bf[nf >> 1][(nf & 1) + 2];
                    asm volatile(
                        "mma.sync.aligned.m16n8k16.row.col.f16.f16.f16.f16 "
                        "{%0,%1}, {%2,%3,%4,%5}, {%6,%7}, {%0,%1};"
                        : "+r"(acc[mf][nf][0]), "+r"(acc[mf][nf][1])
                        : "r"(a[mf][0]), "r"(a[mf][1]), "r"(a[mf][2]), "r"(a[mf][3]),
                          "r"(b0), "r"(b1));
                }
        }
    };

    load_stage(0, 0);
    for (int s = 0; s < NC2; s++) {
        if (s + 1 < NC2) load_stage(s + 1, (s + 1) & 1);
        if (s + 1 < NC2) asm volatile("cp.async.wait_group 1;");
        else             asm volatile("cp.async.wait_group 0;");
        __syncthreads();
        compute(s & 1);
        __syncthreads();
    }

    // epilogue: BN + sign -> fp16 +-1 into g_a3h (fc1-validated pattern)
    const int tg = lane & 3, gid = lane >> 2;
    const __half hp1 = __float2half(1.f), hm1 = __float2half(-1.f);
#pragma unroll
    for (int mf = 0; mf < 4; mf++) {
        int row = bm + warp_m * 64 + mf * 16 + gid;
#pragma unroll
        for (int nf = 0; nf < 8; nf++) {
            int cl = warp_n * 64 + nf * 8 + tg * 2;
            int col = bn + cl;
            float2 fa = __half22float2(*(__half2*)&acc[mf][nf][0]);
            float2 fb = __half22float2(*(__half2*)&acc[mf][nf][1]);
            float f00 = fmaf(fa.x, ssc[cl],     sof[cl]);
            float f01 = fmaf(fa.y, ssc[cl + 1], sof[cl + 1]);
            float f10 = fmaf(fb.x, ssc[cl],     sof[cl]);
            float f11 = fmaf(fb.y, ssc[cl + 1], sof[cl + 1]);
            __half2 hA = __halves2half2(f00 >= 0.f ? hp1 : hm1, f01 >= 0.f ? hp1 : hm1);
            __half2 hB = __halves2half2(f10 >= 0.f ? hp1 : hm1, f11 >= 0.f ? hp1 : hm1);
            *(__half2*)&g_a3h[(size_t)row * H + col]       = hA;
            *(__half2*)&g_a3h[(size_t)(row + 8) * H + col] = hB;
        }
    }
}

// ---------------- fc3: fp16-acc GEMM + fused partial-fc4 epilogue -----------
#define FC3_SMEM (66560 + C * TN * 4)   // + W4 tile [10][128]

__global__ __launch_bounds__(128, 3)
void fc3_gemm(const float* __restrict__ W4) {
    extern __shared__ char smem[];
    const uint32_t sb = smem_u32(smem);
    const int tid = threadIdx.x;
    const int wid = tid >> 5, lane = tid & 31;
    const int warp_m = wid >> 1, warp_n = wid & 1;
    const int bn = blockIdx.x * TN, bm = blockIdx.y * TM;

    float* ssc = (float*)(smem);
    float* sof = (float*)(smem + 512);
    float* sW4 = (float*)(smem + 66560);
    ssc[tid] = g_sc3[bn + tid]; sof[tid] = g_of3[bn + tid];
#pragma unroll
    for (int i = tid; i < C * TN; i += 128) {
        int c = i >> 7, cc = i & 127;
        sW4[i] = W4[c * H + bn + cc];
    }

    const char* Abase = (const char*)g_a3h + (size_t)bm * (H * 2);
    const char* Bbase = (const char*)g_w3h + (size_t)bn * (H * 2);

    uint32_t acc[4][8][2];
#pragma unroll
    for (int i = 0; i < 4; i++)
#pragma unroll
        for (int j = 0; j < 8; j++) { acc[i][j][0] = 0u; acc[i][j][1] = 0u; }

    auto load_stage = [&](int s, int buf) {
        size_t kb = (size_t)s * 128;
        uint32_t adst = sb + A_OFF(buf), bdst = sb + B_OFF(buf);
#pragma unroll
        for (int i = 0; i < 8; i++) {
            int idx = i * 128 + tid;
            int row = idx >> 3, c = idx & 7;
            uint32_t off = SWZ((uint32_t)(row * 128 + c * 16));
            const char* srcA = Abase + (size_t)row * (H * 2) + kb + c * 16;
            const char* srcB = Bbase + (size_t)row * (H * 2) + kb + c * 16;
            asm volatile("cp.async.cg.shared.global [%0], [%1], 16;" :: "r"(adst + off), "l"(srcA));
            asm volatile("cp.async.cg.shared.global [%0], [%1], 16;" :: "r"(bdst + off), "l"(srcB));
        }
        asm volatile("cp.async.commit_group;");
    };

    auto compute = [&](int buf) {
        uint32_t ab = sb + A_OFF(buf), bb = sb + B_OFF(buf);
#pragma unroll
        for (int ks = 0; ks < 4; ks++) {
            uint32_t a[4][4], bf[4][4];
            const int kk = ks * 16 + (lane >> 4) * 8;
            const int mrow = warp_m * 64 + (lane & 15);
            const int nrow = warp_n * 64 + (lane & 15);
#pragma unroll
            for (int mf = 0; mf < 4; mf++) {
                uint32_t addr = ab + SWZ((uint32_t)((mrow + mf * 16) * 128 + kk * 2));
                asm volatile("ldmatrix.sync.aligned.m8n8.x4.shared.b16 {%0,%1,%2,%3}, [%4];"
                    : "=r"(a[mf][0]), "=r"(a[mf][1]), "=r"(a[mf][2]), "=r"(a[mf][3]) : "r"(addr));
            }
#pragma unroll
            for (int p = 0; p < 4; p++) {
                uint32_t addr = bb + SWZ((uint32_t)((nrow + p * 16) * 128 + kk * 2));
                asm volatile("ldmatrix.sync.aligned.m8n8.x4.shared.b16 {%0,%1,%2,%3}, [%4];"
                    : "=r"(bf[p][0]), "=r"(bf[p][1]), "=r"(bf[p][2]), "=r"(bf[p][3]) : "r"(addr));
            }
#pragma unroll
            for (int mf = 0; mf < 4; mf++)
#pragma unroll
                for (int nf = 0; nf < 8; nf++) {
                    uint32_t b0 = bf[nf >> 1][nf & 1], b1 = bf[nf >> 1][(nf & 1) + 2];
                    asm volatile(
                        "mma.sync.aligned.m16n8k16.row.col.f16.f16.f16.f16 "
                        "{%0,%1}, {%2,%3,%4,%5}, {%6,%7}, {%0,%1};"
                        : "+r"(acc[mf][nf][0]), "+r"(acc[mf][nf][1])
                        : "r"(a[mf][0]), "r"(a[mf][1]), "r"(a[mf][2]), "r"(a[mf][3]),
                          "r"(b0), "r"(b1));
                }
        }
    };

    load_stage(0, 0);
    for (int s = 0; s < NC2; s++) {
        if (s + 1 < NC2) load_stage(s + 1, (s + 1) & 1);
        if (s + 1 < NC2) asm volatile("cp.async.wait_group 1;");
        else             asm volatile("cp.async.wait_group 0;");
        __syncthreads();
        compute(s & 1);
        __syncthreads();
    }

    // epilogue: BN + hardtanh + partial fc4 dot over this CTA's 128 columns
    const int tg = lane & 3, gid = lane >> 2;
    const size_t pbase = (size_t)(blockIdx.x * 2 + warp_n) * B * C;
#pragma unroll
    for (int mf = 0; mf < 4; mf++) {
        int r0 = bm + warp_m * 64 + mf * 16 + gid;
        float plg0[C], plg1[C];
#pragma unroll
        for (int c = 0; c < C; c++) { plg0[c] = 0.f; plg1[c] = 0.f; }
#pragma unroll
        for (int nf = 0; nf < 8; nf++) {
            int cl = warp_n * 64 + nf * 8 + tg * 2;
            float2 fa = __half22float2(*(__half2*)&acc[mf][nf][0]);
            float2 fb = __half22float2(*(__half2*)&acc[mf][nf][1]);
            float h00 = fminf(fmaxf(fmaf(fa.x, ssc[cl],     sof[cl]),     -1.f), 1.f);
            float h01 = fminf(fmaxf(fmaf(fa.y, ssc[cl + 1], sof[cl + 1]), -1.f), 1.f);
            float h10 = fminf(fmaxf(fmaf(fb.x, ssc[cl],     sof[cl]),     -1.f), 1.f);
            float h11 = fminf(fmaxf(fmaf(fb.y, ssc[cl + 1], sof[cl + 1]), -1.f), 1.f);
#pragma unroll
            for (int c = 0; c < C; c++) {
                float w0 = sW4[c * TN + cl], w1 = sW4[c * TN + cl + 1];
                plg0[c] += h00 * w0 + h01 * w1;
                plg1[c] += h10 * w0 + h11 * w1;
            }
        }
#pragma unroll
        for (int c = 0; c < C; c++) {
            plg0[c] += __shfl_xor_sync(0xffffffffu, plg0[c], 1);
            plg0[c] += __shfl_xor_sync(0xffffffffu, plg0[c], 2);
            plg1[c] += __shfl_xor_sync(0xffffffffu, plg1[c], 1);
            plg1[c] += __shfl_xor_sync(0xffffffffu, plg1[c], 2);
        }
        if (tg == 0) {
#pragma unroll
            for (int c = 0; c < C; c++) {
                g_plog[pbase + (size_t)r0 * C + c]       = plg0[c];
                g_plog[pbase + (size_t)(r0 + 8) * C + c] = plg1[c];
            }
        }
    }
}

// ---------------- fc4_soft: sum 12 partials + b4 + log_softmax --------------
__global__ __launch_bounds__(256)
void fc4_soft(const float* __restrict__ b4, float* __restrict__ out) {
    int w = blockIdx.x * 256 + threadIdx.x;   // one thread per row
    float lg[C];
#pragma unroll
    for (int c = 0; c < C; c++) lg[c] = b4[c];
#pragma unroll
    for (int p = 0; p < NPART; p++) {
        const float* src = &g_plog[(size_t)p * B * C + (size_t)w * C];
#pragma unroll
        for (int c2 = 0; c2 < C / 2; c2++) {
            float2 v = *(const float2*)&src[c2 * 2];
            lg[c2 * 2]     += v.x;
            lg[c2 * 2 + 1] += v.y;
        }
    }
    float mx = -3.402823466e+38f;
#pragma unroll
    for (int c = 0; c < C; c++) mx = fmaxf(mx, lg[c]);
    float s = 0.f;
#pragma unroll
    for (int c = 0; c < C; c++) s += expf(lg[c] - mx);
    float lse = logf(s);
#pragma unroll
    for (int c2 = 0; c2 < C / 2; c2++) {
        float2 v;
        v.x = lg[c2 * 2] - mx - lse;
        v.y = lg[c2 * 2 + 1] - mx - lse;
        *(float2*)&out[(size_t)w * C + c2 * 2] = v;
    }
}

// ---------------- launch (fc3_gemm is launch #4 -> profiled) ----------------
extern "C" void kernel_launch(void* const* d_in, const int* in_sizes, int n_in,
                              void* d_out, int out_size) {
    const float* x   = (const float*)d_in[0];
    const float* W1  = (const float*)d_in[1];
    const float* b1  = (const float*)d_in[2];
    const float* W2  = (const float*)d_in[3];
    const float* b2  = (const float*)d_in[4];
    const float* W3  = (const float*)d_in[5];
    const float* b3  = (const float*)d_in[6];
    const float* W4  = (const float*)d_in[7];
    const float* b4  = (const float*)d_in[8];
    const float* g1  = (const float*)d_in[9];
    const float* be1 = (const float*)d_in[10];
    const float* m1  = (const float*)d_in[11];
    const float* v1  = (const float*)d_in[12];
    const float* g2  = (const float*)d_in[13];
    const float* be2 = (const float*)d_in[14];
    const float* m2  = (const float*)d_in[15];
    const float* v2  = (const float*)d_in[16];
    const float* g3  = (const float*)d_in[17];
    const float* be3 = (const float*)d_in[18];
    const float* m3  = (const float*)d_in[19];
    const float* v3  = (const float*)d_in[20];
    float* out = (float*)d_out;

    cudaFuncSetAttribute(fc1_gemm, cudaFuncAttributeMaxDynamicSharedMemorySize, GEMM_SMEM);
    cudaFuncSetAttribute(fc2_gemm, cudaFuncAttributeMaxDynamicSharedMemorySize, GEMM_SMEM);
    cudaFuncSetAttribute(fc3_gemm, cudaFuncAttributeMaxDynamicSharedMemorySize, FC3_SMEM);

    int prepThreads = B * 204 + H * 204 + 2 * H * 192 + H;
    prep_all<<<(prepThreads + 255) / 256, 256>>>(x, W1, W2, W3,
        b1, g1, m1, be1, v1, b2, g2, m2, be2, v2, b3, g3, m3, be3, v3);

    fc1_gemm<<<dim3(H / TN, B / TM), 128, GEMM_SMEM>>>();
    fc2_gemm<<<dim3(H / TN, B / TM), 128, GEMM_SMEM>>>();
    fc3_gemm<<<dim3(H / TN, B / TM), 128, FC3_SMEM>>>(W4);    // launch #4 (profiled)
    fc4_soft<<<B / 256, 256>>>(b4, out);
}